// round 10
// baseline (speedup 1.0000x reference)
#include <cuda_runtime.h>
#include <cuda_bf16.h>
#include <cstdint>

using bf16 = __nv_bfloat16;

// ===========================================================================
// MHA_73607149519311 — round 10: r9's 64x64 warp tile kept, but 8 warps per
// CTA (256 thr, 4M x 2N, CTA tile 256x128) -> 2 warps/SMSP in ONE CTA, so
// LDSM phases of one warp overlap MMA phases of the other (r9 had 1 warp/SMSP
// and serialized the two pipes; 255 regs made 2-CTA residency impossible).
//
//   X stored as X_hi + X_lo (bf16); each K=16 step issues hi*hi + hi*lo +
//   lo*hi into fp32 accumulators -> fp32-equivalent GEMM precision.
// ===========================================================================

namespace {
constexpr float kScale = 1.0f / 16.0f;   // 1/sqrt(256)
constexpr float kEps   = 1e-12f;
constexpr uint32_t A_LO = 16384, B_HI = 32768, B_LO = 40960;
constexpr uint32_t STAGE = 49152;
constexpr int kDynSmem = 147456;         // 3 stages x 48KB
}

// ---- scratch (static device globals; no dynamic allocation) ----
#define DEVBUF(name, count) __device__ __align__(128) bf16 name[count]
DEVBUF(g_xh, 8388608);  DEVBUF(g_xl, 8388608);    // leaky(x) split   [32768,256]
DEVBUF(g_weh, 65536);   DEVBUF(g_wel, 65536);     // W_enc split      [256,256]
DEVBUF(g_mth, 524288);  DEVBUF(g_mtl, 524288);    // MT=WK@WQ^T split [8,256,256]
DEVBUF(g_hh, 8388608);  DEVBUF(g_hl, 8388608);    // h split          [32,1024,256]
DEVBUF(g_hth, 8388608); DEVBUF(g_htl, 8388608);   // h^T split        [32,256,1024]
DEVBUF(g_gh, 16777216); DEVBUF(g_gl, 16777216);   // G split          [256,256,256]
DEVBUF(g_ph, 67108864); DEVBUF(g_pl, 67108864);   // prob split       [256,256,1024]
DEVBUF(g_uh, 16777216); DEVBUF(g_ul, 16777216);   // U concat split   [32,256,2048]
DEVBUF(g_wvh, 524288);  DEVBUF(g_wvl, 524288);    // WVT_cat split    [256,2048]
DEVBUF(g_mb, 8388608);                             // mask bf16        [32,256,1024]
__device__ __align__(128) float g_S[67108864];     // S fp32           [256,256,1024]

// ============================= helpers =====================================
__device__ __forceinline__ uint32_t s2u(const void* p) {
    uint32_t a;
    asm("{ .reg .u64 t; cvta.to.shared.u64 t, %1; cvt.u32.u64 %0, t; }"
        : "=r"(a) : "l"(p));
    return a;
}

__device__ __forceinline__ void cp16(uint32_t saddr, const void* gaddr) {
    asm volatile("cp.async.cg.shared.global [%0], [%1], 16;"
                 :: "r"(saddr), "l"(gaddr) : "memory");
}
#define CP_COMMIT() asm volatile("cp.async.commit_group;" ::: "memory")
#define CP_WAIT1()  asm volatile("cp.async.wait_group 1;" ::: "memory")
#define CP_WAIT0()  asm volatile("cp.async.wait_group 0;" ::: "memory")

__device__ __forceinline__ void ldmx4(uint32_t* r, uint32_t addr) {
    asm volatile("ldmatrix.sync.aligned.m8n8.x4.shared.b16 {%0,%1,%2,%3}, [%4];"
                 : "=r"(r[0]), "=r"(r[1]), "=r"(r[2]), "=r"(r[3]) : "r"(addr));
}

__device__ __forceinline__ void mma16816(float* c, const uint32_t* a,
                                         uint32_t b0, uint32_t b1) {
    asm volatile(
        "mma.sync.aligned.m16n8k16.row.col.f32.bf16.bf16.f32 "
        "{%0,%1,%2,%3}, {%4,%5,%6,%7}, {%8,%9}, {%0,%1,%2,%3};"
        : "+f"(c[0]), "+f"(c[1]), "+f"(c[2]), "+f"(c[3])
        : "r"(a[0]), "r"(a[1]), "r"(a[2]), "r"(a[3]), "r"(b0), "r"(b1));
}

__device__ __forceinline__ void split2(float v, bf16& hi, bf16& lo) {
    hi = __float2bfloat16(v);
    lo = __float2bfloat16(v - __bfloat162float(hi));
}
__device__ __forceinline__ uint32_t packbf2(bf16 a, bf16 b) {
    __nv_bfloat162 t; t.x = a; t.y = b;
    return *reinterpret_cast<uint32_t*>(&t);
}

// Swizzled offset within a (rows x 64B) tile: row r, seg s (0..3).
__device__ __forceinline__ uint32_t sw64(int r, int s) {
    return (uint32_t)((r << 6) + (((s ^ ((r >> 1) & 3)) & 3) << 4));
}

// ============================ MMA mainloop =================================
// CTA tile 256(M) x 128(N), NT split-bf16 GEMM. 256 threads = 8 warps
// (4M x 2N), warp tile 64x64. cp.async 3-stage pipeline, K chunks of 32.
// SMEM stage (48KB): Ahi(16K) | Alo(16K) | Bhi(8K) | Blo(8K), 64B rows, sw64.

__device__ __forceinline__ void issue_chunk(
    const bf16* __restrict__ Ah, const bf16* __restrict__ Al, int lda,
    const bf16* __restrict__ Bh, const bf16* __restrict__ Bl, int ldb,
    int row0, int col0, int kt, uint32_t sb)
{
    const int tid = threadIdx.x;
#pragma unroll
    for (int i = 0; i < 4; i++) {            // A: 256 rows x 4 segs
        const int idx = tid + i * 256;       // 0..1023
        const int r = idx >> 2, s = idx & 3;
        const uint32_t off = sw64(r, s);
        const size_t ga = (size_t)(row0 + r) * lda + kt + s * 8;
        cp16(sb + off,        Ah + ga);
        cp16(sb + A_LO + off, Al + ga);
    }
#pragma unroll
    for (int i = 0; i < 2; i++) {            // B: 128 rows x 4 segs
        const int idx = tid + i * 256;       // 0..511
        const int r = idx >> 2, s = idx & 3;
        const uint32_t off = sw64(r, s);
        const size_t gb = (size_t)(col0 + r) * ldb + kt + s * 8;
        cp16(sb + B_HI + off, Bh + gb);
        cp16(sb + B_LO + off, Bl + gb);
    }
    CP_COMMIT();
}

__device__ __forceinline__ void mma_nt_mainloop(
    const bf16* __restrict__ Ah, const bf16* __restrict__ Al, int lda,
    const bf16* __restrict__ Bh, const bf16* __restrict__ Bl, int ldb,
    int row0, int col0, int K, uint32_t sdu, float (&c)[4][8][4])
{
    const int tid = threadIdx.x;
    const int lane = tid & 31, wid = tid >> 5;
    const int wm = (wid & 3) << 6;          // warp M offset (0/64/128/192)
    const int wn = (wid >> 2) << 6;         // warp N offset (0/64)

    const int arow0 = wm + (lane & 15);                       // + mi*16
    const int akseg = lane >> 4;                              // + 2k
    const int brow0 = wn + ((lane >> 4) << 3) + (lane & 7);   // + nj*16
    const int bkseg = (lane >> 3) & 1;                        // + 2k

    const int NC = K >> 5;                  // chunks of 32
    issue_chunk(Ah, Al, lda, Bh, Bl, ldb, row0, col0, 0, sdu);
    issue_chunk(Ah, Al, lda, Bh, Bl, ldb, row0, col0, 32, sdu + STAGE);

    int buf = 0;
    for (int ci = 0; ci < NC; ci++) {
        if (ci + 1 < NC) { CP_WAIT1(); } else { CP_WAIT0(); }
        __syncthreads();        // all warps done compute(ci-1); data(ci) visible
        if (ci + 2 < NC) {
            int nb = buf + 2; if (nb >= 3) nb -= 3;
            issue_chunk(Ah, Al, lda, Bh, Bl, ldb, row0, col0,
                        (ci + 2) << 5, sdu + nb * STAGE);
        }

        const uint32_t sb = sdu + buf * STAGE;
#pragma unroll
        for (int k = 0; k < 2; k++) {
            uint32_t afh[4][4], afl[4][4], bfh[4][4], bfl[4][4];
#pragma unroll
            for (int mi = 0; mi < 4; mi++) {
                const int r = arow0 + mi * 16;
                const uint32_t off = sw64(r, 2 * k + akseg);
                ldmx4(afh[mi], sb + off);
                ldmx4(afl[mi], sb + A_LO + off);
            }
#pragma unroll
            for (int nj = 0; nj < 4; nj++) {
                const int r = brow0 + nj * 16;
                const uint32_t off = sw64(r, 2 * k + bkseg);
                ldmx4(bfh[nj], sb + B_HI + off);
                ldmx4(bfl[nj], sb + B_LO + off);
            }
            // pass-ordered: hh all 32 tiles, then hl, then lh
#pragma unroll
            for (int mi = 0; mi < 4; mi++)
#pragma unroll
                for (int ni = 0; ni < 8; ni++) {
                    const int nj = ni >> 1, o = (ni & 1) << 1;
                    mma16816(c[mi][ni], afh[mi], bfh[nj][o], bfh[nj][o + 1]);
                }
#pragma unroll
            for (int mi = 0; mi < 4; mi++)
#pragma unroll
                for (int ni = 0; ni < 8; ni++) {
                    const int nj = ni >> 1, o = (ni & 1) << 1;
                    mma16816(c[mi][ni], afh[mi], bfl[nj][o], bfl[nj][o + 1]);
                }
#pragma unroll
            for (int mi = 0; mi < 4; mi++)
#pragma unroll
                for (int ni = 0; ni < 8; ni++) {
                    const int nj = ni >> 1, o = (ni & 1) << 1;
                    mma16816(c[mi][ni], afl[mi], bfh[nj][o], bfh[nj][o + 1]);
                }
        }
        if (++buf == 3) buf = 0;
    }
}

// Epilogue mapping for c[mi][j][q]:
//   row = row0 + wm + mi*16 + (lane>>2) + (q>=2 ? 8 : 0)
//   col = col0 + wn + j*8 + (lane&3)*2 + (q&1)
//   wm = (wid&3)<<6, wn = (wid>>2)<<6

// ===================== merged prep kernel (launch #1) ======================
// blockIdx.x ranges:
//   [0, 8192)            conv_x   (leaky + split)
//   [8192, 8256)         conv_wenc
//   [8256, 8768)         conv_wvt (smem-tiled transpose)
//   [8768, 8896)         mt       (MT[h] = WK_h @ WQ_h^T, 64x64 tiles)
//   [8896, 17088)        conv_mask (fp32 -> bf16, exact for {0,1})

__global__ __launch_bounds__(256) void prep_kernel(
    const float* __restrict__ x, const float* __restrict__ W_enc,
    const float* __restrict__ WV,
    const float* __restrict__ WQ, const float* __restrict__ WK,
    const float* __restrict__ m)
{
    const int bid = blockIdx.x;
    if (bid < 8192) {
        size_t idx = (size_t)bid * 256 + threadIdx.x;   // over float4s
        float4 v = ((const float4*)x)[idx];
        v.x = v.x > 0.f ? v.x : 0.01f * v.x;
        v.y = v.y > 0.f ? v.y : 0.01f * v.y;
        v.z = v.z > 0.f ? v.z : 0.01f * v.z;
        v.w = v.w > 0.f ? v.w : 0.01f * v.w;
        bf16 h0,l0,h1,l1,h2,l2,h3,l3;
        split2(v.x,h0,l0); split2(v.y,h1,l1); split2(v.z,h2,l2); split2(v.w,h3,l3);
        *(uint2*)(g_xh + idx * 4) = make_uint2(packbf2(h0,h1), packbf2(h2,h3));
        *(uint2*)(g_xl + idx * 4) = make_uint2(packbf2(l0,l1), packbf2(l2,l3));
        return;
    }
    if (bid < 8256) {
        size_t idx = (size_t)(bid - 8192) * 256 + threadIdx.x;  // 16384 float4s
        float4 v = ((const float4*)W_enc)[idx];
        bf16 h0,l0,h1,l1,h2,l2,h3,l3;
        split2(v.x,h0,l0); split2(v.y,h1,l1); split2(v.z,h2,l2); split2(v.w,h3,l3);
        *(uint2*)(g_weh + idx * 4) = make_uint2(packbf2(h0,h1), packbf2(h2,h3));
        *(uint2*)(g_wel + idx * 4) = make_uint2(packbf2(l0,l1), packbf2(l2,l3));
        return;
    }
    if (bid < 8768) {
        __shared__ float t[32][33];
        const int tb = bid - 8256;
        const int k0 = (tb & 63) * 32, e0 = (tb >> 6) * 32;
        const int tx = threadIdx.x & 31, ty = threadIdx.x >> 5;
#pragma unroll
        for (int i = 0; i < 4; i++) {
            const int k = ty + i * 8;
            t[k][tx] = WV[(size_t)(k0 + k) * 256 + e0 + tx];
        }
        __syncthreads();
#pragma unroll
        for (int i = 0; i < 4; i++) {
            const int e = ty + i * 8;
            const float v = t[tx][e];
            bf16 hi, lo; split2(v, hi, lo);
            const size_t o = (size_t)(e0 + e) * 2048 + k0 + tx;
            g_wvh[o] = hi; g_wvl[o] = lo;
        }
        return;
    }
    if (bid < 8896) {
        __shared__ float As[8][68], Bs[8][68];
        float acc[4][4] = {};
        const int tb = bid - 8768;
        const int hh = tb >> 4;
        const int row0 = ((tb >> 2) & 3) * 64, col0 = (tb & 3) * 64;
        const float* A = WK + (size_t)hh * 65536;
        const float* B = WQ + (size_t)hh * 65536;
        const int tid = threadIdx.x;
        const int lr = tid >> 2, lk = (tid & 3) << 1;
        const int tx = tid & 15, ty = tid >> 4;
        const float* aP = A + (size_t)(row0 + lr) * 256 + lk;
        const float* bP = B + (size_t)(col0 + lr) * 256 + lk;
        for (int kt = 0; kt < 256; kt += 8) {
            float2 av = *(const float2*)(aP + kt);
            float2 bv = *(const float2*)(bP + kt);
            As[lk][lr] = av.x; As[lk + 1][lr] = av.y;
            Bs[lk][lr] = bv.x; Bs[lk + 1][lr] = bv.y;
            __syncthreads();
#pragma unroll
            for (int k = 0; k < 8; k++) {
                float ar[4], br[4];
                *(float4*)ar = *(const float4*)(&As[k][ty * 4]);
                *(float4*)br = *(const float4*)(&Bs[k][tx * 4]);
#pragma unroll
                for (int i = 0; i < 4; i++)
#pragma unroll
                    for (int j = 0; j < 4; j++)
                        acc[i][j] = fmaf(ar[i], br[j], acc[i][j]);
            }
            __syncthreads();
        }
        bf16* Dh = g_mth + (size_t)hh * 65536;
        bf16* Dl = g_mtl + (size_t)hh * 65536;
#pragma unroll
        for (int i = 0; i < 4; i++) {
            size_t base = (size_t)(row0 + ty * 4 + i) * 256 + col0 + tx * 4;
#pragma unroll
            for (int j = 0; j < 4; j += 2) {
                bf16 h0,l0,h1,l1;
                split2(acc[i][j],h0,l0); split2(acc[i][j+1],h1,l1);
                *(uint32_t*)(Dh + base + j) = packbf2(h0,h1);
                *(uint32_t*)(Dl + base + j) = packbf2(l0,l1);
            }
        }
        return;
    }
    {
        size_t idx = (size_t)(bid - 8896) * 256 + threadIdx.x;  // 2097152 float4s
        float4 v = ((const float4*)m)[idx];
        uint2 w = make_uint2(
            packbf2(__float2bfloat16(v.x), __float2bfloat16(v.y)),
            packbf2(__float2bfloat16(v.z), __float2bfloat16(v.w)));
        *(uint2*)(g_mb + idx * 4) = w;
    }
}

// ============================== MMA kernels ================================

// h = x_sp @ Wenc^T + b. grid (2, 128): row0 = by*256, col0 = bx*128.
__global__ __launch_bounds__(256, 1) void enc_mma_kernel(const float* __restrict__ bias) {
    extern __shared__ char sd[];
    const uint32_t sdu = s2u(sd);
    float c[4][8][4] = {};
    const int row0 = blockIdx.y * 256, col0 = blockIdx.x * 128;
    mma_nt_mainloop(g_xh, g_xl, 256, g_weh, g_wel, 256, row0, col0, 256, sdu, c);
    const int lane = threadIdx.x & 31, wid = threadIdx.x >> 5;
    const int wm = (wid & 3) << 6, wn = (wid >> 2) << 6;
#pragma unroll
    for (int mi = 0; mi < 4; mi++)
#pragma unroll
        for (int j = 0; j < 8; j++) {
            const int col = col0 + wn + j * 8 + (lane & 3) * 2;
            const float b0 = bias[col], b1 = bias[col + 1];
#pragma unroll
            for (int q = 0; q < 2; q++) {
                const int row = row0 + wm + mi * 16 + (lane >> 2) + q * 8;
                const float v0 = c[mi][j][q * 2]     + b0;
                const float v1 = c[mi][j][q * 2 + 1] + b1;
                bf16 h0,l0,h1,l1; split2(v0,h0,l0); split2(v1,h1,l1);
                const size_t p = (size_t)row * 256 + col;
                *(uint32_t*)(g_hh + p) = packbf2(h0,h1);
                *(uint32_t*)(g_hl + p) = packbf2(l0,l1);
            }
        }
}

// G[bh] = ha_sp[b] @ MT[h]^T. grid (2, 1, 256): row0 = 0 (M=256 in one tile).
__global__ __launch_bounds__(256, 1) void g_mma_kernel() {
    extern __shared__ char sd[];
    const uint32_t sdu = s2u(sd);
    float c[4][8][4] = {};
    const int z = blockIdx.z, b = z >> 3, hh = z & 7;
    const int col0 = blockIdx.x * 128;
    mma_nt_mainloop(g_hh + (size_t)b * 262144, g_hl + (size_t)b * 262144, 256,
                    g_mth + (size_t)hh * 65536, g_mtl + (size_t)hh * 65536, 256,
                    0, col0, 256, sdu, c);
    const int lane = threadIdx.x & 31, wid = threadIdx.x >> 5;
    const int wm = (wid & 3) << 6, wn = (wid >> 2) << 6;
    bf16* Dh = g_gh + (size_t)z * 65536;
    bf16* Dl = g_gl + (size_t)z * 65536;
#pragma unroll
    for (int mi = 0; mi < 4; mi++)
#pragma unroll
        for (int j = 0; j < 8; j++) {
            const int col = col0 + wn + j * 8 + (lane & 3) * 2;
#pragma unroll
            for (int q = 0; q < 2; q++) {
                const int row = wm + mi * 16 + (lane >> 2) + q * 8;
                bf16 h0,l0,h1,l1;
                split2(c[mi][j][q*2],h0,l0); split2(c[mi][j][q*2+1],h1,l1);
                const size_t p = (size_t)row * 256 + col;
                *(uint32_t*)(Dh + p) = packbf2(h0,h1);
                *(uint32_t*)(Dl + p) = packbf2(l0,l1);
            }
        }
}

// S[bh] = G[bh] @ h[b]^T * SCALE -> fp32. grid (8, 1, 256).  [profiled slot]
__global__ __launch_bounds__(256, 1) void s_mma_kernel() {
    extern __shared__ char sd[];
    const uint32_t sdu = s2u(sd);
    float c[4][8][4] = {};
    const int z = blockIdx.z, b = z >> 3;
    const int col0 = blockIdx.x * 128;
    mma_nt_mainloop(g_gh + (size_t)z * 65536, g_gl + (size_t)z * 65536, 256,
                    g_hh + (size_t)b * 262144, g_hl + (size_t)b * 262144, 256,
                    0, col0, 256, sdu, c);
    const int lane = threadIdx.x & 31, wid = threadIdx.x >> 5;
    const int wm = (wid & 3) << 6, wn = (wid >> 2) << 6;
    float* D = g_S + (size_t)z * 262144;
#pragma unroll
    for (int mi = 0; mi < 4; mi++)
#pragma unroll
        for (int j = 0; j < 8; j++) {
            const int col = col0 + wn + j * 8 + (lane & 3) * 2;
#pragma unroll
            for (int q = 0; q < 2; q++) {
                const int row = wm + mi * 16 + (lane >> 2) + q * 8;
                float2 v;
                v.x = kScale * c[mi][j][q*2];
                v.y = kScale * c[mi][j][q*2+1];
                *(float2*)(D + (size_t)row * 1024 + col) = v;
            }
        }
}

// h_sp [b][n][d] -> h_spT [b][d][n].
__global__ __launch_bounds__(256) void transpose_h_kernel() {
    __shared__ bf16 t[64 * 65];
    const int d0 = blockIdx.x * 64, n0 = blockIdx.y * 64, b = blockIdx.z;
    const int tid = threadIdx.x;
    const bf16* ins[2]  = { g_hh, g_hl };
    bf16*       outs[2] = { g_hth, g_htl };
#pragma unroll
    for (int p = 0; p < 2; p++) {
        const bf16* in = ins[p] + (size_t)b * 1024 * 256;
        bf16* out      = outs[p] + (size_t)b * 256 * 1024;
#pragma unroll
        for (int i = 0; i < 8; i++) {
            int idx = tid + i * 256;
            int r = idx >> 5, c2 = idx & 31;
            uint32_t v = *(const uint32_t*)(in + (size_t)(n0 + r) * 256 + d0 + c2 * 2);
            __nv_bfloat162 bv = *reinterpret_cast<__nv_bfloat162*>(&v);
            t[r * 65 + c2 * 2]     = bv.x;
            t[r * 65 + c2 * 2 + 1] = bv.y;
        }
        __syncthreads();
#pragma unroll
        for (int i = 0; i < 8; i++) {
            int idx = tid + i * 256;
            int r = idx >> 5, c2 = idx & 31;
            uint32_t w = packbf2(t[(c2 * 2) * 65 + r], t[(c2 * 2 + 1) * 65 + r]);
            *(uint32_t*)(out + (size_t)(d0 + r) * 1024 + n0 + c2 * 2) = w;
        }
        __syncthreads();
    }
}

// prob = e*m / (sum(e*m) + eps*Z), split-bf16 output. bf16 mask.
__global__ __launch_bounds__(256) void softmax_kernel() {
    const int idx = blockIdx.x;          // (b*8+h)*256 + a
    const int a = idx & 255, b = idx >> 11;
    const float* row = g_S + (size_t)idx * 1024;
    const bf16* mrow = g_mb + ((size_t)b * 256 + a) * 1024;
    const int tid = threadIdx.x;

    float4 v = ((const float4*)row)[tid];
    uint2 mraw = *(const uint2*)(mrow + 4 * tid);
    __nv_bfloat162 m01 = *reinterpret_cast<__nv_bfloat162*>(&mraw.x);
    __nv_bfloat162 m23 = *reinterpret_cast<__nv_bfloat162*>(&mraw.y);
    const float mv0 = __bfloat162float(m01.x), mv1 = __bfloat162float(m01.y);
    const float mv2 = __bfloat162float(m23.x), mv3 = __bfloat162float(m23.y);

    float lmax = fmaxf(fmaxf(v.x, v.y), fmaxf(v.z, v.w));
#pragma unroll
    for (int o = 16; o > 0; o >>= 1)
        lmax = fmaxf(lmax, __shfl_xor_sync(0xffffffffu, lmax, o));

    __shared__ float redmax[8], redz[8], redm[8], bc[2];
    const int warp = tid >> 5, lane = tid & 31;
    if (lane == 0) redmax[warp] = lmax;
    __syncthreads();
    if (tid == 0) {
        float mx = redmax[0];
        for (int w = 1; w < 8; w++) mx = fmaxf(mx, redmax[w]);
        bc[0] = mx;
    }
    __syncthreads();
    const float mx = bc[0];

    float e0 = __expf(v.x - mx), e1 = __expf(v.y - mx);
    float e2 = __expf(v.z - mx), e3 = __expf(v.w - mx);
    float zs = e0 + e1 + e2 + e3;
    float ms = e0 * mv0 + e1 * mv1 + e2 * mv2 + e3 * mv3;
#pragma unroll
    for (int o = 16; o > 0; o >>= 1) {
        zs += __shfl_xor_sync(0xffffffffu, zs, o);
        ms += __shfl_xor_sync(0xffffffffu, ms, o);
    }
    if (lane == 0) { redz[warp] = zs; redm[warp] = ms; }
    __syncthreads();
    if (tid == 0) {
        float tz = 0.f, tm = 0.f;
        for (int w = 0; w < 8; w++) { tz += redz[w]; tm += redm[w]; }
        bc[1] = 1.0f / (tm + kEps * tz);
    }
    __syncthreads();
    const float inv = bc[1];

    float p0 = e0 * mv0 * inv, p1 = e1 * mv1 * inv;
    float p2 = e2 * mv2 * inv, p3 = e3 * mv3 * inv;
    bf16 h0,l0,h1,l1,h2,l2,h3,l3;
    split2(p0,h0,l0); split2(p1,h1,l1); split2(p2,h2,l2); split2(p3,h3,l3);
    size_t base = (size_t)idx * 1024 + 4 * tid;
    *(uint2*)(g_ph + base) = make_uint2(packbf2(h0,h1), packbf2(h2,h3));
    *(uint2*)(g_pl + base) = make_uint2(packbf2(l0,l1), packbf2(l2,l3));
}

// Ucat[b][a][h*256+d] = prob[bh] @ h[b].  grid (2, 1, 256), K=1024.
__global__ __launch_bounds__(256, 1) void u_mma_kernel() {
    extern __shared__ char sd[];
    const uint32_t sdu = s2u(sd);
    float c[4][8][4] = {};
    const int z = blockIdx.z, b = z >> 3, hh = z & 7;
    const int col0 = blockIdx.x * 128;
    mma_nt_mainloop(g_ph + (size_t)z * 262144, g_pl + (size_t)z * 262144, 1024,
                    g_hth + (size_t)b * 262144, g_htl + (size_t)b * 262144, 1024,
                    0, col0, 1024, sdu, c);
    const int lane = threadIdx.x & 31, wid = threadIdx.x >> 5;
    const int wm = (wid & 3) << 6, wn = (wid >> 2) << 6;
#pragma unroll
    for (int mi = 0; mi < 4; mi++)
#pragma unroll
        for (int j = 0; j < 8; j++) {
            const int col = col0 + wn + j * 8 + (lane & 3) * 2;
#pragma unroll
            for (int q = 0; q < 2; q++) {
                const int row = wm + mi * 16 + (lane >> 2) + q * 8;
                bf16 h0,l0,h1,l1;
                split2(c[mi][j][q*2],h0,l0); split2(c[mi][j][q*2+1],h1,l1);
                const size_t p = ((size_t)b * 256 + row) * 2048 + hh * 256 + col;
                *(uint32_t*)(g_uh + p) = packbf2(h0,h1);
                *(uint32_t*)(g_ul + p) = packbf2(l0,l1);
            }
        }
}

// out[b] = 1/8 * Ucat[b] @ WVT_cat^T.  grid (2, 1, 32), K=2048.
__global__ __launch_bounds__(256, 1) void out_mma_kernel(float* __restrict__ out) {
    extern __shared__ char sd[];
    const uint32_t sdu = s2u(sd);
    float c[4][8][4] = {};
    const int b = blockIdx.z;
    const int col0 = blockIdx.x * 128;
    mma_nt_mainloop(g_uh + (size_t)b * 524288, g_ul + (size_t)b * 524288, 2048,
                    g_wvh, g_wvl, 2048, 0, col0, 2048, sdu, c);
    const int lane = threadIdx.x & 31, wid = threadIdx.x >> 5;
    const int wm = (wid & 3) << 6, wn = (wid >> 2) << 6;
    float* D = out + (size_t)b * 65536;
#pragma unroll
    for (int mi = 0; mi < 4; mi++)
#pragma unroll
        for (int j = 0; j < 8; j++) {
            const int col = col0 + wn + j * 8 + (lane & 3) * 2;
#pragma unroll
            for (int q = 0; q < 2; q++) {
                const int row = wm + mi * 16 + (lane >> 2) + q * 8;
                float2 v;
                v.x = 0.125f * c[mi][j][q*2];
                v.y = 0.125f * c[mi][j][q*2+1];
                *(float2*)(D + (size_t)row * 256 + col) = v;
            }
        }
}

// ===========================================================================
extern "C" void kernel_launch(void* const* d_in, const int* in_sizes, int n_in,
                              void* d_out, int out_size)
{
    const float* x     = (const float*)d_in[0];
    const float* m     = (const float*)d_in[1];
    const float* W_enc = (const float*)d_in[2];
    const float* b_enc = (const float*)d_in[3];
    const float* WQ    = (const float*)d_in[4];
    const float* WK    = (const float*)d_in[5];
    const float* WV    = (const float*)d_in[6];
    float* out = (float*)d_out;

    cudaFuncSetAttribute(enc_mma_kernel, cudaFuncAttributeMaxDynamicSharedMemorySize, kDynSmem);
    cudaFuncSetAttribute(g_mma_kernel,   cudaFuncAttributeMaxDynamicSharedMemorySize, kDynSmem);
    cudaFuncSetAttribute(s_mma_kernel,   cudaFuncAttributeMaxDynamicSharedMemorySize, kDynSmem);
    cudaFuncSetAttribute(u_mma_kernel,   cudaFuncAttributeMaxDynamicSharedMemorySize, kDynSmem);
    cudaFuncSetAttribute(out_mma_kernel, cudaFuncAttributeMaxDynamicSharedMemorySize, kDynSmem);

    prep_kernel<<<17088, 256>>>(x, W_enc, WV, WQ, WK, m);             // launch 1
    enc_mma_kernel<<<dim3(2, 128), 256, kDynSmem>>>(b_enc);           // launch 2
    g_mma_kernel<<<dim3(2, 1, 256), 256, kDynSmem>>>();               // launch 3
    s_mma_kernel<<<dim3(8, 1, 256), 256, kDynSmem>>>();               // launch 4 (profiled)
    transpose_h_kernel<<<dim3(4, 16, 32), 256>>>();                   // launch 5
    softmax_kernel<<<65536, 256>>>();                                 // launch 6
    u_mma_kernel<<<dim3(2, 1, 256), 256, kDynSmem>>>();               // launch 7
    out_mma_kernel<<<dim3(2, 1, 32), 256, kDynSmem>>>(out);           // launch 8
}

// round 11
// speedup vs baseline: 1.2883x; 1.2883x over previous
#include <cuda_runtime.h>
#include <cuda_bf16.h>
#include <cuda_fp16.h>
#include <cstdint>

using bf16 = __nv_bfloat16;
using fp16 = __half;

// ===========================================================================
// MHA_73607149519311 — round 11: r9 config restored (64x64 warp tile, 128-thr
// CTAs, 2 CTAs/SM) + U GEMM reduced to 2 fp16 passes:
//   U = prob_fp16 @ (h_hi16 + h_lo16)    (prob stored single fp16; error
//   std ~2^-12, far under the 1e-3 budget; S path stays 3xbf16)
// transpose+softmax fused into one launch; softmax writes prob once (fp16).
// ===========================================================================

namespace {
constexpr float kScale = 1.0f / 16.0f;   // 1/sqrt(256)
constexpr float kEps   = 1e-12f;
constexpr int kDynSmem  = 98304;         // bf16 mainloop: 3 stages x 32KB
constexpr int kDynSmemU = 73728;         // u mainloop:    3 stages x 24KB
}

// ---- scratch (static device globals; no dynamic allocation) ----
#define DEVBUF(name, count) __device__ __align__(128) bf16 name[count]
#define DEVBUFH(name, count) __device__ __align__(128) fp16 name[count]
DEVBUF(g_xh, 8388608);  DEVBUF(g_xl, 8388608);    // leaky(x) split   [32768,256]
DEVBUF(g_weh, 65536);   DEVBUF(g_wel, 65536);     // W_enc split      [256,256]
DEVBUF(g_mth, 524288);  DEVBUF(g_mtl, 524288);    // MT=WK@WQ^T split [8,256,256]
DEVBUF(g_hh, 8388608);  DEVBUF(g_hl, 8388608);    // h split          [32,1024,256]
DEVBUF(g_gh, 16777216); DEVBUF(g_gl, 16777216);   // G split          [256,256,256]
DEVBUF(g_uh, 16777216); DEVBUF(g_ul, 16777216);   // U concat split   [32,256,2048]
DEVBUF(g_wvh, 524288);  DEVBUF(g_wvl, 524288);    // WVT_cat split    [256,2048]
DEVBUF(g_mb, 8388608);                             // mask bf16        [32,256,1024]
DEVBUFH(g_pf, 67108864);                           // prob fp16        [256,256,1024]
DEVBUFH(g_h16h, 8388608); DEVBUFH(g_h16l, 8388608);// h^T fp16 split   [32,256,1024]
__device__ __align__(128) float g_S[67108864];     // S fp32           [256,256,1024]

// ============================= helpers =====================================
__device__ __forceinline__ uint32_t s2u(const void* p) {
    uint32_t a;
    asm("{ .reg .u64 t; cvta.to.shared.u64 t, %1; cvt.u32.u64 %0, t; }"
        : "=r"(a) : "l"(p));
    return a;
}

__device__ __forceinline__ void cp16(uint32_t saddr, const void* gaddr) {
    asm volatile("cp.async.cg.shared.global [%0], [%1], 16;"
                 :: "r"(saddr), "l"(gaddr) : "memory");
}
#define CP_COMMIT() asm volatile("cp.async.commit_group;" ::: "memory")
#define CP_WAIT1()  asm volatile("cp.async.wait_group 1;" ::: "memory")
#define CP_WAIT0()  asm volatile("cp.async.wait_group 0;" ::: "memory")

__device__ __forceinline__ void ldmx4(uint32_t* r, uint32_t addr) {
    asm volatile("ldmatrix.sync.aligned.m8n8.x4.shared.b16 {%0,%1,%2,%3}, [%4];"
                 : "=r"(r[0]), "=r"(r[1]), "=r"(r[2]), "=r"(r[3]) : "r"(addr));
}

__device__ __forceinline__ void mma16816(float* c, const uint32_t* a,
                                         uint32_t b0, uint32_t b1) {
    asm volatile(
        "mma.sync.aligned.m16n8k16.row.col.f32.bf16.bf16.f32 "
        "{%0,%1,%2,%3}, {%4,%5,%6,%7}, {%8,%9}, {%0,%1,%2,%3};"
        : "+f"(c[0]), "+f"(c[1]), "+f"(c[2]), "+f"(c[3])
        : "r"(a[0]), "r"(a[1]), "r"(a[2]), "r"(a[3]), "r"(b0), "r"(b1));
}

__device__ __forceinline__ void mma16816h(float* c, const uint32_t* a,
                                          uint32_t b0, uint32_t b1) {
    asm volatile(
        "mma.sync.aligned.m16n8k16.row.col.f32.f16.f16.f32 "
        "{%0,%1,%2,%3}, {%4,%5,%6,%7}, {%8,%9}, {%0,%1,%2,%3};"
        : "+f"(c[0]), "+f"(c[1]), "+f"(c[2]), "+f"(c[3])
        : "r"(a[0]), "r"(a[1]), "r"(a[2]), "r"(a[3]), "r"(b0), "r"(b1));
}

__device__ __forceinline__ void split2(float v, bf16& hi, bf16& lo) {
    hi = __float2bfloat16(v);
    lo = __float2bfloat16(v - __bfloat162float(hi));
}
__device__ __forceinline__ void split2h(float v, fp16& hi, fp16& lo) {
    hi = __float2half(v);
    lo = __float2half(v - __half2float(hi));
}
__device__ __forceinline__ uint32_t packbf2(bf16 a, bf16 b) {
    __nv_bfloat162 t; t.x = a; t.y = b;
    return *reinterpret_cast<uint32_t*>(&t);
}
__device__ __forceinline__ uint32_t packh2(fp16 a, fp16 b) {
    __half2 t; t.x = a; t.y = b;
    return *reinterpret_cast<uint32_t*>(&t);
}

// Swizzled offset within a (rows x 64B) tile: row r, seg s (0..3).
__device__ __forceinline__ uint32_t sw64(int r, int s) {
    return (uint32_t)((r << 6) + (((s ^ ((r >> 1) & 3)) & 3) << 4));
}

// ==================== bf16 split-2 mainloop (r9, proven) ===================
// CTA tile 128x128, NT. 128 threads = 4 warps (2M x 2N), warp tile 64x64.
// cp.async 3-stage, K chunks of 32. Stage (32KB): Ahi|Alo|Bhi|Blo 8K each.

__device__ __forceinline__ void issue_chunk(
    const bf16* __restrict__ Ah, const bf16* __restrict__ Al, int lda,
    const bf16* __restrict__ Bh, const bf16* __restrict__ Bl, int ldb,
    int row0, int col0, int kt, uint32_t sb)
{
    const int tid = threadIdx.x;
#pragma unroll
    for (int i = 0; i < 4; i++) {
        const int idx = tid + i * 128;       // 0..511
        const int r = idx >> 2, s = idx & 3;
        const uint32_t off = sw64(r, s);
        const size_t ga = (size_t)(row0 + r) * lda + kt + s * 8;
        const size_t gb = (size_t)(col0 + r) * ldb + kt + s * 8;
        cp16(sb + off,         Ah + ga);
        cp16(sb + 8192 + off,  Al + ga);
        cp16(sb + 16384 + off, Bh + gb);
        cp16(sb + 24576 + off, Bl + gb);
    }
    CP_COMMIT();
}

__device__ __forceinline__ void mma_nt_mainloop(
    const bf16* __restrict__ Ah, const bf16* __restrict__ Al, int lda,
    const bf16* __restrict__ Bh, const bf16* __restrict__ Bl, int ldb,
    int row0, int col0, int K, uint32_t sdu, float (&c)[4][8][4])
{
    const int tid = threadIdx.x;
    const int lane = tid & 31, wid = tid >> 5;
    const int wm = (wid & 1) << 6;
    const int wn = (wid >> 1) << 6;

    const int arow0 = wm + (lane & 15);
    const int akseg = lane >> 4;
    const int brow0 = wn + ((lane >> 4) << 3) + (lane & 7);
    const int bkseg = (lane >> 3) & 1;

    const int NC = K >> 5;
    issue_chunk(Ah, Al, lda, Bh, Bl, ldb, row0, col0, 0, sdu);
    issue_chunk(Ah, Al, lda, Bh, Bl, ldb, row0, col0, 32, sdu + 32768);

    int buf = 0;
    for (int ci = 0; ci < NC; ci++) {
        if (ci + 1 < NC) { CP_WAIT1(); } else { CP_WAIT0(); }
        __syncthreads();
        if (ci + 2 < NC) {
            int nb = buf + 2; if (nb >= 3) nb -= 3;
            issue_chunk(Ah, Al, lda, Bh, Bl, ldb, row0, col0,
                        (ci + 2) << 5, sdu + nb * 32768);
        }

        const uint32_t sb = sdu + buf * 32768;
#pragma unroll
        for (int k = 0; k < 2; k++) {
            uint32_t afh[4][4], afl[4][4], bfh[4][4], bfl[4][4];
#pragma unroll
            for (int mi = 0; mi < 4; mi++) {
                const int r = arow0 + mi * 16;
                const uint32_t off = sw64(r, 2 * k + akseg);
                ldmx4(afh[mi], sb + off);
                ldmx4(afl[mi], sb + 8192 + off);
            }
#pragma unroll
            for (int nj = 0; nj < 4; nj++) {
                const int r = brow0 + nj * 16;
                const uint32_t off = sw64(r, 2 * k + bkseg);
                ldmx4(bfh[nj], sb + 16384 + off);
                ldmx4(bfl[nj], sb + 24576 + off);
            }
#pragma unroll
            for (int mi = 0; mi < 4; mi++)
#pragma unroll
                for (int ni = 0; ni < 8; ni++) {
                    const int nj = ni >> 1, o = (ni & 1) << 1;
                    mma16816(c[mi][ni], afh[mi], bfh[nj][o], bfh[nj][o + 1]);
                }
#pragma unroll
            for (int mi = 0; mi < 4; mi++)
#pragma unroll
                for (int ni = 0; ni < 8; ni++) {
                    const int nj = ni >> 1, o = (ni & 1) << 1;
                    mma16816(c[mi][ni], afh[mi], bfl[nj][o], bfl[nj][o + 1]);
                }
#pragma unroll
            for (int mi = 0; mi < 4; mi++)
#pragma unroll
                for (int ni = 0; ni < 8; ni++) {
                    const int nj = ni >> 1, o = (ni & 1) << 1;
                    mma16816(c[mi][ni], afl[mi], bfh[nj][o], bfh[nj][o + 1]);
                }
        }
        if (++buf == 3) buf = 0;
    }
}

// ==================== fp16 2-pass mainloop (u only) ========================
// A = prob fp16 (single), B = h^T fp16 split. Stage (24KB): A|Bhi|Blo 8K each.

__device__ __forceinline__ void issue_chunk_u(
    const fp16* __restrict__ A, int lda,
    const fp16* __restrict__ Bh, const fp16* __restrict__ Bl, int ldb,
    int row0, int col0, int kt, uint32_t sb)
{
    const int tid = threadIdx.x;
#pragma unroll
    for (int i = 0; i < 4; i++) {
        const int idx = tid + i * 128;       // 0..511
        const int r = idx >> 2, s = idx & 3;
        const uint32_t off = sw64(r, s);
        const size_t ga = (size_t)(row0 + r) * lda + kt + s * 8;
        const size_t gb = (size_t)(col0 + r) * ldb + kt + s * 8;
        cp16(sb + off,         A + ga);
        cp16(sb + 8192 + off,  Bh + gb);
        cp16(sb + 16384 + off, Bl + gb);
    }
    CP_COMMIT();
}

__device__ __forceinline__ void mma_nt_mainloop_u(
    const fp16* __restrict__ A, int lda,
    const fp16* __restrict__ Bh, const fp16* __restrict__ Bl, int ldb,
    int row0, int col0, int K, uint32_t sdu, float (&c)[4][8][4])
{
    const int tid = threadIdx.x;
    const int lane = tid & 31, wid = tid >> 5;
    const int wm = (wid & 1) << 6;
    const int wn = (wid >> 1) << 6;

    const int arow0 = wm + (lane & 15);
    const int akseg = lane >> 4;
    const int brow0 = wn + ((lane >> 4) << 3) + (lane & 7);
    const int bkseg = (lane >> 3) & 1;

    const int NC = K >> 5;
    issue_chunk_u(A, lda, Bh, Bl, ldb, row0, col0, 0, sdu);
    issue_chunk_u(A, lda, Bh, Bl, ldb, row0, col0, 32, sdu + 24576);

    int buf = 0;
    for (int ci = 0; ci < NC; ci++) {
        if (ci + 1 < NC) { CP_WAIT1(); } else { CP_WAIT0(); }
        __syncthreads();
        if (ci + 2 < NC) {
            int nb = buf + 2; if (nb >= 3) nb -= 3;
            issue_chunk_u(A, lda, Bh, Bl, ldb, row0, col0,
                          (ci + 2) << 5, sdu + nb * 24576);
        }

        const uint32_t sb = sdu + buf * 24576;
#pragma unroll
        for (int k = 0; k < 2; k++) {
            uint32_t af[4][4], bfh[4][4], bfl[4][4];
#pragma unroll
            for (int mi = 0; mi < 4; mi++) {
                const int r = arow0 + mi * 16;
                const uint32_t off = sw64(r, 2 * k + akseg);
                ldmx4(af[mi], sb + off);
            }
#pragma unroll
            for (int nj = 0; nj < 4; nj++) {
                const int r = brow0 + nj * 16;
                const uint32_t off = sw64(r, 2 * k + bkseg);
                ldmx4(bfh[nj], sb + 8192 + off);
                ldmx4(bfl[nj], sb + 16384 + off);
            }
#pragma unroll
            for (int mi = 0; mi < 4; mi++)
#pragma unroll
                for (int ni = 0; ni < 8; ni++) {
                    const int nj = ni >> 1, o = (ni & 1) << 1;
                    mma16816h(c[mi][ni], af[mi], bfh[nj][o], bfh[nj][o + 1]);
                }
#pragma unroll
            for (int mi = 0; mi < 4; mi++)
#pragma unroll
                for (int ni = 0; ni < 8; ni++) {
                    const int nj = ni >> 1, o = (ni & 1) << 1;
                    mma16816h(c[mi][ni], af[mi], bfl[nj][o], bfl[nj][o + 1]);
                }
        }
        if (++buf == 3) buf = 0;
    }
}

// Epilogue mapping (both loops) for c[mi][j][q]:
//   row = row0 + wm + mi*16 + (lane>>2) + (q>=2 ? 8 : 0)
//   col = col0 + wn + j*8 + (lane&3)*2 + (q&1)
//   wm = (wid&1)<<6, wn = (wid>>1)<<6

// ===================== merged prep kernel (launch #1) ======================
__global__ __launch_bounds__(256) void prep_kernel(
    const float* __restrict__ x, const float* __restrict__ W_enc,
    const float* __restrict__ WV,
    const float* __restrict__ WQ, const float* __restrict__ WK,
    const float* __restrict__ m)
{
    const int bid = blockIdx.x;
    if (bid < 8192) {
        size_t idx = (size_t)bid * 256 + threadIdx.x;   // over float4s
        float4 v = ((const float4*)x)[idx];
        v.x = v.x > 0.f ? v.x : 0.01f * v.x;
        v.y = v.y > 0.f ? v.y : 0.01f * v.y;
        v.z = v.z > 0.f ? v.z : 0.01f * v.z;
        v.w = v.w > 0.f ? v.w : 0.01f * v.w;
        bf16 h0,l0,h1,l1,h2,l2,h3,l3;
        split2(v.x,h0,l0); split2(v.y,h1,l1); split2(v.z,h2,l2); split2(v.w,h3,l3);
        *(uint2*)(g_xh + idx * 4) = make_uint2(packbf2(h0,h1), packbf2(h2,h3));
        *(uint2*)(g_xl + idx * 4) = make_uint2(packbf2(l0,l1), packbf2(l2,l3));
        return;
    }
    if (bid < 8256) {
        size_t idx = (size_t)(bid - 8192) * 256 + threadIdx.x;  // 16384 float4s
        float4 v = ((const float4*)W_enc)[idx];
        bf16 h0,l0,h1,l1,h2,l2,h3,l3;
        split2(v.x,h0,l0); split2(v.y,h1,l1); split2(v.z,h2,l2); split2(v.w,h3,l3);
        *(uint2*)(g_weh + idx * 4) = make_uint2(packbf2(h0,h1), packbf2(h2,h3));
        *(uint2*)(g_wel + idx * 4) = make_uint2(packbf2(l0,l1), packbf2(l2,l3));
        return;
    }
    if (bid < 8768) {
        __shared__ float t[32][33];
        const int tb = bid - 8256;
        const int k0 = (tb & 63) * 32, e0 = (tb >> 6) * 32;
        const int tx = threadIdx.x & 31, ty = threadIdx.x >> 5;
#pragma unroll
        for (int i = 0; i < 4; i++) {
            const int k = ty + i * 8;
            t[k][tx] = WV[(size_t)(k0 + k) * 256 + e0 + tx];
        }
        __syncthreads();
#pragma unroll
        for (int i = 0; i < 4; i++) {
            const int e = ty + i * 8;
            const float v = t[tx][e];
            bf16 hi, lo; split2(v, hi, lo);
            const size_t o = (size_t)(e0 + e) * 2048 + k0 + tx;
            g_wvh[o] = hi; g_wvl[o] = lo;
        }
        return;
    }
    if (bid < 8896) {
        __shared__ float As[8][68], Bs[8][68];
        float acc[4][4] = {};
        const int tb = bid - 8768;
        const int hh = tb >> 4;
        const int row0 = ((tb >> 2) & 3) * 64, col0 = (tb & 3) * 64;
        const float* A = WK + (size_t)hh * 65536;
        const float* B = WQ + (size_t)hh * 65536;
        const int tid = threadIdx.x;
        const int lr = tid >> 2, lk = (tid & 3) << 1;
        const int tx = tid & 15, ty = tid >> 4;
        const float* aP = A + (size_t)(row0 + lr) * 256 + lk;
        const float* bP = B + (size_t)(col0 + lr) * 256 + lk;
        for (int kt = 0; kt < 256; kt += 8) {
            float2 av = *(const float2*)(aP + kt);
            float2 bv = *(const float2*)(bP + kt);
            As[lk][lr] = av.x; As[lk + 1][lr] = av.y;
            Bs[lk][lr] = bv.x; Bs[lk + 1][lr] = bv.y;
            __syncthreads();
#pragma unroll
            for (int k = 0; k < 8; k++) {
                float ar[4], br[4];
                *(float4*)ar = *(const float4*)(&As[k][ty * 4]);
                *(float4*)br = *(const float4*)(&Bs[k][tx * 4]);
#pragma unroll
                for (int i = 0; i < 4; i++)
#pragma unroll
                    for (int j = 0; j < 4; j++)
                        acc[i][j] = fmaf(ar[i], br[j], acc[i][j]);
            }
            __syncthreads();
        }
        bf16* Dh = g_mth + (size_t)hh * 65536;
        bf16* Dl = g_mtl + (size_t)hh * 65536;
#pragma unroll
        for (int i = 0; i < 4; i++) {
            size_t base = (size_t)(row0 + ty * 4 + i) * 256 + col0 + tx * 4;
#pragma unroll
            for (int j = 0; j < 4; j += 2) {
                bf16 h0,l0,h1,l1;
                split2(acc[i][j],h0,l0); split2(acc[i][j+1],h1,l1);
                *(uint32_t*)(Dh + base + j) = packbf2(h0,h1);
                *(uint32_t*)(Dl + base + j) = packbf2(l0,l1);
            }
        }
        return;
    }
    {
        size_t idx = (size_t)(bid - 8896) * 256 + threadIdx.x;  // 2097152 float4s
        float4 v = ((const float4*)m)[idx];
        uint2 w = make_uint2(
            packbf2(__float2bfloat16(v.x), __float2bfloat16(v.y)),
            packbf2(__float2bfloat16(v.z), __float2bfloat16(v.w)));
        *(uint2*)(g_mb + idx * 4) = w;
    }
}

// ============================== MMA kernels ================================

// h = x_sp @ Wenc^T + b. grid (2, 256).
__global__ __launch_bounds__(128, 2) void enc_mma_kernel(const float* __restrict__ bias) {
    extern __shared__ char sd[];
    const uint32_t sdu = s2u(sd);
    float c[4][8][4] = {};
    const int row0 = blockIdx.y * 128, col0 = blockIdx.x * 128;
    mma_nt_mainloop(g_xh, g_xl, 256, g_weh, g_wel, 256, row0, col0, 256, sdu, c);
    const int lane = threadIdx.x & 31, wid = threadIdx.x >> 5;
    const int wm = (wid & 1) << 6, wn = (wid >> 1) << 6;
#pragma unroll
    for (int mi = 0; mi < 4; mi++)
#pragma unroll
        for (int j = 0; j < 8; j++) {
            const int col = col0 + wn + j * 8 + (lane & 3) * 2;
            const float b0 = bias[col], b1 = bias[col + 1];
#pragma unroll
            for (int q = 0; q < 2; q++) {
                const int row = row0 + wm + mi * 16 + (lane >> 2) + q * 8;
                const float v0 = c[mi][j][q * 2]     + b0;
                const float v1 = c[mi][j][q * 2 + 1] + b1;
                bf16 h0,l0,h1,l1; split2(v0,h0,l0); split2(v1,h1,l1);
                const size_t p = (size_t)row * 256 + col;
                *(uint32_t*)(g_hh + p) = packbf2(h0,h1);
                *(uint32_t*)(g_hl + p) = packbf2(l0,l1);
            }
        }
}

// G[bh] = ha_sp[b] @ MT[h]^T. grid (2, 2, 256).
__global__ __launch_bounds__(128, 2) void g_mma_kernel() {
    extern __shared__ char sd[];
    const uint32_t sdu = s2u(sd);
    float c[4][8][4] = {};
    const int z = blockIdx.z, b = z >> 3, hh = z & 7;
    const int row0 = blockIdx.y * 128, col0 = blockIdx.x * 128;
    mma_nt_mainloop(g_hh + (size_t)b * 262144, g_hl + (size_t)b * 262144, 256,
                    g_mth + (size_t)hh * 65536, g_mtl + (size_t)hh * 65536, 256,
                    row0, col0, 256, sdu, c);
    const int lane = threadIdx.x & 31, wid = threadIdx.x >> 5;
    const int wm = (wid & 1) << 6, wn = (wid >> 1) << 6;
    bf16* Dh = g_gh + (size_t)z * 65536;
    bf16* Dl = g_gl + (size_t)z * 65536;
#pragma unroll
    for (int mi = 0; mi < 4; mi++)
#pragma unroll
        for (int j = 0; j < 8; j++) {
            const int col = col0 + wn + j * 8 + (lane & 3) * 2;
#pragma unroll
            for (int q = 0; q < 2; q++) {
                const int row = row0 + wm + mi * 16 + (lane >> 2) + q * 8;
                bf16 h0,l0,h1,l1;
                split2(c[mi][j][q*2],h0,l0); split2(c[mi][j][q*2+1],h1,l1);
                const size_t p = (size_t)row * 256 + col;
                *(uint32_t*)(Dh + p) = packbf2(h0,h1);
                *(uint32_t*)(Dl + p) = packbf2(l0,l1);
            }
        }
}

// S[bh] = G[bh] @ h[b]^T * SCALE -> fp32. grid (8, 2, 256).  [profiled slot]
__global__ __launch_bounds__(128, 2) void s_mma_kernel() {
    extern __shared__ char sd[];
    const uint32_t sdu = s2u(sd);
    float c[4][8][4] = {};
    const int z = blockIdx.z, b = z >> 3;
    const int row0 = blockIdx.y * 128, col0 = blockIdx.x * 128;
    mma_nt_mainloop(g_gh + (size_t)z * 65536, g_gl + (size_t)z * 65536, 256,
                    g_hh + (size_t)b * 262144, g_hl + (size_t)b * 262144, 256,
                    row0, col0, 256, sdu, c);
    const int lane = threadIdx.x & 31, wid = threadIdx.x >> 5;
    const int wm = (wid & 1) << 6, wn = (wid >> 1) << 6;
    float* D = g_S + (size_t)z * 262144;
#pragma unroll
    for (int mi = 0; mi < 4; mi++)
#pragma unroll
        for (int j = 0; j < 8; j++) {
            const int col = col0 + wn + j * 8 + (lane & 3) * 2;
#pragma unroll
            for (int q = 0; q < 2; q++) {
                const int row = row0 + wm + mi * 16 + (lane >> 2) + q * 8;
                float2 v;
                v.x = kScale * c[mi][j][q*2];
                v.y = kScale * c[mi][j][q*2+1];
                *(float2*)(D + (size_t)row * 1024 + col) = v;
            }
        }
}

// =============== fused softmax + h-transpose (launch #5) ===================
// bid < 65536: softmax row (b*8+h)*256 + a; writes prob as fp16.
// bid >= 65536: transpose tile of h (bf16 split -> fp16 split, [n,d]->[d,n]).
__global__ __launch_bounds__(256) void post_kernel() {
    const int bid = blockIdx.x;
    const int tid = threadIdx.x;
    if (bid < 65536) {
        const int idx = bid;
        const int a = idx & 255, b = idx >> 11;
        const float* row = g_S + (size_t)idx * 1024;
        const bf16* mrow = g_mb + ((size_t)b * 256 + a) * 1024;

        float4 v = ((const float4*)row)[tid];
        uint2 mraw = *(const uint2*)(mrow + 4 * tid);
        __nv_bfloat162 m01 = *reinterpret_cast<__nv_bfloat162*>(&mraw.x);
        __nv_bfloat162 m23 = *reinterpret_cast<__nv_bfloat162*>(&mraw.y);
        const float mv0 = __bfloat162float(m01.x), mv1 = __bfloat162float(m01.y);
        const float mv2 = __bfloat162float(m23.x), mv3 = __bfloat162float(m23.y);

        float lmax = fmaxf(fmaxf(v.x, v.y), fmaxf(v.z, v.w));
#pragma unroll
        for (int o = 16; o > 0; o >>= 1)
            lmax = fmaxf(lmax, __shfl_xor_sync(0xffffffffu, lmax, o));

        __shared__ float redmax[8], redz[8], redm[8], bc[2];
        const int warp = tid >> 5, lane = tid & 31;
        if (lane == 0) redmax[warp] = lmax;
        __syncthreads();
        if (tid == 0) {
            float mx = redmax[0];
            for (int w = 1; w < 8; w++) mx = fmaxf(mx, redmax[w]);
            bc[0] = mx;
        }
        __syncthreads();
        const float mx = bc[0];

        float e0 = __expf(v.x - mx), e1 = __expf(v.y - mx);
        float e2 = __expf(v.z - mx), e3 = __expf(v.w - mx);
        float zs = e0 + e1 + e2 + e3;
        float ms = e0 * mv0 + e1 * mv1 + e2 * mv2 + e3 * mv3;
#pragma unroll
        for (int o = 16; o > 0; o >>= 1) {
            zs += __shfl_xor_sync(0xffffffffu, zs, o);
            ms += __shfl_xor_sync(0xffffffffu, ms, o);
        }
        if (lane == 0) { redz[warp] = zs; redm[warp] = ms; }
        __syncthreads();
        if (tid == 0) {
            float tz = 0.f, tm = 0.f;
            for (int w = 0; w < 8; w++) { tz += redz[w]; tm += redm[w]; }
            bc[1] = 1.0f / (tm + kEps * tz);
        }
        __syncthreads();
        const float inv = bc[1];

        const fp16 p0 = __float2half(e0 * mv0 * inv);
        const fp16 p1 = __float2half(e1 * mv1 * inv);
        const fp16 p2 = __float2half(e2 * mv2 * inv);
        const fp16 p3 = __float2half(e3 * mv3 * inv);
        *(uint2*)(g_pf + (size_t)idx * 1024 + 4 * tid) =
            make_uint2(packh2(p0, p1), packh2(p2, p3));
        return;
    }
    // ---- transpose: h (bf16 hi+lo, [b][n][d]) -> fp16 split [b][d][n] ----
    __shared__ fp16 th[64 * 65], tl[64 * 65];
    const int tb = bid - 65536;              // 0..2047
    const int b = tb >> 6;
    const int rem = tb & 63;
    const int n0 = (rem >> 2) * 64, d0 = (rem & 3) * 64;
    const bf16* inh = g_hh + (size_t)b * 262144;
    const bf16* inl = g_hl + (size_t)b * 262144;
#pragma unroll
    for (int i = 0; i < 8; i++) {
        int idx = tid + i * 256;
        int r = idx >> 5, c2 = idx & 31;
        uint32_t vh = *(const uint32_t*)(inh + (size_t)(n0 + r) * 256 + d0 + c2 * 2);
        uint32_t vl = *(const uint32_t*)(inl + (size_t)(n0 + r) * 256 + d0 + c2 * 2);
        __nv_bfloat162 bh = *reinterpret_cast<__nv_bfloat162*>(&vh);
        __nv_bfloat162 bl = *reinterpret_cast<__nv_bfloat162*>(&vl);
        float f0 = __bfloat162float(bh.x) + __bfloat162float(bl.x);
        float f1 = __bfloat162float(bh.y) + __bfloat162float(bl.y);
        fp16 h0, l0, h1, l1;
        split2h(f0, h0, l0); split2h(f1, h1, l1);
        th[r * 65 + c2 * 2] = h0; th[r * 65 + c2 * 2 + 1] = h1;
        tl[r * 65 + c2 * 2] = l0; tl[r * 65 + c2 * 2 + 1] = l1;
    }
    __syncthreads();
    fp16* oh = g_h16h + (size_t)b * 262144;
    fp16* ol = g_h16l + (size_t)b * 262144;
#pragma unroll
    for (int i = 0; i < 8; i++) {
        int idx = tid + i * 256;
        int r = idx >> 5, c2 = idx & 31;   // r = d_local, c2 = n pair
        uint32_t wh = packh2(th[(c2 * 2) * 65 + r], th[(c2 * 2 + 1) * 65 + r]);
        uint32_t wl = packh2(tl[(c2 * 2) * 65 + r], tl[(c2 * 2 + 1) * 65 + r]);
        *(uint32_t*)(oh + (size_t)(d0 + r) * 1024 + n0 + c2 * 2) = wh;
        *(uint32_t*)(ol + (size_t)(d0 + r) * 1024 + n0 + c2 * 2) = wl;
    }
}

// Ucat[b][a][h*256+d] = prob[bh] @ h[b].  grid (2, 2, 256), K=1024. fp16 2-pass.
__global__ __launch_bounds__(128, 2) void u_mma_kernel() {
    extern __shared__ char sd[];
    const uint32_t sdu = s2u(sd);
    float c[4][8][4] = {};
    const int z = blockIdx.z, b = z >> 3, hh = z & 7;
    const int row0 = blockIdx.y * 128, col0 = blockIdx.x * 128;
    mma_nt_mainloop_u(g_pf + (size_t)z * 262144, 1024,
                      g_h16h + (size_t)b * 262144, g_h16l + (size_t)b * 262144, 1024,
                      row0, col0, 1024, sdu, c);
    const int lane = threadIdx.x & 31, wid = threadIdx.x >> 5;
    const int wm = (wid & 1) << 6, wn = (wid >> 1) << 6;
#pragma unroll
    for (int mi = 0; mi < 4; mi++)
#pragma unroll
        for (int j = 0; j < 8; j++) {
            const int col = col0 + wn + j * 8 + (lane & 3) * 2;
#pragma unroll
            for (int q = 0; q < 2; q++) {
                const int row = row0 + wm + mi * 16 + (lane >> 2) + q * 8;
                bf16 h0,l0,h1,l1;
                split2(c[mi][j][q*2],h0,l0); split2(c[mi][j][q*2+1],h1,l1);
                const size_t p = ((size_t)b * 256 + row) * 2048 + hh * 256 + col;
                *(uint32_t*)(g_uh + p) = packbf2(h0,h1);
                *(uint32_t*)(g_ul + p) = packbf2(l0,l1);
            }
        }
}

// out[b] = 1/8 * Ucat[b] @ WVT_cat^T.  grid (2, 2, 32), K=2048.
__global__ __launch_bounds__(128, 2) void out_mma_kernel(float* __restrict__ out) {
    extern __shared__ char sd[];
    const uint32_t sdu = s2u(sd);
    float c[4][8][4] = {};
    const int b = blockIdx.z;
    const int row0 = blockIdx.y * 128, col0 = blockIdx.x * 128;
    mma_nt_mainloop(g_uh + (size_t)b * 524288, g_ul + (size_t)b * 524288, 2048,
                    g_wvh, g_wvl, 2048, row0, col0, 2048, sdu, c);
    const int lane = threadIdx.x & 31, wid = threadIdx.x >> 5;
    const int wm = (wid & 1) << 6, wn = (wid >> 1) << 6;
    float* D = out + (size_t)b * 65536;
#pragma unroll
    for (int mi = 0; mi < 4; mi++)
#pragma unroll
        for (int j = 0; j < 8; j++) {
            const int col = col0 + wn + j * 8 + (lane & 3) * 2;
#pragma unroll
            for (int q = 0; q < 2; q++) {
                const int row = row0 + wm + mi * 16 + (lane >> 2) + q * 8;
                float2 v;
                v.x = 0.125f * c[mi][j][q*2];
                v.y = 0.125f * c[mi][j][q*2+1];
                *(float2*)(D + (size_t)row * 256 + col) = v;
            }
        }
}

// ===========================================================================
extern "C" void kernel_launch(void* const* d_in, const int* in_sizes, int n_in,
                              void* d_out, int out_size)
{
    const float* x     = (const float*)d_in[0];
    const float* m     = (const float*)d_in[1];
    const float* W_enc = (const float*)d_in[2];
    const float* b_enc = (const float*)d_in[3];
    const float* WQ    = (const float*)d_in[4];
    const float* WK    = (const float*)d_in[5];
    const float* WV    = (const float*)d_in[6];
    float* out = (float*)d_out;

    cudaFuncSetAttribute(enc_mma_kernel, cudaFuncAttributeMaxDynamicSharedMemorySize, kDynSmem);
    cudaFuncSetAttribute(g_mma_kernel,   cudaFuncAttributeMaxDynamicSharedMemorySize, kDynSmem);
    cudaFuncSetAttribute(s_mma_kernel,   cudaFuncAttributeMaxDynamicSharedMemorySize, kDynSmem);
    cudaFuncSetAttribute(u_mma_kernel,   cudaFuncAttributeMaxDynamicSharedMemorySize, kDynSmemU);
    cudaFuncSetAttribute(out_mma_kernel, cudaFuncAttributeMaxDynamicSharedMemorySize, kDynSmem);

    prep_kernel<<<17088, 256>>>(x, W_enc, WV, WQ, WK, m);             // launch 1
    enc_mma_kernel<<<dim3(2, 256, 1), 128, kDynSmem>>>(b_enc);        // launch 2
    g_mma_kernel<<<dim3(2, 2, 256), 128, kDynSmem>>>();               // launch 3
    s_mma_kernel<<<dim3(8, 2, 256), 128, kDynSmem>>>();               // launch 4 (profiled)
    post_kernel<<<67584, 256>>>();                                    // launch 5 (softmax+transpose)
    u_mma_kernel<<<dim3(2, 2, 256), 128, kDynSmemU>>>();              // launch 6
    out_mma_kernel<<<dim3(2, 2, 32), 128, kDynSmem>>>(out);           // launch 7
}

// round 12
// speedup vs baseline: 1.4522x; 1.1272x over previous
#include <cuda_runtime.h>
#include <cuda_bf16.h>
#include <cuda_fp16.h>
#include <cstdint>

using bf16 = __nv_bfloat16;
using fp16 = __half;

// ===========================================================================
// MHA_73607149519311 — round 12: r11 + two changes:
//   * U GEMM reduced to 1 fp16 pass: prob (single fp16) @ h^T (single fp16).
//     Error budget: ~4e-4 rms worst case, measured errors run ~2x below model.
//   * mask pre-conversion removed (it ADDED 134MB of traffic); softmax reads
//     the fp32 mask directly.
// S/G/enc/out keep 3xbf16 split (softmax-sensitive path).
// ===========================================================================

namespace {
constexpr float kScale = 1.0f / 16.0f;   // 1/sqrt(256)
constexpr float kEps   = 1e-12f;
constexpr int kDynSmem  = 98304;         // bf16 mainloop: 3 stages x 32KB
constexpr int kDynSmemU = 49152;         // u mainloop:    3 stages x 16KB
}

// ---- scratch (static device globals; no dynamic allocation) ----
#define DEVBUF(name, count) __device__ __align__(128) bf16 name[count]
#define DEVBUFH(name, count) __device__ __align__(128) fp16 name[count]
DEVBUF(g_xh, 8388608);  DEVBUF(g_xl, 8388608);    // leaky(x) split   [32768,256]
DEVBUF(g_weh, 65536);   DEVBUF(g_wel, 65536);     // W_enc split      [256,256]
DEVBUF(g_mth, 524288);  DEVBUF(g_mtl, 524288);    // MT=WK@WQ^T split [8,256,256]
DEVBUF(g_hh, 8388608);  DEVBUF(g_hl, 8388608);    // h split          [32,1024,256]
DEVBUF(g_gh, 16777216); DEVBUF(g_gl, 16777216);   // G split          [256,256,256]
DEVBUF(g_uh, 16777216); DEVBUF(g_ul, 16777216);   // U concat split   [32,256,2048]
DEVBUF(g_wvh, 524288);  DEVBUF(g_wvl, 524288);    // WVT_cat split    [256,2048]
DEVBUFH(g_pf, 67108864);                           // prob fp16        [256,256,1024]
DEVBUFH(g_h16, 8388608);                           // h^T fp16         [32,256,1024]
__device__ __align__(128) float g_S[67108864];     // S fp32           [256,256,1024]

// ============================= helpers =====================================
__device__ __forceinline__ uint32_t s2u(const void* p) {
    uint32_t a;
    asm("{ .reg .u64 t; cvta.to.shared.u64 t, %1; cvt.u32.u64 %0, t; }"
        : "=r"(a) : "l"(p));
    return a;
}

__device__ __forceinline__ void cp16(uint32_t saddr, const void* gaddr) {
    asm volatile("cp.async.cg.shared.global [%0], [%1], 16;"
                 :: "r"(saddr), "l"(gaddr) : "memory");
}
#define CP_COMMIT() asm volatile("cp.async.commit_group;" ::: "memory")
#define CP_WAIT1()  asm volatile("cp.async.wait_group 1;" ::: "memory")
#define CP_WAIT0()  asm volatile("cp.async.wait_group 0;" ::: "memory")

__device__ __forceinline__ void ldmx4(uint32_t* r, uint32_t addr) {
    asm volatile("ldmatrix.sync.aligned.m8n8.x4.shared.b16 {%0,%1,%2,%3}, [%4];"
                 : "=r"(r[0]), "=r"(r[1]), "=r"(r[2]), "=r"(r[3]) : "r"(addr));
}

__device__ __forceinline__ void mma16816(float* c, const uint32_t* a,
                                         uint32_t b0, uint32_t b1) {
    asm volatile(
        "mma.sync.aligned.m16n8k16.row.col.f32.bf16.bf16.f32 "
        "{%0,%1,%2,%3}, {%4,%5,%6,%7}, {%8,%9}, {%0,%1,%2,%3};"
        : "+f"(c[0]), "+f"(c[1]), "+f"(c[2]), "+f"(c[3])
        : "r"(a[0]), "r"(a[1]), "r"(a[2]), "r"(a[3]), "r"(b0), "r"(b1));
}

__device__ __forceinline__ void mma16816h(float* c, const uint32_t* a,
                                          uint32_t b0, uint32_t b1) {
    asm volatile(
        "mma.sync.aligned.m16n8k16.row.col.f32.f16.f16.f32 "
        "{%0,%1,%2,%3}, {%4,%5,%6,%7}, {%8,%9}, {%0,%1,%2,%3};"
        : "+f"(c[0]), "+f"(c[1]), "+f"(c[2]), "+f"(c[3])
        : "r"(a[0]), "r"(a[1]), "r"(a[2]), "r"(a[3]), "r"(b0), "r"(b1));
}

__device__ __forceinline__ void split2(float v, bf16& hi, bf16& lo) {
    hi = __float2bfloat16(v);
    lo = __float2bfloat16(v - __bfloat162float(hi));
}
__device__ __forceinline__ uint32_t packbf2(bf16 a, bf16 b) {
    __nv_bfloat162 t; t.x = a; t.y = b;
    return *reinterpret_cast<uint32_t*>(&t);
}
__device__ __forceinline__ uint32_t packh2(fp16 a, fp16 b) {
    __half2 t; t.x = a; t.y = b;
    return *reinterpret_cast<uint32_t*>(&t);
}

// Swizzled offset within a (rows x 64B) tile: row r, seg s (0..3).
__device__ __forceinline__ uint32_t sw64(int r, int s) {
    return (uint32_t)((r << 6) + (((s ^ ((r >> 1) & 3)) & 3) << 4));
}

// ==================== bf16 split-2 mainloop (r9, proven) ===================
// CTA tile 128x128, NT. 128 threads = 4 warps (2M x 2N), warp tile 64x64.
// cp.async 3-stage, K chunks of 32. Stage (32KB): Ahi|Alo|Bhi|Blo 8K each.

__device__ __forceinline__ void issue_chunk(
    const bf16* __restrict__ Ah, const bf16* __restrict__ Al, int lda,
    const bf16* __restrict__ Bh, const bf16* __restrict__ Bl, int ldb,
    int row0, int col0, int kt, uint32_t sb)
{
    const int tid = threadIdx.x;
#pragma unroll
    for (int i = 0; i < 4; i++) {
        const int idx = tid + i * 128;       // 0..511
        const int r = idx >> 2, s = idx & 3;
        const uint32_t off = sw64(r, s);
        const size_t ga = (size_t)(row0 + r) * lda + kt + s * 8;
        const size_t gb = (size_t)(col0 + r) * ldb + kt + s * 8;
        cp16(sb + off,         Ah + ga);
        cp16(sb + 8192 + off,  Al + ga);
        cp16(sb + 16384 + off, Bh + gb);
        cp16(sb + 24576 + off, Bl + gb);
    }
    CP_COMMIT();
}

__device__ __forceinline__ void mma_nt_mainloop(
    const bf16* __restrict__ Ah, const bf16* __restrict__ Al, int lda,
    const bf16* __restrict__ Bh, const bf16* __restrict__ Bl, int ldb,
    int row0, int col0, int K, uint32_t sdu, float (&c)[4][8][4])
{
    const int tid = threadIdx.x;
    const int lane = tid & 31, wid = tid >> 5;
    const int wm = (wid & 1) << 6;
    const int wn = (wid >> 1) << 6;

    const int arow0 = wm + (lane & 15);
    const int akseg = lane >> 4;
    const int brow0 = wn + ((lane >> 4) << 3) + (lane & 7);
    const int bkseg = (lane >> 3) & 1;

    const int NC = K >> 5;
    issue_chunk(Ah, Al, lda, Bh, Bl, ldb, row0, col0, 0, sdu);
    issue_chunk(Ah, Al, lda, Bh, Bl, ldb, row0, col0, 32, sdu + 32768);

    int buf = 0;
    for (int ci = 0; ci < NC; ci++) {
        if (ci + 1 < NC) { CP_WAIT1(); } else { CP_WAIT0(); }
        __syncthreads();
        if (ci + 2 < NC) {
            int nb = buf + 2; if (nb >= 3) nb -= 3;
            issue_chunk(Ah, Al, lda, Bh, Bl, ldb, row0, col0,
                        (ci + 2) << 5, sdu + nb * 32768);
        }

        const uint32_t sb = sdu + buf * 32768;
#pragma unroll
        for (int k = 0; k < 2; k++) {
            uint32_t afh[4][4], afl[4][4], bfh[4][4], bfl[4][4];
#pragma unroll
            for (int mi = 0; mi < 4; mi++) {
                const int r = arow0 + mi * 16;
                const uint32_t off = sw64(r, 2 * k + akseg);
                ldmx4(afh[mi], sb + off);
                ldmx4(afl[mi], sb + 8192 + off);
            }
#pragma unroll
            for (int nj = 0; nj < 4; nj++) {
                const int r = brow0 + nj * 16;
                const uint32_t off = sw64(r, 2 * k + bkseg);
                ldmx4(bfh[nj], sb + 16384 + off);
                ldmx4(bfl[nj], sb + 24576 + off);
            }
#pragma unroll
            for (int mi = 0; mi < 4; mi++)
#pragma unroll
                for (int ni = 0; ni < 8; ni++) {
                    const int nj = ni >> 1, o = (ni & 1) << 1;
                    mma16816(c[mi][ni], afh[mi], bfh[nj][o], bfh[nj][o + 1]);
                }
#pragma unroll
            for (int mi = 0; mi < 4; mi++)
#pragma unroll
                for (int ni = 0; ni < 8; ni++) {
                    const int nj = ni >> 1, o = (ni & 1) << 1;
                    mma16816(c[mi][ni], afh[mi], bfl[nj][o], bfl[nj][o + 1]);
                }
#pragma unroll
            for (int mi = 0; mi < 4; mi++)
#pragma unroll
                for (int ni = 0; ni < 8; ni++) {
                    const int nj = ni >> 1, o = (ni & 1) << 1;
                    mma16816(c[mi][ni], afl[mi], bfh[nj][o], bfh[nj][o + 1]);
                }
        }
        if (++buf == 3) buf = 0;
    }
}

// ==================== fp16 1-pass mainloop (u only) ========================
// A = prob fp16 (single), B = h^T fp16 (single). Stage (16KB): A|B 8K each.

__device__ __forceinline__ void issue_chunk_u(
    const fp16* __restrict__ A, int lda,
    const fp16* __restrict__ B, int ldb,
    int row0, int col0, int kt, uint32_t sb)
{
    const int tid = threadIdx.x;
#pragma unroll
    for (int i = 0; i < 4; i++) {
        const int idx = tid + i * 128;       // 0..511
        const int r = idx >> 2, s = idx & 3;
        const uint32_t off = sw64(r, s);
        const size_t ga = (size_t)(row0 + r) * lda + kt + s * 8;
        const size_t gb = (size_t)(col0 + r) * ldb + kt + s * 8;
        cp16(sb + off,        A + ga);
        cp16(sb + 8192 + off, B + gb);
    }
    CP_COMMIT();
}

__device__ __forceinline__ void mma_nt_mainloop_u(
    const fp16* __restrict__ A, int lda,
    const fp16* __restrict__ B, int ldb,
    int row0, int col0, int K, uint32_t sdu, float (&c)[4][8][4])
{
    const int tid = threadIdx.x;
    const int lane = tid & 31, wid = tid >> 5;
    const int wm = (wid & 1) << 6;
    const int wn = (wid >> 1) << 6;

    const int arow0 = wm + (lane & 15);
    const int akseg = lane >> 4;
    const int brow0 = wn + ((lane >> 4) << 3) + (lane & 7);
    const int bkseg = (lane >> 3) & 1;

    const int NC = K >> 5;
    issue_chunk_u(A, lda, B, ldb, row0, col0, 0, sdu);
    issue_chunk_u(A, lda, B, ldb, row0, col0, 32, sdu + 16384);

    int buf = 0;
    for (int ci = 0; ci < NC; ci++) {
        if (ci + 1 < NC) { CP_WAIT1(); } else { CP_WAIT0(); }
        __syncthreads();
        if (ci + 2 < NC) {
            int nb = buf + 2; if (nb >= 3) nb -= 3;
            issue_chunk_u(A, lda, B, ldb, row0, col0,
                          (ci + 2) << 5, sdu + nb * 16384);
        }

        const uint32_t sb = sdu + buf * 16384;
#pragma unroll
        for (int k = 0; k < 2; k++) {
            uint32_t af[4][4], bf[4][4];
#pragma unroll
            for (int mi = 0; mi < 4; mi++) {
                const int r = arow0 + mi * 16;
                const uint32_t off = sw64(r, 2 * k + akseg);
                ldmx4(af[mi], sb + off);
            }
#pragma unroll
            for (int nj = 0; nj < 4; nj++) {
                const int r = brow0 + nj * 16;
                const uint32_t off = sw64(r, 2 * k + bkseg);
                ldmx4(bf[nj], sb + 8192 + off);
            }
#pragma unroll
            for (int mi = 0; mi < 4; mi++)
#pragma unroll
                for (int ni = 0; ni < 8; ni++) {
                    const int nj = ni >> 1, o = (ni & 1) << 1;
                    mma16816h(c[mi][ni], af[mi], bf[nj][o], bf[nj][o + 1]);
                }
        }
        if (++buf == 3) buf = 0;
    }
}

// Epilogue mapping (both loops) for c[mi][j][q]:
//   row = row0 + wm + mi*16 + (lane>>2) + (q>=2 ? 8 : 0)
//   col = col0 + wn + j*8 + (lane&3)*2 + (q&1)
//   wm = (wid&1)<<6, wn = (wid>>1)<<6

// ===================== merged prep kernel (launch #1) ======================
// blockIdx.x: [0,8192) conv_x | [8192,8256) conv_wenc | [8256,8768) conv_wvt
//             | [8768,8896) mt
__global__ __launch_bounds__(256) void prep_kernel(
    const float* __restrict__ x, const float* __restrict__ W_enc,
    const float* __restrict__ WV,
    const float* __restrict__ WQ, const float* __restrict__ WK)
{
    const int bid = blockIdx.x;
    if (bid < 8192) {
        size_t idx = (size_t)bid * 256 + threadIdx.x;   // over float4s
        float4 v = ((const float4*)x)[idx];
        v.x = v.x > 0.f ? v.x : 0.01f * v.x;
        v.y = v.y > 0.f ? v.y : 0.01f * v.y;
        v.z = v.z > 0.f ? v.z : 0.01f * v.z;
        v.w = v.w > 0.f ? v.w : 0.01f * v.w;
        bf16 h0,l0,h1,l1,h2,l2,h3,l3;
        split2(v.x,h0,l0); split2(v.y,h1,l1); split2(v.z,h2,l2); split2(v.w,h3,l3);
        *(uint2*)(g_xh + idx * 4) = make_uint2(packbf2(h0,h1), packbf2(h2,h3));
        *(uint2*)(g_xl + idx * 4) = make_uint2(packbf2(l0,l1), packbf2(l2,l3));
        return;
    }
    if (bid < 8256) {
        size_t idx = (size_t)(bid - 8192) * 256 + threadIdx.x;  // 16384 float4s
        float4 v = ((const float4*)W_enc)[idx];
        bf16 h0,l0,h1,l1,h2,l2,h3,l3;
        split2(v.x,h0,l0); split2(v.y,h1,l1); split2(v.z,h2,l2); split2(v.w,h3,l3);
        *(uint2*)(g_weh + idx * 4) = make_uint2(packbf2(h0,h1), packbf2(h2,h3));
        *(uint2*)(g_wel + idx * 4) = make_uint2(packbf2(l0,l1), packbf2(l2,l3));
        return;
    }
    if (bid < 8768) {
        __shared__ float t[32][33];
        const int tb = bid - 8256;
        const int k0 = (tb & 63) * 32, e0 = (tb >> 6) * 32;
        const int tx = threadIdx.x & 31, ty = threadIdx.x >> 5;
#pragma unroll
        for (int i = 0; i < 4; i++) {
            const int k = ty + i * 8;
            t[k][tx] = WV[(size_t)(k0 + k) * 256 + e0 + tx];
        }
        __syncthreads();
#pragma unroll
        for (int i = 0; i < 4; i++) {
            const int e = ty + i * 8;
            const float v = t[tx][e];
            bf16 hi, lo; split2(v, hi, lo);
            const size_t o = (size_t)(e0 + e) * 2048 + k0 + tx;
            g_wvh[o] = hi; g_wvl[o] = lo;
        }
        return;
    }
    {
        __shared__ float As[8][68], Bs[8][68];
        float acc[4][4] = {};
        const int tb = bid - 8768;
        const int hh = tb >> 4;
        const int row0 = ((tb >> 2) & 3) * 64, col0 = (tb & 3) * 64;
        const float* A = WK + (size_t)hh * 65536;
        const float* B = WQ + (size_t)hh * 65536;
        const int tid = threadIdx.x;
        const int lr = tid >> 2, lk = (tid & 3) << 1;
        const int tx = tid & 15, ty = tid >> 4;
        const float* aP = A + (size_t)(row0 + lr) * 256 + lk;
        const float* bP = B + (size_t)(col0 + lr) * 256 + lk;
        for (int kt = 0; kt < 256; kt += 8) {
            float2 av = *(const float2*)(aP + kt);
            float2 bv = *(const float2*)(bP + kt);
            As[lk][lr] = av.x; As[lk + 1][lr] = av.y;
            Bs[lk][lr] = bv.x; Bs[lk + 1][lr] = bv.y;
            __syncthreads();
#pragma unroll
            for (int k = 0; k < 8; k++) {
                float ar[4], br[4];
                *(float4*)ar = *(const float4*)(&As[k][ty * 4]);
                *(float4*)br = *(const float4*)(&Bs[k][tx * 4]);
#pragma unroll
                for (int i = 0; i < 4; i++)
#pragma unroll
                    for (int j = 0; j < 4; j++)
                        acc[i][j] = fmaf(ar[i], br[j], acc[i][j]);
            }
            __syncthreads();
        }
        bf16* Dh = g_mth + (size_t)hh * 65536;
        bf16* Dl = g_mtl + (size_t)hh * 65536;
#pragma unroll
        for (int i = 0; i < 4; i++) {
            size_t base = (size_t)(row0 + ty * 4 + i) * 256 + col0 + tx * 4;
#pragma unroll
            for (int j = 0; j < 4; j += 2) {
                bf16 h0,l0,h1,l1;
                split2(acc[i][j],h0,l0); split2(acc[i][j+1],h1,l1);
                *(uint32_t*)(Dh + base + j) = packbf2(h0,h1);
                *(uint32_t*)(Dl + base + j) = packbf2(l0,l1);
            }
        }
    }
}

// ============================== MMA kernels ================================

// h = x_sp @ Wenc^T + b. grid (2, 256).
__global__ __launch_bounds__(128, 2) void enc_mma_kernel(const float* __restrict__ bias) {
    extern __shared__ char sd[];
    const uint32_t sdu = s2u(sd);
    float c[4][8][4] = {};
    const int row0 = blockIdx.y * 128, col0 = blockIdx.x * 128;
    mma_nt_mainloop(g_xh, g_xl, 256, g_weh, g_wel, 256, row0, col0, 256, sdu, c);
    const int lane = threadIdx.x & 31, wid = threadIdx.x >> 5;
    const int wm = (wid & 1) << 6, wn = (wid >> 1) << 6;
#pragma unroll
    for (int mi = 0; mi < 4; mi++)
#pragma unroll
        for (int j = 0; j < 8; j++) {
            const int col = col0 + wn + j * 8 + (lane & 3) * 2;
            const float b0 = bias[col], b1 = bias[col + 1];
#pragma unroll
            for (int q = 0; q < 2; q++) {
                const int row = row0 + wm + mi * 16 + (lane >> 2) + q * 8;
                const float v0 = c[mi][j][q * 2]     + b0;
                const float v1 = c[mi][j][q * 2 + 1] + b1;
                bf16 h0,l0,h1,l1; split2(v0,h0,l0); split2(v1,h1,l1);
                const size_t p = (size_t)row * 256 + col;
                *(uint32_t*)(g_hh + p) = packbf2(h0,h1);
                *(uint32_t*)(g_hl + p) = packbf2(l0,l1);
            }
        }
}

// G[bh] = ha_sp[b] @ MT[h]^T. grid (2, 2, 256).
__global__ __launch_bounds__(128, 2) void g_mma_kernel() {
    extern __shared__ char sd[];
    const uint32_t sdu = s2u(sd);
    float c[4][8][4] = {};
    const int z = blockIdx.z, b = z >> 3, hh = z & 7;
    const int row0 = blockIdx.y * 128, col0 = blockIdx.x * 128;
    mma_nt_mainloop(g_hh + (size_t)b * 262144, g_hl + (size_t)b * 262144, 256,
                    g_mth + (size_t)hh * 65536, g_mtl + (size_t)hh * 65536, 256,
                    row0, col0, 256, sdu, c);
    const int lane = threadIdx.x & 31, wid = threadIdx.x >> 5;
    const int wm = (wid & 1) << 6, wn = (wid >> 1) << 6;
    bf16* Dh = g_gh + (size_t)z * 65536;
    bf16* Dl = g_gl + (size_t)z * 65536;
#pragma unroll
    for (int mi = 0; mi < 4; mi++)
#pragma unroll
        for (int j = 0; j < 8; j++) {
            const int col = col0 + wn + j * 8 + (lane & 3) * 2;
#pragma unroll
            for (int q = 0; q < 2; q++) {
                const int row = row0 + wm + mi * 16 + (lane >> 2) + q * 8;
                bf16 h0,l0,h1,l1;
                split2(c[mi][j][q*2],h0,l0); split2(c[mi][j][q*2+1],h1,l1);
                const size_t p = (size_t)row * 256 + col;
                *(uint32_t*)(Dh + p) = packbf2(h0,h1);
                *(uint32_t*)(Dl + p) = packbf2(l0,l1);
            }
        }
}

// S[bh] = G[bh] @ h[b]^T * SCALE -> fp32. grid (8, 2, 256).  [profiled slot]
__global__ __launch_bounds__(128, 2) void s_mma_kernel() {
    extern __shared__ char sd[];
    const uint32_t sdu = s2u(sd);
    float c[4][8][4] = {};
    const int z = blockIdx.z, b = z >> 3;
    const int row0 = blockIdx.y * 128, col0 = blockIdx.x * 128;
    mma_nt_mainloop(g_gh + (size_t)z * 65536, g_gl + (size_t)z * 65536, 256,
                    g_hh + (size_t)b * 262144, g_hl + (size_t)b * 262144, 256,
                    row0, col0, 256, sdu, c);
    const int lane = threadIdx.x & 31, wid = threadIdx.x >> 5;
    const int wm = (wid & 1) << 6, wn = (wid >> 1) << 6;
    float* D = g_S + (size_t)z * 262144;
#pragma unroll
    for (int mi = 0; mi < 4; mi++)
#pragma unroll
        for (int j = 0; j < 8; j++) {
            const int col = col0 + wn + j * 8 + (lane & 3) * 2;
#pragma unroll
            for (int q = 0; q < 2; q++) {
                const int row = row0 + wm + mi * 16 + (lane >> 2) + q * 8;
                float2 v;
                v.x = kScale * c[mi][j][q*2];
                v.y = kScale * c[mi][j][q*2+1];
                *(float2*)(D + (size_t)row * 1024 + col) = v;
            }
        }
}

// =============== fused softmax + h-transpose (launch #5) ===================
// bid < 65536: softmax row (b*8+h)*256 + a; reads fp32 mask; writes prob fp16.
// bid >= 65536: transpose h (bf16 split -> single fp16, [n,d]->[d,n]).
__global__ __launch_bounds__(256) void post_kernel(const float* __restrict__ mglob) {
    const int bid = blockIdx.x;
    const int tid = threadIdx.x;
    if (bid < 65536) {
        const int idx = bid;
        const int a = idx & 255, b = idx >> 11;
        const float* row = g_S + (size_t)idx * 1024;
        const float* mrow = mglob + ((size_t)b * 256 + a) * 1024;

        float4 v = ((const float4*)row)[tid];
        float4 mv = ((const float4*)mrow)[tid];

        float lmax = fmaxf(fmaxf(v.x, v.y), fmaxf(v.z, v.w));
#pragma unroll
        for (int o = 16; o > 0; o >>= 1)
            lmax = fmaxf(lmax, __shfl_xor_sync(0xffffffffu, lmax, o));

        __shared__ float redmax[8], redz[8], redm[8], bc[2];
        const int warp = tid >> 5, lane = tid & 31;
        if (lane == 0) redmax[warp] = lmax;
        __syncthreads();
        if (tid == 0) {
            float mx = redmax[0];
            for (int w = 1; w < 8; w++) mx = fmaxf(mx, redmax[w]);
            bc[0] = mx;
        }
        __syncthreads();
        const float mx = bc[0];

        float e0 = __expf(v.x - mx), e1 = __expf(v.y - mx);
        float e2 = __expf(v.z - mx), e3 = __expf(v.w - mx);
        float zs = e0 + e1 + e2 + e3;
        float ms = e0 * mv.x + e1 * mv.y + e2 * mv.z + e3 * mv.w;
#pragma unroll
        for (int o = 16; o > 0; o >>= 1) {
            zs += __shfl_xor_sync(0xffffffffu, zs, o);
            ms += __shfl_xor_sync(0xffffffffu, ms, o);
        }
        if (lane == 0) { redz[warp] = zs; redm[warp] = ms; }
        __syncthreads();
        if (tid == 0) {
            float tz = 0.f, tm = 0.f;
            for (int w = 0; w < 8; w++) { tz += redz[w]; tm += redm[w]; }
            bc[1] = 1.0f / (tm + kEps * tz);
        }
        __syncthreads();
        const float inv = bc[1];

        const fp16 p0 = __float2half(e0 * mv.x * inv);
        const fp16 p1 = __float2half(e1 * mv.y * inv);
        const fp16 p2 = __float2half(e2 * mv.z * inv);
        const fp16 p3 = __float2half(e3 * mv.w * inv);
        *(uint2*)(g_pf + (size_t)idx * 1024 + 4 * tid) =
            make_uint2(packh2(p0, p1), packh2(p2, p3));
        return;
    }
    // ---- transpose: h (bf16 hi+lo, [b][n][d]) -> fp16 single [b][d][n] ----
    __shared__ fp16 th[64 * 65];
    const int tb = bid - 65536;              // 0..2047
    const int b = tb >> 6;
    const int rem = tb & 63;
    const int n0 = (rem >> 2) * 64, d0 = (rem & 3) * 64;
    const bf16* inh = g_hh + (size_t)b * 262144;
    const bf16* inl = g_hl + (size_t)b * 262144;
#pragma unroll
    for (int i = 0; i < 8; i++) {
        int idx = tid + i * 256;
        int r = idx >> 5, c2 = idx & 31;
        uint32_t vh = *(const uint32_t*)(inh + (size_t)(n0 + r) * 256 + d0 + c2 * 2);
        uint32_t vl = *(const uint32_t*)(inl + (size_t)(n0 + r) * 256 + d0 + c2 * 2);
        __nv_bfloat162 bh = *reinterpret_cast<__nv_bfloat162*>(&vh);
        __nv_bfloat162 bl = *reinterpret_cast<__nv_bfloat162*>(&vl);
        float f0 = __bfloat162float(bh.x) + __bfloat162float(bl.x);
        float f1 = __bfloat162float(bh.y) + __bfloat162float(bl.y);
        th[r * 65 + c2 * 2]     = __float2half(f0);
        th[r * 65 + c2 * 2 + 1] = __float2half(f1);
    }
    __syncthreads();
    fp16* oh = g_h16 + (size_t)b * 262144;
#pragma unroll
    for (int i = 0; i < 8; i++) {
        int idx = tid + i * 256;
        int r = idx >> 5, c2 = idx & 31;   // r = d_local, c2 = n pair
        uint32_t wh = packh2(th[(c2 * 2) * 65 + r], th[(c2 * 2 + 1) * 65 + r]);
        *(uint32_t*)(oh + (size_t)(d0 + r) * 1024 + n0 + c2 * 2) = wh;
    }
}

// Ucat[b][a][h*256+d] = prob[bh] @ h[b].  grid (2, 2, 256), K=1024. fp16 1-pass.
__global__ __launch_bounds__(128, 2) void u_mma_kernel() {
    extern __shared__ char sd[];
    const uint32_t sdu = s2u(sd);
    float c[4][8][4] = {};
    const int z = blockIdx.z, b = z >> 3, hh = z & 7;
    const int row0 = blockIdx.y * 128, col0 = blockIdx.x * 128;
    mma_nt_mainloop_u(g_pf + (size_t)z * 262144, 1024,
                      g_h16 + (size_t)b * 262144, 1024,
                      row0, col0, 1024, sdu, c);
    const int lane = threadIdx.x & 31, wid = threadIdx.x >> 5;
    const int wm = (wid & 1) << 6, wn = (wid >> 1) << 6;
#pragma unroll
    for (int mi = 0; mi < 4; mi++)
#pragma unroll
        for (int j = 0; j < 8; j++) {
            const int col = col0 + wn + j * 8 + (lane & 3) * 2;
#pragma unroll
            for (int q = 0; q < 2; q++) {
                const int row = row0 + wm + mi * 16 + (lane >> 2) + q * 8;
                bf16 h0,l0,h1,l1;
                split2(c[mi][j][q*2],h0,l0); split2(c[mi][j][q*2+1],h1,l1);
                const size_t p = ((size_t)b * 256 + row) * 2048 + hh * 256 + col;
                *(uint32_t*)(g_uh + p) = packbf2(h0,h1);
                *(uint32_t*)(g_ul + p) = packbf2(l0,l1);
            }
        }
}

// out[b] = 1/8 * Ucat[b] @ WVT_cat^T.  grid (2, 2, 32), K=2048.
__global__ __launch_bounds__(128, 2) void out_mma_kernel(float* __restrict__ out) {
    extern __shared__ char sd[];
    const uint32_t sdu = s2u(sd);
    float c[4][8][4] = {};
    const int b = blockIdx.z;
    const int row0 = blockIdx.y * 128, col0 = blockIdx.x * 128;
    mma_nt_mainloop(g_uh + (size_t)b * 524288, g_ul + (size_t)b * 524288, 2048,
                    g_wvh, g_wvl, 2048, row0, col0, 2048, sdu, c);
    const int lane = threadIdx.x & 31, wid = threadIdx.x >> 5;
    const int wm = (wid & 1) << 6, wn = (wid >> 1) << 6;
    float* D = out + (size_t)b * 65536;
#pragma unroll
    for (int mi = 0; mi < 4; mi++)
#pragma unroll
        for (int j = 0; j < 8; j++) {
            const int col = col0 + wn + j * 8 + (lane & 3) * 2;
#pragma unroll
            for (int q = 0; q < 2; q++) {
                const int row = row0 + wm + mi * 16 + (lane >> 2) + q * 8;
                float2 v;
                v.x = 0.125f * c[mi][j][q*2];
                v.y = 0.125f * c[mi][j][q*2+1];
                *(float2*)(D + (size_t)row * 256 + col) = v;
            }
        }
}

// ===========================================================================
extern "C" void kernel_launch(void* const* d_in, const int* in_sizes, int n_in,
                              void* d_out, int out_size)
{
    const float* x     = (const float*)d_in[0];
    const float* m     = (const float*)d_in[1];
    const float* W_enc = (const float*)d_in[2];
    const float* b_enc = (const float*)d_in[3];
    const float* WQ    = (const float*)d_in[4];
    const float* WK    = (const float*)d_in[5];
    const float* WV    = (const float*)d_in[6];
    float* out = (float*)d_out;

    cudaFuncSetAttribute(enc_mma_kernel, cudaFuncAttributeMaxDynamicSharedMemorySize, kDynSmem);
    cudaFuncSetAttribute(g_mma_kernel,   cudaFuncAttributeMaxDynamicSharedMemorySize, kDynSmem);
    cudaFuncSetAttribute(s_mma_kernel,   cudaFuncAttributeMaxDynamicSharedMemorySize, kDynSmem);
    cudaFuncSetAttribute(u_mma_kernel,   cudaFuncAttributeMaxDynamicSharedMemorySize, kDynSmemU);
    cudaFuncSetAttribute(out_mma_kernel, cudaFuncAttributeMaxDynamicSharedMemorySize, kDynSmem);

    prep_kernel<<<8896, 256>>>(x, W_enc, WV, WQ, WK);                 // launch 1
    enc_mma_kernel<<<dim3(2, 256, 1), 128, kDynSmem>>>(b_enc);        // launch 2
    g_mma_kernel<<<dim3(2, 2, 256), 128, kDynSmem>>>();               // launch 3
    s_mma_kernel<<<dim3(8, 2, 256), 128, kDynSmem>>>();               // launch 4 (profiled)
    post_kernel<<<67584, 256>>>(m);                                   // launch 5
    u_mma_kernel<<<dim3(2, 2, 256), 128, kDynSmemU>>>();              // launch 6
    out_mma_kernel<<<dim3(2, 2, 32), 128, kDynSmem>>>(out);           // launch 7
}

// round 13
// speedup vs baseline: 1.5700x; 1.0811x over previous
#include <cuda_runtime.h>
#include <cuda_bf16.h>
#include <cuda_fp16.h>
#include <cstdint>

using bf16 = __nv_bfloat16;
using fp16 = __half;

// ===========================================================================
// MHA_73607149519311 — round 13: r12 + out-GEMM on the fp16 1-pass path.
//   * U stored single fp16 (u epilogue writes fp16 directly; traffic halved)
//   * WVT_cat stored single fp16
//   * out = 1/8 * U_f16 @ WVT_f16^T (1-pass, K=2048)
// S path (enc/g/s) stays 3xbf16 split; u stays fp16 1-pass.
// ===========================================================================

namespace {
constexpr float kScale = 1.0f / 16.0f;   // 1/sqrt(256)
constexpr float kEps   = 1e-12f;
constexpr int kDynSmem  = 98304;         // bf16 mainloop: 3 stages x 32KB
constexpr int kDynSmemU = 49152;         // fp16 mainloop: 3 stages x 16KB
}

// ---- scratch (static device globals; no dynamic allocation) ----
#define DEVBUF(name, count) __device__ __align__(128) bf16 name[count]
#define DEVBUFH(name, count) __device__ __align__(128) fp16 name[count]
DEVBUF(g_xh, 8388608);  DEVBUF(g_xl, 8388608);    // leaky(x) split   [32768,256]
DEVBUF(g_weh, 65536);   DEVBUF(g_wel, 65536);     // W_enc split      [256,256]
DEVBUF(g_mth, 524288);  DEVBUF(g_mtl, 524288);    // MT=WK@WQ^T split [8,256,256]
DEVBUF(g_hh, 8388608);  DEVBUF(g_hl, 8388608);    // h split          [32,1024,256]
DEVBUF(g_gh, 16777216); DEVBUF(g_gl, 16777216);   // G split          [256,256,256]
DEVBUFH(g_u16, 16777216);                          // U concat fp16    [32,256,2048]
DEVBUFH(g_wv16, 524288);                           // WVT_cat fp16     [256,2048]
DEVBUFH(g_pf, 67108864);                           // prob fp16        [256,256,1024]
DEVBUFH(g_h16, 8388608);                           // h^T fp16         [32,256,1024]
__device__ __align__(128) float g_S[67108864];     // S fp32           [256,256,1024]

// ============================= helpers =====================================
__device__ __forceinline__ uint32_t s2u(const void* p) {
    uint32_t a;
    asm("{ .reg .u64 t; cvta.to.shared.u64 t, %1; cvt.u32.u64 %0, t; }"
        : "=r"(a) : "l"(p));
    return a;
}

__device__ __forceinline__ void cp16(uint32_t saddr, const void* gaddr) {
    asm volatile("cp.async.cg.shared.global [%0], [%1], 16;"
                 :: "r"(saddr), "l"(gaddr) : "memory");
}
#define CP_COMMIT() asm volatile("cp.async.commit_group;" ::: "memory")
#define CP_WAIT1()  asm volatile("cp.async.wait_group 1;" ::: "memory")
#define CP_WAIT0()  asm volatile("cp.async.wait_group 0;" ::: "memory")

__device__ __forceinline__ void ldmx4(uint32_t* r, uint32_t addr) {
    asm volatile("ldmatrix.sync.aligned.m8n8.x4.shared.b16 {%0,%1,%2,%3}, [%4];"
                 : "=r"(r[0]), "=r"(r[1]), "=r"(r[2]), "=r"(r[3]) : "r"(addr));
}

__device__ __forceinline__ void mma16816(float* c, const uint32_t* a,
                                         uint32_t b0, uint32_t b1) {
    asm volatile(
        "mma.sync.aligned.m16n8k16.row.col.f32.bf16.bf16.f32 "
        "{%0,%1,%2,%3}, {%4,%5,%6,%7}, {%8,%9}, {%0,%1,%2,%3};"
        : "+f"(c[0]), "+f"(c[1]), "+f"(c[2]), "+f"(c[3])
        : "r"(a[0]), "r"(a[1]), "r"(a[2]), "r"(a[3]), "r"(b0), "r"(b1));
}

__device__ __forceinline__ void mma16816h(float* c, const uint32_t* a,
                                          uint32_t b0, uint32_t b1) {
    asm volatile(
        "mma.sync.aligned.m16n8k16.row.col.f32.f16.f16.f32 "
        "{%0,%1,%2,%3}, {%4,%5,%6,%7}, {%8,%9}, {%0,%1,%2,%3};"
        : "+f"(c[0]), "+f"(c[1]), "+f"(c[2]), "+f"(c[3])
        : "r"(a[0]), "r"(a[1]), "r"(a[2]), "r"(a[3]), "r"(b0), "r"(b1));
}

__device__ __forceinline__ void split2(float v, bf16& hi, bf16& lo) {
    hi = __float2bfloat16(v);
    lo = __float2bfloat16(v - __bfloat162float(hi));
}
__device__ __forceinline__ uint32_t packbf2(bf16 a, bf16 b) {
    __nv_bfloat162 t; t.x = a; t.y = b;
    return *reinterpret_cast<uint32_t*>(&t);
}
__device__ __forceinline__ uint32_t packh2(fp16 a, fp16 b) {
    __half2 t; t.x = a; t.y = b;
    return *reinterpret_cast<uint32_t*>(&t);
}

// Swizzled offset within a (rows x 64B) tile: row r, seg s (0..3).
__device__ __forceinline__ uint32_t sw64(int r, int s) {
    return (uint32_t)((r << 6) + (((s ^ ((r >> 1) & 3)) & 3) << 4));
}

// ==================== bf16 split-2 mainloop (r9, proven) ===================
// CTA tile 128x128, NT. 128 threads = 4 warps (2M x 2N), warp tile 64x64.
// cp.async 3-stage, K chunks of 32. Stage (32KB): Ahi|Alo|Bhi|Blo 8K each.

__device__ __forceinline__ void issue_chunk(
    const bf16* __restrict__ Ah, const bf16* __restrict__ Al, int lda,
    const bf16* __restrict__ Bh, const bf16* __restrict__ Bl, int ldb,
    int row0, int col0, int kt, uint32_t sb)
{
    const int tid = threadIdx.x;
#pragma unroll
    for (int i = 0; i < 4; i++) {
        const int idx = tid + i * 128;       // 0..511
        const int r = idx >> 2, s = idx & 3;
        const uint32_t off = sw64(r, s);
        const size_t ga = (size_t)(row0 + r) * lda + kt + s * 8;
        const size_t gb = (size_t)(col0 + r) * ldb + kt + s * 8;
        cp16(sb + off,         Ah + ga);
        cp16(sb + 8192 + off,  Al + ga);
        cp16(sb + 16384 + off, Bh + gb);
        cp16(sb + 24576 + off, Bl + gb);
    }
    CP_COMMIT();
}

__device__ __forceinline__ void mma_nt_mainloop(
    const bf16* __restrict__ Ah, const bf16* __restrict__ Al, int lda,
    const bf16* __restrict__ Bh, const bf16* __restrict__ Bl, int ldb,
    int row0, int col0, int K, uint32_t sdu, float (&c)[4][8][4])
{
    const int tid = threadIdx.x;
    const int lane = tid & 31, wid = tid >> 5;
    const int wm = (wid & 1) << 6;
    const int wn = (wid >> 1) << 6;

    const int arow0 = wm + (lane & 15);
    const int akseg = lane >> 4;
    const int brow0 = wn + ((lane >> 4) << 3) + (lane & 7);
    const int bkseg = (lane >> 3) & 1;

    const int NC = K >> 5;
    issue_chunk(Ah, Al, lda, Bh, Bl, ldb, row0, col0, 0, sdu);
    issue_chunk(Ah, Al, lda, Bh, Bl, ldb, row0, col0, 32, sdu + 32768);

    int buf = 0;
    for (int ci = 0; ci < NC; ci++) {
        if (ci + 1 < NC) { CP_WAIT1(); } else { CP_WAIT0(); }
        __syncthreads();
        if (ci + 2 < NC) {
            int nb = buf + 2; if (nb >= 3) nb -= 3;
            issue_chunk(Ah, Al, lda, Bh, Bl, ldb, row0, col0,
                        (ci + 2) << 5, sdu + nb * 32768);
        }

        const uint32_t sb = sdu + buf * 32768;
#pragma unroll
        for (int k = 0; k < 2; k++) {
            uint32_t afh[4][4], afl[4][4], bfh[4][4], bfl[4][4];
#pragma unroll
            for (int mi = 0; mi < 4; mi++) {
                const int r = arow0 + mi * 16;
                const uint32_t off = sw64(r, 2 * k + akseg);
                ldmx4(afh[mi], sb + off);
                ldmx4(afl[mi], sb + 8192 + off);
            }
#pragma unroll
            for (int nj = 0; nj < 4; nj++) {
                const int r = brow0 + nj * 16;
                const uint32_t off = sw64(r, 2 * k + bkseg);
                ldmx4(bfh[nj], sb + 16384 + off);
                ldmx4(bfl[nj], sb + 24576 + off);
            }
#pragma unroll
            for (int mi = 0; mi < 4; mi++)
#pragma unroll
                for (int ni = 0; ni < 8; ni++) {
                    const int nj = ni >> 1, o = (ni & 1) << 1;
                    mma16816(c[mi][ni], afh[mi], bfh[nj][o], bfh[nj][o + 1]);
                }
#pragma unroll
            for (int mi = 0; mi < 4; mi++)
#pragma unroll
                for (int ni = 0; ni < 8; ni++) {
                    const int nj = ni >> 1, o = (ni & 1) << 1;
                    mma16816(c[mi][ni], afh[mi], bfl[nj][o], bfl[nj][o + 1]);
                }
#pragma unroll
            for (int mi = 0; mi < 4; mi++)
#pragma unroll
                for (int ni = 0; ni < 8; ni++) {
                    const int nj = ni >> 1, o = (ni & 1) << 1;
                    mma16816(c[mi][ni], afl[mi], bfh[nj][o], bfh[nj][o + 1]);
                }
        }
        if (++buf == 3) buf = 0;
    }
}

// ==================== fp16 1-pass mainloop (u, out) ========================
// A, B single fp16. Stage (16KB): A|B 8K each.

__device__ __forceinline__ void issue_chunk_u(
    const fp16* __restrict__ A, int lda,
    const fp16* __restrict__ B, int ldb,
    int row0, int col0, int kt, uint32_t sb)
{
    const int tid = threadIdx.x;
#pragma unroll
    for (int i = 0; i < 4; i++) {
        const int idx = tid + i * 128;       // 0..511
        const int r = idx >> 2, s = idx & 3;
        const uint32_t off = sw64(r, s);
        const size_t ga = (size_t)(row0 + r) * lda + kt + s * 8;
        const size_t gb = (size_t)(col0 + r) * ldb + kt + s * 8;
        cp16(sb + off,        A + ga);
        cp16(sb + 8192 + off, B + gb);
    }
    CP_COMMIT();
}

__device__ __forceinline__ void mma_nt_mainloop_u(
    const fp16* __restrict__ A, int lda,
    const fp16* __restrict__ B, int ldb,
    int row0, int col0, int K, uint32_t sdu, float (&c)[4][8][4])
{
    const int tid = threadIdx.x;
    const int lane = tid & 31, wid = tid >> 5;
    const int wm = (wid & 1) << 6;
    const int wn = (wid >> 1) << 6;

    const int arow0 = wm + (lane & 15);
    const int akseg = lane >> 4;
    const int brow0 = wn + ((lane >> 4) << 3) + (lane & 7);
    const int bkseg = (lane >> 3) & 1;

    const int NC = K >> 5;
    issue_chunk_u(A, lda, B, ldb, row0, col0, 0, sdu);
    issue_chunk_u(A, lda, B, ldb, row0, col0, 32, sdu + 16384);

    int buf = 0;
    for (int ci = 0; ci < NC; ci++) {
        if (ci + 1 < NC) { CP_WAIT1(); } else { CP_WAIT0(); }
        __syncthreads();
        if (ci + 2 < NC) {
            int nb = buf + 2; if (nb >= 3) nb -= 3;
            issue_chunk_u(A, lda, B, ldb, row0, col0,
                          (ci + 2) << 5, sdu + nb * 16384);
        }

        const uint32_t sb = sdu + buf * 16384;
#pragma unroll
        for (int k = 0; k < 2; k++) {
            uint32_t af[4][4], bf[4][4];
#pragma unroll
            for (int mi = 0; mi < 4; mi++) {
                const int r = arow0 + mi * 16;
                const uint32_t off = sw64(r, 2 * k + akseg);
                ldmx4(af[mi], sb + off);
            }
#pragma unroll
            for (int nj = 0; nj < 4; nj++) {
                const int r = brow0 + nj * 16;
                const uint32_t off = sw64(r, 2 * k + bkseg);
                ldmx4(bf[nj], sb + 8192 + off);
            }
#pragma unroll
            for (int mi = 0; mi < 4; mi++)
#pragma unroll
                for (int ni = 0; ni < 8; ni++) {
                    const int nj = ni >> 1, o = (ni & 1) << 1;
                    mma16816h(c[mi][ni], af[mi], bf[nj][o], bf[nj][o + 1]);
                }
        }
        if (++buf == 3) buf = 0;
    }
}

// Epilogue mapping (both loops) for c[mi][j][q]:
//   row = row0 + wm + mi*16 + (lane>>2) + (q>=2 ? 8 : 0)
//   col = col0 + wn + j*8 + (lane&3)*2 + (q&1)
//   wm = (wid&1)<<6, wn = (wid>>1)<<6

// ===================== merged prep kernel (launch #1) ======================
// blockIdx.x: [0,8192) conv_x | [8192,8256) conv_wenc | [8256,8768) conv_wvt
//             | [8768,8896) mt
__global__ __launch_bounds__(256) void prep_kernel(
    const float* __restrict__ x, const float* __restrict__ W_enc,
    const float* __restrict__ WV,
    const float* __restrict__ WQ, const float* __restrict__ WK)
{
    const int bid = blockIdx.x;
    if (bid < 8192) {
        size_t idx = (size_t)bid * 256 + threadIdx.x;   // over float4s
        float4 v = ((const float4*)x)[idx];
        v.x = v.x > 0.f ? v.x : 0.01f * v.x;
        v.y = v.y > 0.f ? v.y : 0.01f * v.y;
        v.z = v.z > 0.f ? v.z : 0.01f * v.z;
        v.w = v.w > 0.f ? v.w : 0.01f * v.w;
        bf16 h0,l0,h1,l1,h2,l2,h3,l3;
        split2(v.x,h0,l0); split2(v.y,h1,l1); split2(v.z,h2,l2); split2(v.w,h3,l3);
        *(uint2*)(g_xh + idx * 4) = make_uint2(packbf2(h0,h1), packbf2(h2,h3));
        *(uint2*)(g_xl + idx * 4) = make_uint2(packbf2(l0,l1), packbf2(l2,l3));
        return;
    }
    if (bid < 8256) {
        size_t idx = (size_t)(bid - 8192) * 256 + threadIdx.x;  // 16384 float4s
        float4 v = ((const float4*)W_enc)[idx];
        bf16 h0,l0,h1,l1,h2,l2,h3,l3;
        split2(v.x,h0,l0); split2(v.y,h1,l1); split2(v.z,h2,l2); split2(v.w,h3,l3);
        *(uint2*)(g_weh + idx * 4) = make_uint2(packbf2(h0,h1), packbf2(h2,h3));
        *(uint2*)(g_wel + idx * 4) = make_uint2(packbf2(l0,l1), packbf2(l2,l3));
        return;
    }
    if (bid < 8768) {
        __shared__ float t[32][33];
        const int tb = bid - 8256;
        const int k0 = (tb & 63) * 32, e0 = (tb >> 6) * 32;
        const int tx = threadIdx.x & 31, ty = threadIdx.x >> 5;
#pragma unroll
        for (int i = 0; i < 4; i++) {
            const int k = ty + i * 8;
            t[k][tx] = WV[(size_t)(k0 + k) * 256 + e0 + tx];
        }
        __syncthreads();
#pragma unroll
        for (int i = 0; i < 4; i++) {
            const int e = ty + i * 8;
            g_wv16[(size_t)(e0 + e) * 2048 + k0 + tx] = __float2half(t[tx][e]);
        }
        return;
    }
    {
        __shared__ float As[8][68], Bs[8][68];
        float acc[4][4] = {};
        const int tb = bid - 8768;
        const int hh = tb >> 4;
        const int row0 = ((tb >> 2) & 3) * 64, col0 = (tb & 3) * 64;
        const float* A = WK + (size_t)hh * 65536;
        const float* B = WQ + (size_t)hh * 65536;
        const int tid = threadIdx.x;
        const int lr = tid >> 2, lk = (tid & 3) << 1;
        const int tx = tid & 15, ty = tid >> 4;
        const float* aP = A + (size_t)(row0 + lr) * 256 + lk;
        const float* bP = B + (size_t)(col0 + lr) * 256 + lk;
        for (int kt = 0; kt < 256; kt += 8) {
            float2 av = *(const float2*)(aP + kt);
            float2 bv = *(const float2*)(bP + kt);
            As[lk][lr] = av.x; As[lk + 1][lr] = av.y;
            Bs[lk][lr] = bv.x; Bs[lk + 1][lr] = bv.y;
            __syncthreads();
#pragma unroll
            for (int k = 0; k < 8; k++) {
                float ar[4], br[4];
                *(float4*)ar = *(const float4*)(&As[k][ty * 4]);
                *(float4*)br = *(const float4*)(&Bs[k][tx * 4]);
#pragma unroll
                for (int i = 0; i < 4; i++)
#pragma unroll
                    for (int j = 0; j < 4; j++)
                        acc[i][j] = fmaf(ar[i], br[j], acc[i][j]);
            }
            __syncthreads();
        }
        bf16* Dh = g_mth + (size_t)hh * 65536;
        bf16* Dl = g_mtl + (size_t)hh * 65536;
#pragma unroll
        for (int i = 0; i < 4; i++) {
            size_t base = (size_t)(row0 + ty * 4 + i) * 256 + col0 + tx * 4;
#pragma unroll
            for (int j = 0; j < 4; j += 2) {
                bf16 h0,l0,h1,l1;
                split2(acc[i][j],h0,l0); split2(acc[i][j+1],h1,l1);
                *(uint32_t*)(Dh + base + j) = packbf2(h0,h1);
                *(uint32_t*)(Dl + base + j) = packbf2(l0,l1);
            }
        }
    }
}

// ============================== MMA kernels ================================

// h = x_sp @ Wenc^T + b. grid (2, 256).
__global__ __launch_bounds__(128, 2) void enc_mma_kernel(const float* __restrict__ bias) {
    extern __shared__ char sd[];
    const uint32_t sdu = s2u(sd);
    float c[4][8][4] = {};
    const int row0 = blockIdx.y * 128, col0 = blockIdx.x * 128;
    mma_nt_mainloop(g_xh, g_xl, 256, g_weh, g_wel, 256, row0, col0, 256, sdu, c);
    const int lane = threadIdx.x & 31, wid = threadIdx.x >> 5;
    const int wm = (wid & 1) << 6, wn = (wid >> 1) << 6;
#pragma unroll
    for (int mi = 0; mi < 4; mi++)
#pragma unroll
        for (int j = 0; j < 8; j++) {
            const int col = col0 + wn + j * 8 + (lane & 3) * 2;
            const float b0 = bias[col], b1 = bias[col + 1];
#pragma unroll
            for (int q = 0; q < 2; q++) {
                const int row = row0 + wm + mi * 16 + (lane >> 2) + q * 8;
                const float v0 = c[mi][j][q * 2]     + b0;
                const float v1 = c[mi][j][q * 2 + 1] + b1;
                bf16 h0,l0,h1,l1; split2(v0,h0,l0); split2(v1,h1,l1);
                const size_t p = (size_t)row * 256 + col;
                *(uint32_t*)(g_hh + p) = packbf2(h0,h1);
                *(uint32_t*)(g_hl + p) = packbf2(l0,l1);
            }
        }
}

// G[bh] = ha_sp[b] @ MT[h]^T. grid (2, 2, 256).
__global__ __launch_bounds__(128, 2) void g_mma_kernel() {
    extern __shared__ char sd[];
    const uint32_t sdu = s2u(sd);
    float c[4][8][4] = {};
    const int z = blockIdx.z, b = z >> 3, hh = z & 7;
    const int row0 = blockIdx.y * 128, col0 = blockIdx.x * 128;
    mma_nt_mainloop(g_hh + (size_t)b * 262144, g_hl + (size_t)b * 262144, 256,
                    g_mth + (size_t)hh * 65536, g_mtl + (size_t)hh * 65536, 256,
                    row0, col0, 256, sdu, c);
    const int lane = threadIdx.x & 31, wid = threadIdx.x >> 5;
    const int wm = (wid & 1) << 6, wn = (wid >> 1) << 6;
    bf16* Dh = g_gh + (size_t)z * 65536;
    bf16* Dl = g_gl + (size_t)z * 65536;
#pragma unroll
    for (int mi = 0; mi < 4; mi++)
#pragma unroll
        for (int j = 0; j < 8; j++) {
            const int col = col0 + wn + j * 8 + (lane & 3) * 2;
#pragma unroll
            for (int q = 0; q < 2; q++) {
                const int row = row0 + wm + mi * 16 + (lane >> 2) + q * 8;
                bf16 h0,l0,h1,l1;
                split2(c[mi][j][q*2],h0,l0); split2(c[mi][j][q*2+1],h1,l1);
                const size_t p = (size_t)row * 256 + col;
                *(uint32_t*)(Dh + p) = packbf2(h0,h1);
                *(uint32_t*)(Dl + p) = packbf2(l0,l1);
            }
        }
}

// S[bh] = G[bh] @ h[b]^T * SCALE -> fp32. grid (8, 2, 256).  [profiled slot]
__global__ __launch_bounds__(128, 2) void s_mma_kernel() {
    extern __shared__ char sd[];
    const uint32_t sdu = s2u(sd);
    float c[4][8][4] = {};
    const int z = blockIdx.z, b = z >> 3;
    const int row0 = blockIdx.y * 128, col0 = blockIdx.x * 128;
    mma_nt_mainloop(g_gh + (size_t)z * 65536, g_gl + (size_t)z * 65536, 256,
                    g_hh + (size_t)b * 262144, g_hl + (size_t)b * 262144, 256,
                    row0, col0, 256, sdu, c);
    const int lane = threadIdx.x & 31, wid = threadIdx.x >> 5;
    const int wm = (wid & 1) << 6, wn = (wid >> 1) << 6;
    float* D = g_S + (size_t)z * 262144;
#pragma unroll
    for (int mi = 0; mi < 4; mi++)
#pragma unroll
        for (int j = 0; j < 8; j++) {
            const int col = col0 + wn + j * 8 + (lane & 3) * 2;
#pragma unroll
            for (int q = 0; q < 2; q++) {
                const int row = row0 + wm + mi * 16 + (lane >> 2) + q * 8;
                float2 v;
                v.x = kScale * c[mi][j][q*2];
                v.y = kScale * c[mi][j][q*2+1];
                *(float2*)(D + (size_t)row * 1024 + col) = v;
            }
        }
}

// =============== fused softmax + h-transpose (launch #5) ===================
__global__ __launch_bounds__(256) void post_kernel(const float* __restrict__ mglob) {
    const int bid = blockIdx.x;
    const int tid = threadIdx.x;
    if (bid < 65536) {
        const int idx = bid;
        const int a = idx & 255, b = idx >> 11;
        const float* row = g_S + (size_t)idx * 1024;
        const float* mrow = mglob + ((size_t)b * 256 + a) * 1024;

        float4 v = ((const float4*)row)[tid];
        float4 mv = ((const float4*)mrow)[tid];

        float lmax = fmaxf(fmaxf(v.x, v.y), fmaxf(v.z, v.w));
#pragma unroll
        for (int o = 16; o > 0; o >>= 1)
            lmax = fmaxf(lmax, __shfl_xor_sync(0xffffffffu, lmax, o));

        __shared__ float redmax[8], redz[8], redm[8], bc[2];
        const int warp = tid >> 5, lane = tid & 31;
        if (lane == 0) redmax[warp] = lmax;
        __syncthreads();
        if (tid == 0) {
            float mx = redmax[0];
            for (int w = 1; w < 8; w++) mx = fmaxf(mx, redmax[w]);
            bc[0] = mx;
        }
        __syncthreads();
        const float mx = bc[0];

        float e0 = __expf(v.x - mx), e1 = __expf(v.y - mx);
        float e2 = __expf(v.z - mx), e3 = __expf(v.w - mx);
        float zs = e0 + e1 + e2 + e3;
        float ms = e0 * mv.x + e1 * mv.y + e2 * mv.z + e3 * mv.w;
#pragma unroll
        for (int o = 16; o > 0; o >>= 1) {
            zs += __shfl_xor_sync(0xffffffffu, zs, o);
            ms += __shfl_xor_sync(0xffffffffu, ms, o);
        }
        if (lane == 0) { redz[warp] = zs; redm[warp] = ms; }
        __syncthreads();
        if (tid == 0) {
            float tz = 0.f, tm = 0.f;
            for (int w = 0; w < 8; w++) { tz += redz[w]; tm += redm[w]; }
            bc[1] = 1.0f / (tm + kEps * tz);
        }
        __syncthreads();
        const float inv = bc[1];

        const fp16 p0 = __float2half(e0 * mv.x * inv);
        const fp16 p1 = __float2half(e1 * mv.y * inv);
        const fp16 p2 = __float2half(e2 * mv.z * inv);
        const fp16 p3 = __float2half(e3 * mv.w * inv);
        *(uint2*)(g_pf + (size_t)idx * 1024 + 4 * tid) =
            make_uint2(packh2(p0, p1), packh2(p2, p3));
        return;
    }
    // ---- transpose: h (bf16 hi+lo, [b][n][d]) -> fp16 single [b][d][n] ----
    __shared__ fp16 th[64 * 65];
    const int tb = bid - 65536;              // 0..2047
    const int b = tb >> 6;
    const int rem = tb & 63;
    const int n0 = (rem >> 2) * 64, d0 = (rem & 3) * 64;
    const bf16* inh = g_hh + (size_t)b * 262144;
    const bf16* inl = g_hl + (size_t)b * 262144;
#pragma unroll
    for (int i = 0; i < 8; i++) {
        int idx = tid + i * 256;
        int r = idx >> 5, c2 = idx & 31;
        uint32_t vh = *(const uint32_t*)(inh + (size_t)(n0 + r) * 256 + d0 + c2 * 2);
        uint32_t vl = *(const uint32_t*)(inl + (size_t)(n0 + r) * 256 + d0 + c2 * 2);
        __nv_bfloat162 bh = *reinterpret_cast<__nv_bfloat162*>(&vh);
        __nv_bfloat162 bl = *reinterpret_cast<__nv_bfloat162*>(&vl);
        float f0 = __bfloat162float(bh.x) + __bfloat162float(bl.x);
        float f1 = __bfloat162float(bh.y) + __bfloat162float(bl.y);
        th[r * 65 + c2 * 2]     = __float2half(f0);
        th[r * 65 + c2 * 2 + 1] = __float2half(f1);
    }
    __syncthreads();
    fp16* oh = g_h16 + (size_t)b * 262144;
#pragma unroll
    for (int i = 0; i < 8; i++) {
        int idx = tid + i * 256;
        int r = idx >> 5, c2 = idx & 31;   // r = d_local, c2 = n pair
        uint32_t wh = packh2(th[(c2 * 2) * 65 + r], th[(c2 * 2 + 1) * 65 + r]);
        *(uint32_t*)(oh + (size_t)(d0 + r) * 1024 + n0 + c2 * 2) = wh;
    }
}

// Ucat[b][a][h*256+d] = prob[bh] @ h[b].  grid (2, 2, 256), K=1024. fp16 1-pass.
__global__ __launch_bounds__(128, 2) void u_mma_kernel() {
    extern __shared__ char sd[];
    const uint32_t sdu = s2u(sd);
    float c[4][8][4] = {};
    const int z = blockIdx.z, b = z >> 3, hh = z & 7;
    const int row0 = blockIdx.y * 128, col0 = blockIdx.x * 128;
    mma_nt_mainloop_u(g_pf + (size_t)z * 262144, 1024,
                      g_h16 + (size_t)b * 262144, 1024,
                      row0, col0, 1024, sdu, c);
    const int lane = threadIdx.x & 31, wid = threadIdx.x >> 5;
    const int wm = (wid & 1) << 6, wn = (wid >> 1) << 6;
#pragma unroll
    for (int mi = 0; mi < 4; mi++)
#pragma unroll
        for (int j = 0; j < 8; j++) {
            const int col = col0 + wn + j * 8 + (lane & 3) * 2;
#pragma unroll
            for (int q = 0; q < 2; q++) {
                const int row = row0 + wm + mi * 16 + (lane >> 2) + q * 8;
                const size_t p = ((size_t)b * 256 + row) * 2048 + hh * 256 + col;
                *(uint32_t*)(g_u16 + p) =
                    packh2(__float2half(c[mi][j][q*2]), __float2half(c[mi][j][q*2+1]));
            }
        }
}

// out[b] = 1/8 * U_f16[b] @ WVT_f16^T.  grid (2, 2, 32), K=2048. fp16 1-pass.
__global__ __launch_bounds__(128, 2) void out_mma_kernel(float* __restrict__ out) {
    extern __shared__ char sd[];
    const uint32_t sdu = s2u(sd);
    float c[4][8][4] = {};
    const int b = blockIdx.z;
    const int row0 = blockIdx.y * 128, col0 = blockIdx.x * 128;
    mma_nt_mainloop_u(g_u16 + (size_t)b * 524288, 2048,
                      g_wv16, 2048, row0, col0, 2048, sdu, c);
    const int lane = threadIdx.x & 31, wid = threadIdx.x >> 5;
    const int wm = (wid & 1) << 6, wn = (wid >> 1) << 6;
    float* D = out + (size_t)b * 65536;
#pragma unroll
    for (int mi = 0; mi < 4; mi++)
#pragma unroll
        for (int j = 0; j < 8; j++) {
            const int col = col0 + wn + j * 8 + (lane & 3) * 2;
#pragma unroll
            for (int q = 0; q < 2; q++) {
                const int row = row0 + wm + mi * 16 + (lane >> 2) + q * 8;
                float2 v;
                v.x = 0.125f * c[mi][j][q*2];
                v.y = 0.125f * c[mi][j][q*2+1];
                *(float2*)(D + (size_t)row * 256 + col) = v;
            }
        }
}

// ===========================================================================
extern "C" void kernel_launch(void* const* d_in, const int* in_sizes, int n_in,
                              void* d_out, int out_size)
{
    const float* x     = (const float*)d_in[0];
    const float* m     = (const float*)d_in[1];
    const float* W_enc = (const float*)d_in[2];
    const float* b_enc = (const float*)d_in[3];
    const float* WQ    = (const float*)d_in[4];
    const float* WK    = (const float*)d_in[5];
    const float* WV    = (const float*)d_in[6];
    float* out = (float*)d_out;

    cudaFuncSetAttribute(enc_mma_kernel, cudaFuncAttributeMaxDynamicSharedMemorySize, kDynSmem);
    cudaFuncSetAttribute(g_mma_kernel,   cudaFuncAttributeMaxDynamicSharedMemorySize, kDynSmem);
    cudaFuncSetAttribute(s_mma_kernel,   cudaFuncAttributeMaxDynamicSharedMemorySize, kDynSmem);
    cudaFuncSetAttribute(u_mma_kernel,   cudaFuncAttributeMaxDynamicSharedMemorySize, kDynSmemU);
    cudaFuncSetAttribute(out_mma_kernel, cudaFuncAttributeMaxDynamicSharedMemorySize, kDynSmemU);

    prep_kernel<<<8896, 256>>>(x, W_enc, WV, WQ, WK);                 // launch 1
    enc_mma_kernel<<<dim3(2, 256, 1), 128, kDynSmem>>>(b_enc);        // launch 2
    g_mma_kernel<<<dim3(2, 2, 256), 128, kDynSmem>>>();               // launch 3
    s_mma_kernel<<<dim3(8, 2, 256), 128, kDynSmem>>>();               // launch 4 (profiled)
    post_kernel<<<67584, 256>>>(m);                                   // launch 5
    u_mma_kernel<<<dim3(2, 2, 256), 128, kDynSmemU>>>();              // launch 6
    out_mma_kernel<<<dim3(2, 2, 32), 128, kDynSmemU>>>(out);          // launch 7
}

// round 14
// speedup vs baseline: 1.6222x; 1.0332x over previous
#include <cuda_runtime.h>
#include <cuda_bf16.h>
#include <cuda_fp16.h>
#include <cstdint>

using bf16 = __nv_bfloat16;
using fp16 = __half;

// ===========================================================================
// MHA_73607149519311 — round 14: r13 + warp-per-row softmax (no block syncs,
// mask loaded post-max to keep occupancy) + 4-stage pipeline on the fp16
// 1-pass loop (u/out). Numerics identical to r13.
// ===========================================================================

namespace {
constexpr float kScale = 1.0f / 16.0f;   // 1/sqrt(256)
constexpr float kEps   = 1e-12f;
constexpr int kDynSmem  = 98304;         // bf16 mainloop: 3 stages x 32KB
constexpr int kDynSmemU = 65536;         // fp16 mainloop: 4 stages x 16KB
}

// ---- scratch (static device globals; no dynamic allocation) ----
#define DEVBUF(name, count) __device__ __align__(128) bf16 name[count]
#define DEVBUFH(name, count) __device__ __align__(128) fp16 name[count]
DEVBUF(g_xh, 8388608);  DEVBUF(g_xl, 8388608);    // leaky(x) split   [32768,256]
DEVBUF(g_weh, 65536);   DEVBUF(g_wel, 65536);     // W_enc split      [256,256]
DEVBUF(g_mth, 524288);  DEVBUF(g_mtl, 524288);    // MT=WK@WQ^T split [8,256,256]
DEVBUF(g_hh, 8388608);  DEVBUF(g_hl, 8388608);    // h split          [32,1024,256]
DEVBUF(g_gh, 16777216); DEVBUF(g_gl, 16777216);   // G split          [256,256,256]
DEVBUFH(g_u16, 16777216);                          // U concat fp16    [32,256,2048]
DEVBUFH(g_wv16, 524288);                           // WVT_cat fp16     [256,2048]
DEVBUFH(g_pf, 67108864);                           // prob fp16        [256,256,1024]
DEVBUFH(g_h16, 8388608);                           // h^T fp16         [32,256,1024]
__device__ __align__(128) float g_S[67108864];     // S fp32           [256,256,1024]

// ============================= helpers =====================================
__device__ __forceinline__ uint32_t s2u(const void* p) {
    uint32_t a;
    asm("{ .reg .u64 t; cvta.to.shared.u64 t, %1; cvt.u32.u64 %0, t; }"
        : "=r"(a) : "l"(p));
    return a;
}

__device__ __forceinline__ void cp16(uint32_t saddr, const void* gaddr) {
    asm volatile("cp.async.cg.shared.global [%0], [%1], 16;"
                 :: "r"(saddr), "l"(gaddr) : "memory");
}
#define CP_COMMIT() asm volatile("cp.async.commit_group;" ::: "memory")
#define CP_WAIT2()  asm volatile("cp.async.wait_group 2;" ::: "memory")
#define CP_WAIT1()  asm volatile("cp.async.wait_group 1;" ::: "memory")
#define CP_WAIT0()  asm volatile("cp.async.wait_group 0;" ::: "memory")

__device__ __forceinline__ void ldmx4(uint32_t* r, uint32_t addr) {
    asm volatile("ldmatrix.sync.aligned.m8n8.x4.shared.b16 {%0,%1,%2,%3}, [%4];"
                 : "=r"(r[0]), "=r"(r[1]), "=r"(r[2]), "=r"(r[3]) : "r"(addr));
}

__device__ __forceinline__ void mma16816(float* c, const uint32_t* a,
                                         uint32_t b0, uint32_t b1) {
    asm volatile(
        "mma.sync.aligned.m16n8k16.row.col.f32.bf16.bf16.f32 "
        "{%0,%1,%2,%3}, {%4,%5,%6,%7}, {%8,%9}, {%0,%1,%2,%3};"
        : "+f"(c[0]), "+f"(c[1]), "+f"(c[2]), "+f"(c[3])
        : "r"(a[0]), "r"(a[1]), "r"(a[2]), "r"(a[3]), "r"(b0), "r"(b1));
}

__device__ __forceinline__ void mma16816h(float* c, const uint32_t* a,
                                          uint32_t b0, uint32_t b1) {
    asm volatile(
        "mma.sync.aligned.m16n8k16.row.col.f32.f16.f16.f32 "
        "{%0,%1,%2,%3}, {%4,%5,%6,%7}, {%8,%9}, {%0,%1,%2,%3};"
        : "+f"(c[0]), "+f"(c[1]), "+f"(c[2]), "+f"(c[3])
        : "r"(a[0]), "r"(a[1]), "r"(a[2]), "r"(a[3]), "r"(b0), "r"(b1));
}

__device__ __forceinline__ void split2(float v, bf16& hi, bf16& lo) {
    hi = __float2bfloat16(v);
    lo = __float2bfloat16(v - __bfloat162float(hi));
}
__device__ __forceinline__ uint32_t packbf2(bf16 a, bf16 b) {
    __nv_bfloat162 t; t.x = a; t.y = b;
    return *reinterpret_cast<uint32_t*>(&t);
}
__device__ __forceinline__ uint32_t packh2(fp16 a, fp16 b) {
    __half2 t; t.x = a; t.y = b;
    return *reinterpret_cast<uint32_t*>(&t);
}

// Swizzled offset within a (rows x 64B) tile: row r, seg s (0..3).
__device__ __forceinline__ uint32_t sw64(int r, int s) {
    return (uint32_t)((r << 6) + (((s ^ ((r >> 1) & 3)) & 3) << 4));
}

// ==================== bf16 split-2 mainloop (r9, proven) ===================
// CTA tile 128x128, NT. 128 threads = 4 warps (2M x 2N), warp tile 64x64.
// cp.async 3-stage, K chunks of 32. Stage (32KB): Ahi|Alo|Bhi|Blo 8K each.

__device__ __forceinline__ void issue_chunk(
    const bf16* __restrict__ Ah, const bf16* __restrict__ Al, int lda,
    const bf16* __restrict__ Bh, const bf16* __restrict__ Bl, int ldb,
    int row0, int col0, int kt, uint32_t sb)
{
    const int tid = threadIdx.x;
#pragma unroll
    for (int i = 0; i < 4; i++) {
        const int idx = tid + i * 128;       // 0..511
        const int r = idx >> 2, s = idx & 3;
        const uint32_t off = sw64(r, s);
        const size_t ga = (size_t)(row0 + r) * lda + kt + s * 8;
        const size_t gb = (size_t)(col0 + r) * ldb + kt + s * 8;
        cp16(sb + off,         Ah + ga);
        cp16(sb + 8192 + off,  Al + ga);
        cp16(sb + 16384 + off, Bh + gb);
        cp16(sb + 24576 + off, Bl + gb);
    }
    CP_COMMIT();
}

__device__ __forceinline__ void mma_nt_mainloop(
    const bf16* __restrict__ Ah, const bf16* __restrict__ Al, int lda,
    const bf16* __restrict__ Bh, const bf16* __restrict__ Bl, int ldb,
    int row0, int col0, int K, uint32_t sdu, float (&c)[4][8][4])
{
    const int tid = threadIdx.x;
    const int lane = tid & 31, wid = tid >> 5;
    const int wm = (wid & 1) << 6;
    const int wn = (wid >> 1) << 6;

    const int arow0 = wm + (lane & 15);
    const int akseg = lane >> 4;
    const int brow0 = wn + ((lane >> 4) << 3) + (lane & 7);
    const int bkseg = (lane >> 3) & 1;

    const int NC = K >> 5;
    issue_chunk(Ah, Al, lda, Bh, Bl, ldb, row0, col0, 0, sdu);
    issue_chunk(Ah, Al, lda, Bh, Bl, ldb, row0, col0, 32, sdu + 32768);

    int buf = 0;
    for (int ci = 0; ci < NC; ci++) {
        if (ci + 1 < NC) { CP_WAIT1(); } else { CP_WAIT0(); }
        __syncthreads();
        if (ci + 2 < NC) {
            int nb = buf + 2; if (nb >= 3) nb -= 3;
            issue_chunk(Ah, Al, lda, Bh, Bl, ldb, row0, col0,
                        (ci + 2) << 5, sdu + nb * 32768);
        }

        const uint32_t sb = sdu + buf * 32768;
#pragma unroll
        for (int k = 0; k < 2; k++) {
            uint32_t afh[4][4], afl[4][4], bfh[4][4], bfl[4][4];
#pragma unroll
            for (int mi = 0; mi < 4; mi++) {
                const int r = arow0 + mi * 16;
                const uint32_t off = sw64(r, 2 * k + akseg);
                ldmx4(afh[mi], sb + off);
                ldmx4(afl[mi], sb + 8192 + off);
            }
#pragma unroll
            for (int nj = 0; nj < 4; nj++) {
                const int r = brow0 + nj * 16;
                const uint32_t off = sw64(r, 2 * k + bkseg);
                ldmx4(bfh[nj], sb + 16384 + off);
                ldmx4(bfl[nj], sb + 24576 + off);
            }
#pragma unroll
            for (int mi = 0; mi < 4; mi++)
#pragma unroll
                for (int ni = 0; ni < 8; ni++) {
                    const int nj = ni >> 1, o = (ni & 1) << 1;
                    mma16816(c[mi][ni], afh[mi], bfh[nj][o], bfh[nj][o + 1]);
                }
#pragma unroll
            for (int mi = 0; mi < 4; mi++)
#pragma unroll
                for (int ni = 0; ni < 8; ni++) {
                    const int nj = ni >> 1, o = (ni & 1) << 1;
                    mma16816(c[mi][ni], afh[mi], bfl[nj][o], bfl[nj][o + 1]);
                }
#pragma unroll
            for (int mi = 0; mi < 4; mi++)
#pragma unroll
                for (int ni = 0; ni < 8; ni++) {
                    const int nj = ni >> 1, o = (ni & 1) << 1;
                    mma16816(c[mi][ni], afl[mi], bfh[nj][o], bfh[nj][o + 1]);
                }
        }
        if (++buf == 3) buf = 0;
    }
}

// ==================== fp16 1-pass mainloop (u, out) ========================
// A, B single fp16. 4-stage pipeline; stage (16KB): A|B 8K each.

__device__ __forceinline__ void issue_chunk_u(
    const fp16* __restrict__ A, int lda,
    const fp16* __restrict__ B, int ldb,
    int row0, int col0, int kt, uint32_t sb)
{
    const int tid = threadIdx.x;
#pragma unroll
    for (int i = 0; i < 4; i++) {
        const int idx = tid + i * 128;       // 0..511
        const int r = idx >> 2, s = idx & 3;
        const uint32_t off = sw64(r, s);
        const size_t ga = (size_t)(row0 + r) * lda + kt + s * 8;
        const size_t gb = (size_t)(col0 + r) * ldb + kt + s * 8;
        cp16(sb + off,        A + ga);
        cp16(sb + 8192 + off, B + gb);
    }
    CP_COMMIT();
}

__device__ __forceinline__ void mma_nt_mainloop_u(
    const fp16* __restrict__ A, int lda,
    const fp16* __restrict__ B, int ldb,
    int row0, int col0, int K, uint32_t sdu, float (&c)[4][8][4])
{
    const int tid = threadIdx.x;
    const int lane = tid & 31, wid = tid >> 5;
    const int wm = (wid & 1) << 6;
    const int wn = (wid >> 1) << 6;

    const int arow0 = wm + (lane & 15);
    const int akseg = lane >> 4;
    const int brow0 = wn + ((lane >> 4) << 3) + (lane & 7);
    const int bkseg = (lane >> 3) & 1;

    const int NC = K >> 5;                  // NC >= 32 for all callers
    issue_chunk_u(A, lda, B, ldb, row0, col0, 0,  sdu);
    issue_chunk_u(A, lda, B, ldb, row0, col0, 32, sdu + 16384);
    issue_chunk_u(A, lda, B, ldb, row0, col0, 64, sdu + 32768);

    int buf = 0;
    for (int ci = 0; ci < NC; ci++) {
        if (ci + 2 < NC)      { CP_WAIT2(); }
        else if (ci + 1 < NC) { CP_WAIT1(); }
        else                  { CP_WAIT0(); }
        __syncthreads();      // all warps done compute(ci-1)
        if (ci + 3 < NC) {
            int nb = buf + 3; if (nb >= 4) nb -= 4;
            issue_chunk_u(A, lda, B, ldb, row0, col0,
                          (ci + 3) << 5, sdu + nb * 16384);
        }

        const uint32_t sb = sdu + buf * 16384;
#pragma unroll
        for (int k = 0; k < 2; k++) {
            uint32_t af[4][4], bf[4][4];
#pragma unroll
            for (int mi = 0; mi < 4; mi++) {
                const int r = arow0 + mi * 16;
                const uint32_t off = sw64(r, 2 * k + akseg);
                ldmx4(af[mi], sb + off);
            }
#pragma unroll
            for (int nj = 0; nj < 4; nj++) {
                const int r = brow0 + nj * 16;
                const uint32_t off = sw64(r, 2 * k + bkseg);
                ldmx4(bf[nj], sb + 8192 + off);
            }
#pragma unroll
            for (int mi = 0; mi < 4; mi++)
#pragma unroll
                for (int ni = 0; ni < 8; ni++) {
                    const int nj = ni >> 1, o = (ni & 1) << 1;
                    mma16816h(c[mi][ni], af[mi], bf[nj][o], bf[nj][o + 1]);
                }
        }
        if (++buf == 4) buf = 0;
    }
}

// Epilogue mapping (both loops) for c[mi][j][q]:
//   row = row0 + wm + mi*16 + (lane>>2) + (q>=2 ? 8 : 0)
//   col = col0 + wn + j*8 + (lane&3)*2 + (q&1)
//   wm = (wid&1)<<6, wn = (wid>>1)<<6

// ===================== merged prep kernel (launch #1) ======================
// blockIdx.x: [0,8192) conv_x | [8192,8256) conv_wenc | [8256,8768) conv_wvt
//             | [8768,8896) mt
__global__ __launch_bounds__(256) void prep_kernel(
    const float* __restrict__ x, const float* __restrict__ W_enc,
    const float* __restrict__ WV,
    const float* __restrict__ WQ, const float* __restrict__ WK)
{
    const int bid = blockIdx.x;
    if (bid < 8192) {
        size_t idx = (size_t)bid * 256 + threadIdx.x;   // over float4s
        float4 v = ((const float4*)x)[idx];
        v.x = v.x > 0.f ? v.x : 0.01f * v.x;
        v.y = v.y > 0.f ? v.y : 0.01f * v.y;
        v.z = v.z > 0.f ? v.z : 0.01f * v.z;
        v.w = v.w > 0.f ? v.w : 0.01f * v.w;
        bf16 h0,l0,h1,l1,h2,l2,h3,l3;
        split2(v.x,h0,l0); split2(v.y,h1,l1); split2(v.z,h2,l2); split2(v.w,h3,l3);
        *(uint2*)(g_xh + idx * 4) = make_uint2(packbf2(h0,h1), packbf2(h2,h3));
        *(uint2*)(g_xl + idx * 4) = make_uint2(packbf2(l0,l1), packbf2(l2,l3));
        return;
    }
    if (bid < 8256) {
        size_t idx = (size_t)(bid - 8192) * 256 + threadIdx.x;  // 16384 float4s
        float4 v = ((const float4*)W_enc)[idx];
        bf16 h0,l0,h1,l1,h2,l2,h3,l3;
        split2(v.x,h0,l0); split2(v.y,h1,l1); split2(v.z,h2,l2); split2(v.w,h3,l3);
        *(uint2*)(g_weh + idx * 4) = make_uint2(packbf2(h0,h1), packbf2(h2,h3));
        *(uint2*)(g_wel + idx * 4) = make_uint2(packbf2(l0,l1), packbf2(l2,l3));
        return;
    }
    if (bid < 8768) {
        __shared__ float t[32][33];
        const int tb = bid - 8256;
        const int k0 = (tb & 63) * 32, e0 = (tb >> 6) * 32;
        const int tx = threadIdx.x & 31, ty = threadIdx.x >> 5;
#pragma unroll
        for (int i = 0; i < 4; i++) {
            const int k = ty + i * 8;
            t[k][tx] = WV[(size_t)(k0 + k) * 256 + e0 + tx];
        }
        __syncthreads();
#pragma unroll
        for (int i = 0; i < 4; i++) {
            const int e = ty + i * 8;
            g_wv16[(size_t)(e0 + e) * 2048 + k0 + tx] = __float2half(t[tx][e]);
        }
        return;
    }
    {
        __shared__ float As[8][68], Bs[8][68];
        float acc[4][4] = {};
        const int tb = bid - 8768;
        const int hh = tb >> 4;
        const int row0 = ((tb >> 2) & 3) * 64, col0 = (tb & 3) * 64;
        const float* A = WK + (size_t)hh * 65536;
        const float* B = WQ + (size_t)hh * 65536;
        const int tid = threadIdx.x;
        const int lr = tid >> 2, lk = (tid & 3) << 1;
        const int tx = tid & 15, ty = tid >> 4;
        const float* aP = A + (size_t)(row0 + lr) * 256 + lk;
        const float* bP = B + (size_t)(col0 + lr) * 256 + lk;
        for (int kt = 0; kt < 256; kt += 8) {
            float2 av = *(const float2*)(aP + kt);
            float2 bv = *(const float2*)(bP + kt);
            As[lk][lr] = av.x; As[lk + 1][lr] = av.y;
            Bs[lk][lr] = bv.x; Bs[lk + 1][lr] = bv.y;
            __syncthreads();
#pragma unroll
            for (int k = 0; k < 8; k++) {
                float ar[4], br[4];
                *(float4*)ar = *(const float4*)(&As[k][ty * 4]);
                *(float4*)br = *(const float4*)(&Bs[k][tx * 4]);
#pragma unroll
                for (int i = 0; i < 4; i++)
#pragma unroll
                    for (int j = 0; j < 4; j++)
                        acc[i][j] = fmaf(ar[i], br[j], acc[i][j]);
            }
            __syncthreads();
        }
        bf16* Dh = g_mth + (size_t)hh * 65536;
        bf16* Dl = g_mtl + (size_t)hh * 65536;
#pragma unroll
        for (int i = 0; i < 4; i++) {
            size_t base = (size_t)(row0 + ty * 4 + i) * 256 + col0 + tx * 4;
#pragma unroll
            for (int j = 0; j < 4; j += 2) {
                bf16 h0,l0,h1,l1;
                split2(acc[i][j],h0,l0); split2(acc[i][j+1],h1,l1);
                *(uint32_t*)(Dh + base + j) = packbf2(h0,h1);
                *(uint32_t*)(Dl + base + j) = packbf2(l0,l1);
            }
        }
    }
}

// ============================== MMA kernels ================================

// h = x_sp @ Wenc^T + b. grid (2, 256).
__global__ __launch_bounds__(128, 2) void enc_mma_kernel(const float* __restrict__ bias) {
    extern __shared__ char sd[];
    const uint32_t sdu = s2u(sd);
    float c[4][8][4] = {};
    const int row0 = blockIdx.y * 128, col0 = blockIdx.x * 128;
    mma_nt_mainloop(g_xh, g_xl, 256, g_weh, g_wel, 256, row0, col0, 256, sdu, c);
    const int lane = threadIdx.x & 31, wid = threadIdx.x >> 5;
    const int wm = (wid & 1) << 6, wn = (wid >> 1) << 6;
#pragma unroll
    for (int mi = 0; mi < 4; mi++)
#pragma unroll
        for (int j = 0; j < 8; j++) {
            const int col = col0 + wn + j * 8 + (lane & 3) * 2;
            const float b0 = bias[col], b1 = bias[col + 1];
#pragma unroll
            for (int q = 0; q < 2; q++) {
                const int row = row0 + wm + mi * 16 + (lane >> 2) + q * 8;
                const float v0 = c[mi][j][q * 2]     + b0;
                const float v1 = c[mi][j][q * 2 + 1] + b1;
                bf16 h0,l0,h1,l1; split2(v0,h0,l0); split2(v1,h1,l1);
                const size_t p = (size_t)row * 256 + col;
                *(uint32_t*)(g_hh + p) = packbf2(h0,h1);
                *(uint32_t*)(g_hl + p) = packbf2(l0,l1);
            }
        }
}

// G[bh] = ha_sp[b] @ MT[h]^T. grid (2, 2, 256).
__global__ __launch_bounds__(128, 2) void g_mma_kernel() {
    extern __shared__ char sd[];
    const uint32_t sdu = s2u(sd);
    float c[4][8][4] = {};
    const int z = blockIdx.z, b = z >> 3, hh = z & 7;
    const int row0 = blockIdx.y * 128, col0 = blockIdx.x * 128;
    mma_nt_mainloop(g_hh + (size_t)b * 262144, g_hl + (size_t)b * 262144, 256,
                    g_mth + (size_t)hh * 65536, g_mtl + (size_t)hh * 65536, 256,
                    row0, col0, 256, sdu, c);
    const int lane = threadIdx.x & 31, wid = threadIdx.x >> 5;
    const int wm = (wid & 1) << 6, wn = (wid >> 1) << 6;
    bf16* Dh = g_gh + (size_t)z * 65536;
    bf16* Dl = g_gl + (size_t)z * 65536;
#pragma unroll
    for (int mi = 0; mi < 4; mi++)
#pragma unroll
        for (int j = 0; j < 8; j++) {
            const int col = col0 + wn + j * 8 + (lane & 3) * 2;
#pragma unroll
            for (int q = 0; q < 2; q++) {
                const int row = row0 + wm + mi * 16 + (lane >> 2) + q * 8;
                bf16 h0,l0,h1,l1;
                split2(c[mi][j][q*2],h0,l0); split2(c[mi][j][q*2+1],h1,l1);
                const size_t p = (size_t)row * 256 + col;
                *(uint32_t*)(Dh + p) = packbf2(h0,h1);
                *(uint32_t*)(Dl + p) = packbf2(l0,l1);
            }
        }
}

// S[bh] = G[bh] @ h[b]^T * SCALE -> fp32. grid (8, 2, 256).  [profiled slot]
__global__ __launch_bounds__(128, 2) void s_mma_kernel() {
    extern __shared__ char sd[];
    const uint32_t sdu = s2u(sd);
    float c[4][8][4] = {};
    const int z = blockIdx.z, b = z >> 3;
    const int row0 = blockIdx.y * 128, col0 = blockIdx.x * 128;
    mma_nt_mainloop(g_gh + (size_t)z * 65536, g_gl + (size_t)z * 65536, 256,
                    g_hh + (size_t)b * 262144, g_hl + (size_t)b * 262144, 256,
                    row0, col0, 256, sdu, c);
    const int lane = threadIdx.x & 31, wid = threadIdx.x >> 5;
    const int wm = (wid & 1) << 6, wn = (wid >> 1) << 6;
    float* D = g_S + (size_t)z * 262144;
#pragma unroll
    for (int mi = 0; mi < 4; mi++)
#pragma unroll
        for (int j = 0; j < 8; j++) {
            const int col = col0 + wn + j * 8 + (lane & 3) * 2;
#pragma unroll
            for (int q = 0; q < 2; q++) {
                const int row = row0 + wm + mi * 16 + (lane >> 2) + q * 8;
                float2 v;
                v.x = kScale * c[mi][j][q*2];
                v.y = kScale * c[mi][j][q*2+1];
                *(float2*)(D + (size_t)row * 1024 + col) = v;
            }
        }
}

// =============== fused softmax + h-transpose (launch #5) ===================
// bid < 8192: warp-per-row softmax (8 rows per 256-thread block).
// bid >= 8192: transpose h (bf16 split -> single fp16, [n,d]->[d,n]).
__global__ __launch_bounds__(256) void post_kernel(const float* __restrict__ mglob) {
    const int bid = blockIdx.x;
    const int tid = threadIdx.x;
    if (bid < 8192) {
        const int lane = tid & 31;
        const int row_id = bid * 8 + (tid >> 5);       // 0..65535
        const int a = row_id & 255, b = row_id >> 11;
        const float4* row4 = (const float4*)(g_S + (size_t)row_id * 1024);
        const float4* m4 = (const float4*)(mglob + ((size_t)b * 256 + a) * 1024);

        float4 v[8];
#pragma unroll
        for (int i = 0; i < 8; i++) v[i] = row4[lane + i * 32];

        float mx = -1e30f;
#pragma unroll
        for (int i = 0; i < 8; i++)
            mx = fmaxf(mx, fmaxf(fmaxf(v[i].x, v[i].y), fmaxf(v[i].z, v[i].w)));
#pragma unroll
        for (int o = 16; o > 0; o >>= 1)
            mx = fmaxf(mx, __shfl_xor_sync(0xffffffffu, mx, o));

        // exp pass; load mask now (keeps register count low for occupancy)
        float4 mv[8];
#pragma unroll
        for (int i = 0; i < 8; i++) mv[i] = m4[lane + i * 32];

        float zs = 0.f, ms = 0.f;
#pragma unroll
        for (int i = 0; i < 8; i++) {
            v[i].x = __expf(v[i].x - mx);
            v[i].y = __expf(v[i].y - mx);
            v[i].z = __expf(v[i].z - mx);
            v[i].w = __expf(v[i].w - mx);
            zs += v[i].x + v[i].y + v[i].z + v[i].w;
            ms += v[i].x * mv[i].x + v[i].y * mv[i].y
                + v[i].z * mv[i].z + v[i].w * mv[i].w;
        }
#pragma unroll
        for (int o = 16; o > 0; o >>= 1) {
            zs += __shfl_xor_sync(0xffffffffu, zs, o);
            ms += __shfl_xor_sync(0xffffffffu, ms, o);
        }
        const float inv = 1.0f / (ms + kEps * zs);

        uint2* out2 = (uint2*)(g_pf + (size_t)row_id * 1024);
#pragma unroll
        for (int i = 0; i < 8; i++) {
            const fp16 p0 = __float2half(v[i].x * mv[i].x * inv);
            const fp16 p1 = __float2half(v[i].y * mv[i].y * inv);
            const fp16 p2 = __float2half(v[i].z * mv[i].z * inv);
            const fp16 p3 = __float2half(v[i].w * mv[i].w * inv);
            out2[lane + i * 32] = make_uint2(packh2(p0, p1), packh2(p2, p3));
        }
        return;
    }
    // ---- transpose: h (bf16 hi+lo, [b][n][d]) -> fp16 single [b][d][n] ----
    __shared__ fp16 th[64 * 65];
    const int tb = bid - 8192;               // 0..2047
    const int b = tb >> 6;
    const int rem = tb & 63;
    const int n0 = (rem >> 2) * 64, d0 = (rem & 3) * 64;
    const bf16* inh = g_hh + (size_t)b * 262144;
    const bf16* inl = g_hl + (size_t)b * 262144;
#pragma unroll
    for (int i = 0; i < 8; i++) {
        int idx = tid + i * 256;
        int r = idx >> 5, c2 = idx & 31;
        uint32_t vh = *(const uint32_t*)(inh + (size_t)(n0 + r) * 256 + d0 + c2 * 2);
        uint32_t vl = *(const uint32_t*)(inl + (size_t)(n0 + r) * 256 + d0 + c2 * 2);
        __nv_bfloat162 bh = *reinterpret_cast<__nv_bfloat162*>(&vh);
        __nv_bfloat162 bl = *reinterpret_cast<__nv_bfloat162*>(&vl);
        float f0 = __bfloat162float(bh.x) + __bfloat162float(bl.x);
        float f1 = __bfloat162float(bh.y) + __bfloat162float(bl.y);
        th[r * 65 + c2 * 2]     = __float2half(f0);
        th[r * 65 + c2 * 2 + 1] = __float2half(f1);
    }
    __syncthreads();
    fp16* oh = g_h16 + (size_t)b * 262144;
#pragma unroll
    for (int i = 0; i < 8; i++) {
        int idx = tid + i * 256;
        int r = idx >> 5, c2 = idx & 31;   // r = d_local, c2 = n pair
        uint32_t wh = packh2(th[(c2 * 2) * 65 + r], th[(c2 * 2 + 1) * 65 + r]);
        *(uint32_t*)(oh + (size_t)(d0 + r) * 1024 + n0 + c2 * 2) = wh;
    }
}

// Ucat[b][a][h*256+d] = prob[bh] @ h[b].  grid (2, 2, 256), K=1024. fp16 1-pass.
__global__ __launch_bounds__(128, 2) void u_mma_kernel() {
    extern __shared__ char sd[];
    const uint32_t sdu = s2u(sd);
    float c[4][8][4] = {};
    const int z = blockIdx.z, b = z >> 3, hh = z & 7;
    const int row0 = blockIdx.y * 128, col0 = blockIdx.x * 128;
    mma_nt_mainloop_u(g_pf + (size_t)z * 262144, 1024,
                      g_h16 + (size_t)b * 262144, 1024,
                      row0, col0, 1024, sdu, c);
    const int lane = threadIdx.x & 31, wid = threadIdx.x >> 5;
    const int wm = (wid & 1) << 6, wn = (wid >> 1) << 6;
#pragma unroll
    for (int mi = 0; mi < 4; mi++)
#pragma unroll
        for (int j = 0; j < 8; j++) {
            const int col = col0 + wn + j * 8 + (lane & 3) * 2;
#pragma unroll
            for (int q = 0; q < 2; q++) {
                const int row = row0 + wm + mi * 16 + (lane >> 2) + q * 8;
                const size_t p = ((size_t)b * 256 + row) * 2048 + hh * 256 + col;
                *(uint32_t*)(g_u16 + p) =
                    packh2(__float2half(c[mi][j][q*2]), __float2half(c[mi][j][q*2+1]));
            }
        }
}

// out[b] = 1/8 * U_f16[b] @ WVT_f16^T.  grid (2, 2, 32), K=2048. fp16 1-pass.
__global__ __launch_bounds__(128, 2) void out_mma_kernel(float* __restrict__ out) {
    extern __shared__ char sd[];
    const uint32_t sdu = s2u(sd);
    float c[4][8][4] = {};
    const int b = blockIdx.z;
    const int row0 = blockIdx.y * 128, col0 = blockIdx.x * 128;
    mma_nt_mainloop_u(g_u16 + (size_t)b * 524288, 2048,
                      g_wv16, 2048, row0, col0, 2048, sdu, c);
    const int lane = threadIdx.x & 31, wid = threadIdx.x >> 5;
    const int wm = (wid & 1) << 6, wn = (wid >> 1) << 6;
    float* D = out + (size_t)b * 65536;
#pragma unroll
    for (int mi = 0; mi < 4; mi++)
#pragma unroll
        for (int j = 0; j < 8; j++) {
            const int col = col0 + wn + j * 8 + (lane & 3) * 2;
#pragma unroll
            for (int q = 0; q < 2; q++) {
                const int row = row0 + wm + mi * 16 + (lane >> 2) + q * 8;
                float2 v;
                v.x = 0.125f * c[mi][j][q*2];
                v.y = 0.125f * c[mi][j][q*2+1];
                *(float2*)(D + (size_t)row * 256 + col) = v;
            }
        }
}

// ===========================================================================
extern "C" void kernel_launch(void* const* d_in, const int* in_sizes, int n_in,
                              void* d_out, int out_size)
{
    const float* x     = (const float*)d_in[0];
    const float* m     = (const float*)d_in[1];
    const float* W_enc = (const float*)d_in[2];
    const float* b_enc = (const float*)d_in[3];
    const float* WQ    = (const float*)d_in[4];
    const float* WK    = (const float*)d_in[5];
    const float* WV    = (const float*)d_in[6];
    float* out = (float*)d_out;

    cudaFuncSetAttribute(enc_mma_kernel, cudaFuncAttributeMaxDynamicSharedMemorySize, kDynSmem);
    cudaFuncSetAttribute(g_mma_kernel,   cudaFuncAttributeMaxDynamicSharedMemorySize, kDynSmem);
    cudaFuncSetAttribute(s_mma_kernel,   cudaFuncAttributeMaxDynamicSharedMemorySize, kDynSmem);
    cudaFuncSetAttribute(u_mma_kernel,   cudaFuncAttributeMaxDynamicSharedMemorySize, kDynSmemU);
    cudaFuncSetAttribute(out_mma_kernel, cudaFuncAttributeMaxDynamicSharedMemorySize, kDynSmemU);

    prep_kernel<<<8896, 256>>>(x, W_enc, WV, WQ, WK);                 // launch 1
    enc_mma_kernel<<<dim3(2, 256, 1), 128, kDynSmem>>>(b_enc);        // launch 2
    g_mma_kernel<<<dim3(2, 2, 256), 128, kDynSmem>>>();               // launch 3
    s_mma_kernel<<<dim3(8, 2, 256), 128, kDynSmem>>>();               // launch 4 (profiled)
    post_kernel<<<10240, 256>>>(m);                                   // launch 5
    u_mma_kernel<<<dim3(2, 2, 256), 128, kDynSmemU>>>();              // launch 6
    out_mma_kernel<<<dim3(2, 2, 32), 128, kDynSmemU>>>(out);          // launch 7
}

// round 15
// speedup vs baseline: 1.6499x; 1.0171x over previous
#include <cuda_runtime.h>
#include <cuda_bf16.h>
#include <cuda_fp16.h>
#include <cstdint>

using bf16 = __nv_bfloat16;
using fp16 = __half;

// ===========================================================================
// MHA_73607149519311 — round 15: r14 + transpose elimination. enc's epilogue
// transposes its h tile through (post-mainloop idle) pipeline smem and writes
// g_h16 [b][d][n] directly; post_kernel is softmax-only. Numerics: h16 now
// rounds from full fp32 (was hi+lo sum) — marginally more accurate.
// ===========================================================================

namespace {
constexpr float kScale = 1.0f / 16.0f;   // 1/sqrt(256)
constexpr float kEps   = 1e-12f;
constexpr int kDynSmem  = 98304;         // bf16 mainloop: 3 stages x 32KB
constexpr int kDynSmemU = 65536;         // fp16 mainloop: 4 stages x 16KB
}

// ---- scratch (static device globals; no dynamic allocation) ----
#define DEVBUF(name, count) __device__ __align__(128) bf16 name[count]
#define DEVBUFH(name, count) __device__ __align__(128) fp16 name[count]
DEVBUF(g_xh, 8388608);  DEVBUF(g_xl, 8388608);    // leaky(x) split   [32768,256]
DEVBUF(g_weh, 65536);   DEVBUF(g_wel, 65536);     // W_enc split      [256,256]
DEVBUF(g_mth, 524288);  DEVBUF(g_mtl, 524288);    // MT=WK@WQ^T split [8,256,256]
DEVBUF(g_hh, 8388608);  DEVBUF(g_hl, 8388608);    // h split          [32,1024,256]
DEVBUF(g_gh, 16777216); DEVBUF(g_gl, 16777216);   // G split          [256,256,256]
DEVBUFH(g_u16, 16777216);                          // U concat fp16    [32,256,2048]
DEVBUFH(g_wv16, 524288);                           // WVT_cat fp16     [256,2048]
DEVBUFH(g_pf, 67108864);                           // prob fp16        [256,256,1024]
DEVBUFH(g_h16, 8388608);                           // h^T fp16         [32,256,1024]
__device__ __align__(128) float g_S[67108864];     // S fp32           [256,256,1024]

// ============================= helpers =====================================
__device__ __forceinline__ uint32_t s2u(const void* p) {
    uint32_t a;
    asm("{ .reg .u64 t; cvta.to.shared.u64 t, %1; cvt.u32.u64 %0, t; }"
        : "=r"(a) : "l"(p));
    return a;
}

__device__ __forceinline__ void cp16(uint32_t saddr, const void* gaddr) {
    asm volatile("cp.async.cg.shared.global [%0], [%1], 16;"
                 :: "r"(saddr), "l"(gaddr) : "memory");
}
#define CP_COMMIT() asm volatile("cp.async.commit_group;" ::: "memory")
#define CP_WAIT2()  asm volatile("cp.async.wait_group 2;" ::: "memory")
#define CP_WAIT1()  asm volatile("cp.async.wait_group 1;" ::: "memory")
#define CP_WAIT0()  asm volatile("cp.async.wait_group 0;" ::: "memory")

__device__ __forceinline__ void ldmx4(uint32_t* r, uint32_t addr) {
    asm volatile("ldmatrix.sync.aligned.m8n8.x4.shared.b16 {%0,%1,%2,%3}, [%4];"
                 : "=r"(r[0]), "=r"(r[1]), "=r"(r[2]), "=r"(r[3]) : "r"(addr));
}

__device__ __forceinline__ void mma16816(float* c, const uint32_t* a,
                                         uint32_t b0, uint32_t b1) {
    asm volatile(
        "mma.sync.aligned.m16n8k16.row.col.f32.bf16.bf16.f32 "
        "{%0,%1,%2,%3}, {%4,%5,%6,%7}, {%8,%9}, {%0,%1,%2,%3};"
        : "+f"(c[0]), "+f"(c[1]), "+f"(c[2]), "+f"(c[3])
        : "r"(a[0]), "r"(a[1]), "r"(a[2]), "r"(a[3]), "r"(b0), "r"(b1));
}

__device__ __forceinline__ void mma16816h(float* c, const uint32_t* a,
                                          uint32_t b0, uint32_t b1) {
    asm volatile(
        "mma.sync.aligned.m16n8k16.row.col.f32.f16.f16.f32 "
        "{%0,%1,%2,%3}, {%4,%5,%6,%7}, {%8,%9}, {%0,%1,%2,%3};"
        : "+f"(c[0]), "+f"(c[1]), "+f"(c[2]), "+f"(c[3])
        : "r"(a[0]), "r"(a[1]), "r"(a[2]), "r"(a[3]), "r"(b0), "r"(b1));
}

__device__ __forceinline__ void split2(float v, bf16& hi, bf16& lo) {
    hi = __float2bfloat16(v);
    lo = __float2bfloat16(v - __bfloat162float(hi));
}
__device__ __forceinline__ uint32_t packbf2(bf16 a, bf16 b) {
    __nv_bfloat162 t; t.x = a; t.y = b;
    return *reinterpret_cast<uint32_t*>(&t);
}
__device__ __forceinline__ uint32_t packh2(fp16 a, fp16 b) {
    __half2 t; t.x = a; t.y = b;
    return *reinterpret_cast<uint32_t*>(&t);
}

// Swizzled offset within a (rows x 64B) tile: row r, seg s (0..3).
__device__ __forceinline__ uint32_t sw64(int r, int s) {
    return (uint32_t)((r << 6) + (((s ^ ((r >> 1) & 3)) & 3) << 4));
}

// ==================== bf16 split-2 mainloop (r9, proven) ===================
// CTA tile 128x128, NT. 128 threads = 4 warps (2M x 2N), warp tile 64x64.
// cp.async 3-stage, K chunks of 32. Stage (32KB): Ahi|Alo|Bhi|Blo 8K each.

__device__ __forceinline__ void issue_chunk(
    const bf16* __restrict__ Ah, const bf16* __restrict__ Al, int lda,
    const bf16* __restrict__ Bh, const bf16* __restrict__ Bl, int ldb,
    int row0, int col0, int kt, uint32_t sb)
{
    const int tid = threadIdx.x;
#pragma unroll
    for (int i = 0; i < 4; i++) {
        const int idx = tid + i * 128;       // 0..511
        const int r = idx >> 2, s = idx & 3;
        const uint32_t off = sw64(r, s);
        const size_t ga = (size_t)(row0 + r) * lda + kt + s * 8;
        const size_t gb = (size_t)(col0 + r) * ldb + kt + s * 8;
        cp16(sb + off,         Ah + ga);
        cp16(sb + 8192 + off,  Al + ga);
        cp16(sb + 16384 + off, Bh + gb);
        cp16(sb + 24576 + off, Bl + gb);
    }
    CP_COMMIT();
}

__device__ __forceinline__ void mma_nt_mainloop(
    const bf16* __restrict__ Ah, const bf16* __restrict__ Al, int lda,
    const bf16* __restrict__ Bh, const bf16* __restrict__ Bl, int ldb,
    int row0, int col0, int K, uint32_t sdu, float (&c)[4][8][4])
{
    const int tid = threadIdx.x;
    const int lane = tid & 31, wid = tid >> 5;
    const int wm = (wid & 1) << 6;
    const int wn = (wid >> 1) << 6;

    const int arow0 = wm + (lane & 15);
    const int akseg = lane >> 4;
    const int brow0 = wn + ((lane >> 4) << 3) + (lane & 7);
    const int bkseg = (lane >> 3) & 1;

    const int NC = K >> 5;
    issue_chunk(Ah, Al, lda, Bh, Bl, ldb, row0, col0, 0, sdu);
    issue_chunk(Ah, Al, lda, Bh, Bl, ldb, row0, col0, 32, sdu + 32768);

    int buf = 0;
    for (int ci = 0; ci < NC; ci++) {
        if (ci + 1 < NC) { CP_WAIT1(); } else { CP_WAIT0(); }
        __syncthreads();
        if (ci + 2 < NC) {
            int nb = buf + 2; if (nb >= 3) nb -= 3;
            issue_chunk(Ah, Al, lda, Bh, Bl, ldb, row0, col0,
                        (ci + 2) << 5, sdu + nb * 32768);
        }

        const uint32_t sb = sdu + buf * 32768;
#pragma unroll
        for (int k = 0; k < 2; k++) {
            uint32_t afh[4][4], afl[4][4], bfh[4][4], bfl[4][4];
#pragma unroll
            for (int mi = 0; mi < 4; mi++) {
                const int r = arow0 + mi * 16;
                const uint32_t off = sw64(r, 2 * k + akseg);
                ldmx4(afh[mi], sb + off);
                ldmx4(afl[mi], sb + 8192 + off);
            }
#pragma unroll
            for (int nj = 0; nj < 4; nj++) {
                const int r = brow0 + nj * 16;
                const uint32_t off = sw64(r, 2 * k + bkseg);
                ldmx4(bfh[nj], sb + 16384 + off);
                ldmx4(bfl[nj], sb + 24576 + off);
            }
#pragma unroll
            for (int mi = 0; mi < 4; mi++)
#pragma unroll
                for (int ni = 0; ni < 8; ni++) {
                    const int nj = ni >> 1, o = (ni & 1) << 1;
                    mma16816(c[mi][ni], afh[mi], bfh[nj][o], bfh[nj][o + 1]);
                }
#pragma unroll
            for (int mi = 0; mi < 4; mi++)
#pragma unroll
                for (int ni = 0; ni < 8; ni++) {
                    const int nj = ni >> 1, o = (ni & 1) << 1;
                    mma16816(c[mi][ni], afh[mi], bfl[nj][o], bfl[nj][o + 1]);
                }
#pragma unroll
            for (int mi = 0; mi < 4; mi++)
#pragma unroll
                for (int ni = 0; ni < 8; ni++) {
                    const int nj = ni >> 1, o = (ni & 1) << 1;
                    mma16816(c[mi][ni], afl[mi], bfh[nj][o], bfh[nj][o + 1]);
                }
        }
        if (++buf == 3) buf = 0;
    }
}

// ==================== fp16 1-pass mainloop (u, out) ========================
// A, B single fp16. 4-stage pipeline; stage (16KB): A|B 8K each.

__device__ __forceinline__ void issue_chunk_u(
    const fp16* __restrict__ A, int lda,
    const fp16* __restrict__ B, int ldb,
    int row0, int col0, int kt, uint32_t sb)
{
    const int tid = threadIdx.x;
#pragma unroll
    for (int i = 0; i < 4; i++) {
        const int idx = tid + i * 128;       // 0..511
        const int r = idx >> 2, s = idx & 3;
        const uint32_t off = sw64(r, s);
        const size_t ga = (size_t)(row0 + r) * lda + kt + s * 8;
        const size_t gb = (size_t)(col0 + r) * ldb + kt + s * 8;
        cp16(sb + off,        A + ga);
        cp16(sb + 8192 + off, B + gb);
    }
    CP_COMMIT();
}

__device__ __forceinline__ void mma_nt_mainloop_u(
    const fp16* __restrict__ A, int lda,
    const fp16* __restrict__ B, int ldb,
    int row0, int col0, int K, uint32_t sdu, float (&c)[4][8][4])
{
    const int tid = threadIdx.x;
    const int lane = tid & 31, wid = tid >> 5;
    const int wm = (wid & 1) << 6;
    const int wn = (wid >> 1) << 6;

    const int arow0 = wm + (lane & 15);
    const int akseg = lane >> 4;
    const int brow0 = wn + ((lane >> 4) << 3) + (lane & 7);
    const int bkseg = (lane >> 3) & 1;

    const int NC = K >> 5;                  // NC >= 32 for all callers
    issue_chunk_u(A, lda, B, ldb, row0, col0, 0,  sdu);
    issue_chunk_u(A, lda, B, ldb, row0, col0, 32, sdu + 16384);
    issue_chunk_u(A, lda, B, ldb, row0, col0, 64, sdu + 32768);

    int buf = 0;
    for (int ci = 0; ci < NC; ci++) {
        if (ci + 2 < NC)      { CP_WAIT2(); }
        else if (ci + 1 < NC) { CP_WAIT1(); }
        else                  { CP_WAIT0(); }
        __syncthreads();      // all warps done compute(ci-1)
        if (ci + 3 < NC) {
            int nb = buf + 3; if (nb >= 4) nb -= 4;
            issue_chunk_u(A, lda, B, ldb, row0, col0,
                          (ci + 3) << 5, sdu + nb * 16384);
        }

        const uint32_t sb = sdu + buf * 16384;
#pragma unroll
        for (int k = 0; k < 2; k++) {
            uint32_t af[4][4], bf[4][4];
#pragma unroll
            for (int mi = 0; mi < 4; mi++) {
                const int r = arow0 + mi * 16;
                const uint32_t off = sw64(r, 2 * k + akseg);
                ldmx4(af[mi], sb + off);
            }
#pragma unroll
            for (int nj = 0; nj < 4; nj++) {
                const int r = brow0 + nj * 16;
                const uint32_t off = sw64(r, 2 * k + bkseg);
                ldmx4(bf[nj], sb + 8192 + off);
            }
#pragma unroll
            for (int mi = 0; mi < 4; mi++)
#pragma unroll
                for (int ni = 0; ni < 8; ni++) {
                    const int nj = ni >> 1, o = (ni & 1) << 1;
                    mma16816h(c[mi][ni], af[mi], bf[nj][o], bf[nj][o + 1]);
                }
        }
        if (++buf == 4) buf = 0;
    }
}

// Epilogue mapping (both loops) for c[mi][j][q]:
//   row = row0 + wm + mi*16 + (lane>>2) + (q>=2 ? 8 : 0)
//   col = col0 + wn + j*8 + (lane&3)*2 + (q&1)
//   wm = (wid&1)<<6, wn = (wid>>1)<<6

// ===================== merged prep kernel (launch #1) ======================
// blockIdx.x: [0,8192) conv_x | [8192,8256) conv_wenc | [8256,8768) conv_wvt
//             | [8768,8896) mt
__global__ __launch_bounds__(256) void prep_kernel(
    const float* __restrict__ x, const float* __restrict__ W_enc,
    const float* __restrict__ WV,
    const float* __restrict__ WQ, const float* __restrict__ WK)
{
    const int bid = blockIdx.x;
    if (bid < 8192) {
        size_t idx = (size_t)bid * 256 + threadIdx.x;   // over float4s
        float4 v = ((const float4*)x)[idx];
        v.x = v.x > 0.f ? v.x : 0.01f * v.x;
        v.y = v.y > 0.f ? v.y : 0.01f * v.y;
        v.z = v.z > 0.f ? v.z : 0.01f * v.z;
        v.w = v.w > 0.f ? v.w : 0.01f * v.w;
        bf16 h0,l0,h1,l1,h2,l2,h3,l3;
        split2(v.x,h0,l0); split2(v.y,h1,l1); split2(v.z,h2,l2); split2(v.w,h3,l3);
        *(uint2*)(g_xh + idx * 4) = make_uint2(packbf2(h0,h1), packbf2(h2,h3));
        *(uint2*)(g_xl + idx * 4) = make_uint2(packbf2(l0,l1), packbf2(l2,l3));
        return;
    }
    if (bid < 8256) {
        size_t idx = (size_t)(bid - 8192) * 256 + threadIdx.x;  // 16384 float4s
        float4 v = ((const float4*)W_enc)[idx];
        bf16 h0,l0,h1,l1,h2,l2,h3,l3;
        split2(v.x,h0,l0); split2(v.y,h1,l1); split2(v.z,h2,l2); split2(v.w,h3,l3);
        *(uint2*)(g_weh + idx * 4) = make_uint2(packbf2(h0,h1), packbf2(h2,h3));
        *(uint2*)(g_wel + idx * 4) = make_uint2(packbf2(l0,l1), packbf2(l2,l3));
        return;
    }
    if (bid < 8768) {
        __shared__ float t[32][33];
        const int tb = bid - 8256;
        const int k0 = (tb & 63) * 32, e0 = (tb >> 6) * 32;
        const int tx = threadIdx.x & 31, ty = threadIdx.x >> 5;
#pragma unroll
        for (int i = 0; i < 4; i++) {
            const int k = ty + i * 8;
            t[k][tx] = WV[(size_t)(k0 + k) * 256 + e0 + tx];
        }
        __syncthreads();
#pragma unroll
        for (int i = 0; i < 4; i++) {
            const int e = ty + i * 8;
            g_wv16[(size_t)(e0 + e) * 2048 + k0 + tx] = __float2half(t[tx][e]);
        }
        return;
    }
    {
        __shared__ float As[8][68], Bs[8][68];
        float acc[4][4] = {};
        const int tb = bid - 8768;
        const int hh = tb >> 4;
        const int row0 = ((tb >> 2) & 3) * 64, col0 = (tb & 3) * 64;
        const float* A = WK + (size_t)hh * 65536;
        const float* B = WQ + (size_t)hh * 65536;
        const int tid = threadIdx.x;
        const int lr = tid >> 2, lk = (tid & 3) << 1;
        const int tx = tid & 15, ty = tid >> 4;
        const float* aP = A + (size_t)(row0 + lr) * 256 + lk;
        const float* bP = B + (size_t)(col0 + lr) * 256 + lk;
        for (int kt = 0; kt < 256; kt += 8) {
            float2 av = *(const float2*)(aP + kt);
            float2 bv = *(const float2*)(bP + kt);
            As[lk][lr] = av.x; As[lk + 1][lr] = av.y;
            Bs[lk][lr] = bv.x; Bs[lk + 1][lr] = bv.y;
            __syncthreads();
#pragma unroll
            for (int k = 0; k < 8; k++) {
                float ar[4], br[4];
                *(float4*)ar = *(const float4*)(&As[k][ty * 4]);
                *(float4*)br = *(const float4*)(&Bs[k][tx * 4]);
#pragma unroll
                for (int i = 0; i < 4; i++)
#pragma unroll
                    for (int j = 0; j < 4; j++)
                        acc[i][j] = fmaf(ar[i], br[j], acc[i][j]);
            }
            __syncthreads();
        }
        bf16* Dh = g_mth + (size_t)hh * 65536;
        bf16* Dl = g_mtl + (size_t)hh * 65536;
#pragma unroll
        for (int i = 0; i < 4; i++) {
            size_t base = (size_t)(row0 + ty * 4 + i) * 256 + col0 + tx * 4;
#pragma unroll
            for (int j = 0; j < 4; j += 2) {
                bf16 h0,l0,h1,l1;
                split2(acc[i][j],h0,l0); split2(acc[i][j+1],h1,l1);
                *(uint32_t*)(Dh + base + j) = packbf2(h0,h1);
                *(uint32_t*)(Dl + base + j) = packbf2(l0,l1);
            }
        }
    }
}

// ============================== MMA kernels ================================

// h = x_sp @ Wenc^T + b. grid (2, 256). Also writes h^T fp16 via smem bounce.
__global__ __launch_bounds__(128, 2) void enc_mma_kernel(const float* __restrict__ bias) {
    extern __shared__ char sd[];
    const uint32_t sdu = s2u(sd);
    float c[4][8][4] = {};
    const int row0 = blockIdx.y * 128, col0 = blockIdx.x * 128;
    mma_nt_mainloop(g_xh, g_xl, 256, g_weh, g_wel, 256, row0, col0, 256, sdu, c);
    const int lane = threadIdx.x & 31, wid = threadIdx.x >> 5;
    const int wm = (wid & 1) << 6, wn = (wid >> 1) << 6;

    __syncthreads();                       // mainloop smem free for reuse
    fp16* ts = (fp16*)sd;                  // transpose tile [128 d][stride 136]
#pragma unroll
    for (int mi = 0; mi < 4; mi++)
#pragma unroll
        for (int j = 0; j < 8; j++) {
            const int col = col0 + wn + j * 8 + (lane & 3) * 2;
            const float b0 = bias[col], b1 = bias[col + 1];
            const int dl = wn + j * 8 + (lane & 3) * 2;   // d_local
#pragma unroll
            for (int q = 0; q < 2; q++) {
                const int row = row0 + wm + mi * 16 + (lane >> 2) + q * 8;
                const int nl = wm + mi * 16 + (lane >> 2) + q * 8;  // n_local
                const float v0 = c[mi][j][q * 2]     + b0;
                const float v1 = c[mi][j][q * 2 + 1] + b1;
                bf16 h0,l0,h1,l1; split2(v0,h0,l0); split2(v1,h1,l1);
                const size_t p = (size_t)row * 256 + col;
                *(uint32_t*)(g_hh + p) = packbf2(h0,h1);
                *(uint32_t*)(g_hl + p) = packbf2(l0,l1);
                ts[dl * 136 + nl]       = __float2half(v0);
                ts[(dl + 1) * 136 + nl] = __float2half(v1);
            }
        }
    __syncthreads();
    // write h^T fp16: g_h16[b][col0+d][nbase+n], coalesced along n.
    const int b = row0 >> 10, nbase = row0 & 1023;
    fp16* oh = g_h16 + (size_t)b * 262144 + (size_t)col0 * 1024 + nbase;
    const int tid = threadIdx.x;
#pragma unroll
    for (int i = 0; i < 16; i++) {
        const int idx = tid + i * 128;     // 0..2047 uint4s
        const int d = idx >> 4, s = idx & 15;
        uint4 v = *(const uint4*)(ts + d * 136 + s * 8);
        *(uint4*)(oh + (size_t)d * 1024 + s * 8) = v;
    }
}

// G[bh] = ha_sp[b] @ MT[h]^T. grid (2, 2, 256).
__global__ __launch_bounds__(128, 2) void g_mma_kernel() {
    extern __shared__ char sd[];
    const uint32_t sdu = s2u(sd);
    float c[4][8][4] = {};
    const int z = blockIdx.z, b = z >> 3, hh = z & 7;
    const int row0 = blockIdx.y * 128, col0 = blockIdx.x * 128;
    mma_nt_mainloop(g_hh + (size_t)b * 262144, g_hl + (size_t)b * 262144, 256,
                    g_mth + (size_t)hh * 65536, g_mtl + (size_t)hh * 65536, 256,
                    row0, col0, 256, sdu, c);
    const int lane = threadIdx.x & 31, wid = threadIdx.x >> 5;
    const int wm = (wid & 1) << 6, wn = (wid >> 1) << 6;
    bf16* Dh = g_gh + (size_t)z * 65536;
    bf16* Dl = g_gl + (size_t)z * 65536;
#pragma unroll
    for (int mi = 0; mi < 4; mi++)
#pragma unroll
        for (int j = 0; j < 8; j++) {
            const int col = col0 + wn + j * 8 + (lane & 3) * 2;
#pragma unroll
            for (int q = 0; q < 2; q++) {
                const int row = row0 + wm + mi * 16 + (lane >> 2) + q * 8;
                bf16 h0,l0,h1,l1;
                split2(c[mi][j][q*2],h0,l0); split2(c[mi][j][q*2+1],h1,l1);
                const size_t p = (size_t)row * 256 + col;
                *(uint32_t*)(Dh + p) = packbf2(h0,h1);
                *(uint32_t*)(Dl + p) = packbf2(l0,l1);
            }
        }
}

// S[bh] = G[bh] @ h[b]^T * SCALE -> fp32. grid (8, 2, 256).  [profiled slot]
__global__ __launch_bounds__(128, 2) void s_mma_kernel() {
    extern __shared__ char sd[];
    const uint32_t sdu = s2u(sd);
    float c[4][8][4] = {};
    const int z = blockIdx.z, b = z >> 3;
    const int row0 = blockIdx.y * 128, col0 = blockIdx.x * 128;
    mma_nt_mainloop(g_gh + (size_t)z * 65536, g_gl + (size_t)z * 65536, 256,
                    g_hh + (size_t)b * 262144, g_hl + (size_t)b * 262144, 256,
                    row0, col0, 256, sdu, c);
    const int lane = threadIdx.x & 31, wid = threadIdx.x >> 5;
    const int wm = (wid & 1) << 6, wn = (wid >> 1) << 6;
    float* D = g_S + (size_t)z * 262144;
#pragma unroll
    for (int mi = 0; mi < 4; mi++)
#pragma unroll
        for (int j = 0; j < 8; j++) {
            const int col = col0 + wn + j * 8 + (lane & 3) * 2;
#pragma unroll
            for (int q = 0; q < 2; q++) {
                const int row = row0 + wm + mi * 16 + (lane >> 2) + q * 8;
                float2 v;
                v.x = kScale * c[mi][j][q*2];
                v.y = kScale * c[mi][j][q*2+1];
                *(float2*)(D + (size_t)row * 1024 + col) = v;
            }
        }
}

// ===================== softmax (launch #5, warp-per-row) ===================
__global__ __launch_bounds__(256) void post_kernel(const float* __restrict__ mglob) {
    const int tid = threadIdx.x;
    const int lane = tid & 31;
    const int row_id = blockIdx.x * 8 + (tid >> 5);    // 0..65535
    const int a = row_id & 255, b = row_id >> 11;
    const float4* row4 = (const float4*)(g_S + (size_t)row_id * 1024);
    const float4* m4 = (const float4*)(mglob + ((size_t)b * 256 + a) * 1024);

    float4 v[8];
#pragma unroll
    for (int i = 0; i < 8; i++) v[i] = row4[lane + i * 32];

    float mx = -1e30f;
#pragma unroll
    for (int i = 0; i < 8; i++)
        mx = fmaxf(mx, fmaxf(fmaxf(v[i].x, v[i].y), fmaxf(v[i].z, v[i].w)));
#pragma unroll
    for (int o = 16; o > 0; o >>= 1)
        mx = fmaxf(mx, __shfl_xor_sync(0xffffffffu, mx, o));

    float4 mv[8];
#pragma unroll
    for (int i = 0; i < 8; i++) mv[i] = m4[lane + i * 32];

    float zs = 0.f, ms = 0.f;
#pragma unroll
    for (int i = 0; i < 8; i++) {
        v[i].x = __expf(v[i].x - mx);
        v[i].y = __expf(v[i].y - mx);
        v[i].z = __expf(v[i].z - mx);
        v[i].w = __expf(v[i].w - mx);
        zs += v[i].x + v[i].y + v[i].z + v[i].w;
        ms += v[i].x * mv[i].x + v[i].y * mv[i].y
            + v[i].z * mv[i].z + v[i].w * mv[i].w;
    }
#pragma unroll
    for (int o = 16; o > 0; o >>= 1) {
        zs += __shfl_xor_sync(0xffffffffu, zs, o);
        ms += __shfl_xor_sync(0xffffffffu, ms, o);
    }
    const float inv = 1.0f / (ms + kEps * zs);

    uint2* out2 = (uint2*)(g_pf + (size_t)row_id * 1024);
#pragma unroll
    for (int i = 0; i < 8; i++) {
        const fp16 p0 = __float2half(v[i].x * mv[i].x * inv);
        const fp16 p1 = __float2half(v[i].y * mv[i].y * inv);
        const fp16 p2 = __float2half(v[i].z * mv[i].z * inv);
        const fp16 p3 = __float2half(v[i].w * mv[i].w * inv);
        out2[lane + i * 32] = make_uint2(packh2(p0, p1), packh2(p2, p3));
    }
}

// Ucat[b][a][h*256+d] = prob[bh] @ h[b].  grid (2, 2, 256), K=1024. fp16 1-pass.
__global__ __launch_bounds__(128, 2) void u_mma_kernel() {
    extern __shared__ char sd[];
    const uint32_t sdu = s2u(sd);
    float c[4][8][4] = {};
    const int z = blockIdx.z, b = z >> 3, hh = z & 7;
    const int row0 = blockIdx.y * 128, col0 = blockIdx.x * 128;
    mma_nt_mainloop_u(g_pf + (size_t)z * 262144, 1024,
                      g_h16 + (size_t)b * 262144, 1024,
                      row0, col0, 1024, sdu, c);
    const int lane = threadIdx.x & 31, wid = threadIdx.x >> 5;
    const int wm = (wid & 1) << 6, wn = (wid >> 1) << 6;
#pragma unroll
    for (int mi = 0; mi < 4; mi++)
#pragma unroll
        for (int j = 0; j < 8; j++) {
            const int col = col0 + wn + j * 8 + (lane & 3) * 2;
#pragma unroll
            for (int q = 0; q < 2; q++) {
                const int row = row0 + wm + mi * 16 + (lane >> 2) + q * 8;
                const size_t p = ((size_t)b * 256 + row) * 2048 + hh * 256 + col;
                *(uint32_t*)(g_u16 + p) =
                    packh2(__float2half(c[mi][j][q*2]), __float2half(c[mi][j][q*2+1]));
            }
        }
}

// out[b] = 1/8 * U_f16[b] @ WVT_f16^T.  grid (2, 2, 32), K=2048. fp16 1-pass.
__global__ __launch_bounds__(128, 2) void out_mma_kernel(float* __restrict__ out) {
    extern __shared__ char sd[];
    const uint32_t sdu = s2u(sd);
    float c[4][8][4] = {};
    const int b = blockIdx.z;
    const int row0 = blockIdx.y * 128, col0 = blockIdx.x * 128;
    mma_nt_mainloop_u(g_u16 + (size_t)b * 524288, 2048,
                      g_wv16, 2048, row0, col0, 2048, sdu, c);
    const int lane = threadIdx.x & 31, wid = threadIdx.x >> 5;
    const int wm = (wid & 1) << 6, wn = (wid >> 1) << 6;
    float* D = out + (size_t)b * 65536;
#pragma unroll
    for (int mi = 0; mi < 4; mi++)
#pragma unroll
        for (int j = 0; j < 8; j++) {
            const int col = col0 + wn + j * 8 + (lane & 3) * 2;
#pragma unroll
            for (int q = 0; q < 2; q++) {
                const int row = row0 + wm + mi * 16 + (lane >> 2) + q * 8;
                float2 v;
                v.x = 0.125f * c[mi][j][q*2];
                v.y = 0.125f * c[mi][j][q*2+1];
                *(float2*)(D + (size_t)row * 256 + col) = v;
            }
        }
}

// ===========================================================================
extern "C" void kernel_launch(void* const* d_in, const int* in_sizes, int n_in,
                              void* d_out, int out_size)
{
    const float* x     = (const float*)d_in[0];
    const float* m     = (const float*)d_in[1];
    const float* W_enc = (const float*)d_in[2];
    const float* b_enc = (const float*)d_in[3];
    const float* WQ    = (const float*)d_in[4];
    const float* WK    = (const float*)d_in[5];
    const float* WV    = (const float*)d_in[6];
    float* out = (float*)d_out;

    cudaFuncSetAttribute(enc_mma_kernel, cudaFuncAttributeMaxDynamicSharedMemorySize, kDynSmem);
    cudaFuncSetAttribute(g_mma_kernel,   cudaFuncAttributeMaxDynamicSharedMemorySize, kDynSmem);
    cudaFuncSetAttribute(s_mma_kernel,   cudaFuncAttributeMaxDynamicSharedMemorySize, kDynSmem);
    cudaFuncSetAttribute(u_mma_kernel,   cudaFuncAttributeMaxDynamicSharedMemorySize, kDynSmemU);
    cudaFuncSetAttribute(out_mma_kernel, cudaFuncAttributeMaxDynamicSharedMemorySize, kDynSmemU);

    prep_kernel<<<8896, 256>>>(x, W_enc, WV, WQ, WK);                 // launch 1
    enc_mma_kernel<<<dim3(2, 256, 1), 128, kDynSmem>>>(b_enc);        // launch 2
    g_mma_kernel<<<dim3(2, 2, 256), 128, kDynSmem>>>();               // launch 3
    s_mma_kernel<<<dim3(8, 2, 256), 128, kDynSmem>>>();               // launch 4 (profiled)
    post_kernel<<<8192, 256>>>(m);                                    // launch 5 (softmax only)
    u_mma_kernel<<<dim3(2, 2, 256), 128, kDynSmemU>>>();              // launch 6
    out_mma_kernel<<<dim3(2, 2, 32), 128, kDynSmemU>>>(out);          // launch 7
}

// round 16
// speedup vs baseline: 1.6736x; 1.0143x over previous
#include <cuda_runtime.h>
#include <cuda_bf16.h>
#include <cuda_fp16.h>
#include <cstdint>

using bf16 = __nv_bfloat16;
using fp16 = __half;

// ===========================================================================
// MHA_73607149519311 — round 16: r15 + fp16 loops (u/out) moved to K-chunk 64
// (stage 32KB, 3 stages = 96KB, 2 CTAs/SM): halves barrier count per GEMM.
// Numerics identical.
// ===========================================================================

namespace {
constexpr float kScale = 1.0f / 16.0f;   // 1/sqrt(256)
constexpr float kEps   = 1e-12f;
constexpr int kDynSmem  = 98304;         // bf16 mainloop: 3 stages x 32KB
constexpr int kDynSmemU = 98304;         // fp16 mainloop: 3 stages x 32KB
}

// ---- scratch (static device globals; no dynamic allocation) ----
#define DEVBUF(name, count) __device__ __align__(128) bf16 name[count]
#define DEVBUFH(name, count) __device__ __align__(128) fp16 name[count]
DEVBUF(g_xh, 8388608);  DEVBUF(g_xl, 8388608);    // leaky(x) split   [32768,256]
DEVBUF(g_weh, 65536);   DEVBUF(g_wel, 65536);     // W_enc split      [256,256]
DEVBUF(g_mth, 524288);  DEVBUF(g_mtl, 524288);    // MT=WK@WQ^T split [8,256,256]
DEVBUF(g_hh, 8388608);  DEVBUF(g_hl, 8388608);    // h split          [32,1024,256]
DEVBUF(g_gh, 16777216); DEVBUF(g_gl, 16777216);   // G split          [256,256,256]
DEVBUFH(g_u16, 16777216);                          // U concat fp16    [32,256,2048]
DEVBUFH(g_wv16, 524288);                           // WVT_cat fp16     [256,2048]
DEVBUFH(g_pf, 67108864);                           // prob fp16        [256,256,1024]
DEVBUFH(g_h16, 8388608);                           // h^T fp16         [32,256,1024]
__device__ __align__(128) float g_S[67108864];     // S fp32           [256,256,1024]

// ============================= helpers =====================================
__device__ __forceinline__ uint32_t s2u(const void* p) {
    uint32_t a;
    asm("{ .reg .u64 t; cvta.to.shared.u64 t, %1; cvt.u32.u64 %0, t; }"
        : "=r"(a) : "l"(p));
    return a;
}

__device__ __forceinline__ void cp16(uint32_t saddr, const void* gaddr) {
    asm volatile("cp.async.cg.shared.global [%0], [%1], 16;"
                 :: "r"(saddr), "l"(gaddr) : "memory");
}
#define CP_COMMIT() asm volatile("cp.async.commit_group;" ::: "memory")
#define CP_WAIT1()  asm volatile("cp.async.wait_group 1;" ::: "memory")
#define CP_WAIT0()  asm volatile("cp.async.wait_group 0;" ::: "memory")

__device__ __forceinline__ void ldmx4(uint32_t* r, uint32_t addr) {
    asm volatile("ldmatrix.sync.aligned.m8n8.x4.shared.b16 {%0,%1,%2,%3}, [%4];"
                 : "=r"(r[0]), "=r"(r[1]), "=r"(r[2]), "=r"(r[3]) : "r"(addr));
}

__device__ __forceinline__ void mma16816(float* c, const uint32_t* a,
                                         uint32_t b0, uint32_t b1) {
    asm volatile(
        "mma.sync.aligned.m16n8k16.row.col.f32.bf16.bf16.f32 "
        "{%0,%1,%2,%3}, {%4,%5,%6,%7}, {%8,%9}, {%0,%1,%2,%3};"
        : "+f"(c[0]), "+f"(c[1]), "+f"(c[2]), "+f"(c[3])
        : "r"(a[0]), "r"(a[1]), "r"(a[2]), "r"(a[3]), "r"(b0), "r"(b1));
}

__device__ __forceinline__ void mma16816h(float* c, const uint32_t* a,
                                          uint32_t b0, uint32_t b1) {
    asm volatile(
        "mma.sync.aligned.m16n8k16.row.col.f32.f16.f16.f32 "
        "{%0,%1,%2,%3}, {%4,%5,%6,%7}, {%8,%9}, {%0,%1,%2,%3};"
        : "+f"(c[0]), "+f"(c[1]), "+f"(c[2]), "+f"(c[3])
        : "r"(a[0]), "r"(a[1]), "r"(a[2]), "r"(a[3]), "r"(b0), "r"(b1));
}

__device__ __forceinline__ void split2(float v, bf16& hi, bf16& lo) {
    hi = __float2bfloat16(v);
    lo = __float2bfloat16(v - __bfloat162float(hi));
}
__device__ __forceinline__ uint32_t packbf2(bf16 a, bf16 b) {
    __nv_bfloat162 t; t.x = a; t.y = b;
    return *reinterpret_cast<uint32_t*>(&t);
}
__device__ __forceinline__ uint32_t packh2(fp16 a, fp16 b) {
    __half2 t; t.x = a; t.y = b;
    return *reinterpret_cast<uint32_t*>(&t);
}

// Swizzled offset within a (rows x 64B) tile: row r, seg s (0..3).
__device__ __forceinline__ uint32_t sw64(int r, int s) {
    return (uint32_t)((r << 6) + (((s ^ ((r >> 1) & 3)) & 3) << 4));
}
// Swizzled offset within a (rows x 128B) tile: row r, 16B seg s (0..7).
__device__ __forceinline__ uint32_t sw128(int r, int s) {
    uint32_t off = (uint32_t)(r * 128 + s * 16);
    return off ^ ((off >> 3) & 0x70);
}

// ==================== bf16 split-2 mainloop (r9, proven) ===================
// CTA tile 128x128, NT. 128 threads = 4 warps (2M x 2N), warp tile 64x64.
// cp.async 3-stage, K chunks of 32. Stage (32KB): Ahi|Alo|Bhi|Blo 8K each.

__device__ __forceinline__ void issue_chunk(
    const bf16* __restrict__ Ah, const bf16* __restrict__ Al, int lda,
    const bf16* __restrict__ Bh, const bf16* __restrict__ Bl, int ldb,
    int row0, int col0, int kt, uint32_t sb)
{
    const int tid = threadIdx.x;
#pragma unroll
    for (int i = 0; i < 4; i++) {
        const int idx = tid + i * 128;       // 0..511
        const int r = idx >> 2, s = idx & 3;
        const uint32_t off = sw64(r, s);
        const size_t ga = (size_t)(row0 + r) * lda + kt + s * 8;
        const size_t gb = (size_t)(col0 + r) * ldb + kt + s * 8;
        cp16(sb + off,         Ah + ga);
        cp16(sb + 8192 + off,  Al + ga);
        cp16(sb + 16384 + off, Bh + gb);
        cp16(sb + 24576 + off, Bl + gb);
    }
    CP_COMMIT();
}

__device__ __forceinline__ void mma_nt_mainloop(
    const bf16* __restrict__ Ah, const bf16* __restrict__ Al, int lda,
    const bf16* __restrict__ Bh, const bf16* __restrict__ Bl, int ldb,
    int row0, int col0, int K, uint32_t sdu, float (&c)[4][8][4])
{
    const int tid = threadIdx.x;
    const int lane = tid & 31, wid = tid >> 5;
    const int wm = (wid & 1) << 6;
    const int wn = (wid >> 1) << 6;

    const int arow0 = wm + (lane & 15);
    const int akseg = lane >> 4;
    const int brow0 = wn + ((lane >> 4) << 3) + (lane & 7);
    const int bkseg = (lane >> 3) & 1;

    const int NC = K >> 5;
    issue_chunk(Ah, Al, lda, Bh, Bl, ldb, row0, col0, 0, sdu);
    issue_chunk(Ah, Al, lda, Bh, Bl, ldb, row0, col0, 32, sdu + 32768);

    int buf = 0;
    for (int ci = 0; ci < NC; ci++) {
        if (ci + 1 < NC) { CP_WAIT1(); } else { CP_WAIT0(); }
        __syncthreads();
        if (ci + 2 < NC) {
            int nb = buf + 2; if (nb >= 3) nb -= 3;
            issue_chunk(Ah, Al, lda, Bh, Bl, ldb, row0, col0,
                        (ci + 2) << 5, sdu + nb * 32768);
        }

        const uint32_t sb = sdu + buf * 32768;
#pragma unroll
        for (int k = 0; k < 2; k++) {
            uint32_t afh[4][4], afl[4][4], bfh[4][4], bfl[4][4];
#pragma unroll
            for (int mi = 0; mi < 4; mi++) {
                const int r = arow0 + mi * 16;
                const uint32_t off = sw64(r, 2 * k + akseg);
                ldmx4(afh[mi], sb + off);
                ldmx4(afl[mi], sb + 8192 + off);
            }
#pragma unroll
            for (int nj = 0; nj < 4; nj++) {
                const int r = brow0 + nj * 16;
                const uint32_t off = sw64(r, 2 * k + bkseg);
                ldmx4(bfh[nj], sb + 16384 + off);
                ldmx4(bfl[nj], sb + 24576 + off);
            }
#pragma unroll
            for (int mi = 0; mi < 4; mi++)
#pragma unroll
                for (int ni = 0; ni < 8; ni++) {
                    const int nj = ni >> 1, o = (ni & 1) << 1;
                    mma16816(c[mi][ni], afh[mi], bfh[nj][o], bfh[nj][o + 1]);
                }
#pragma unroll
            for (int mi = 0; mi < 4; mi++)
#pragma unroll
                for (int ni = 0; ni < 8; ni++) {
                    const int nj = ni >> 1, o = (ni & 1) << 1;
                    mma16816(c[mi][ni], afh[mi], bfl[nj][o], bfl[nj][o + 1]);
                }
#pragma unroll
            for (int mi = 0; mi < 4; mi++)
#pragma unroll
                for (int ni = 0; ni < 8; ni++) {
                    const int nj = ni >> 1, o = (ni & 1) << 1;
                    mma16816(c[mi][ni], afl[mi], bfh[nj][o], bfh[nj][o + 1]);
                }
        }
        if (++buf == 3) buf = 0;
    }
}

// ==================== fp16 1-pass mainloop (u, out) ========================
// A, B single fp16. K chunks of 64; 3-stage pipeline.
// Stage (32KB): A 16KB | B 16KB, 128B rows, sw128 swizzle.

__device__ __forceinline__ void issue_chunk_u(
    const fp16* __restrict__ A, int lda,
    const fp16* __restrict__ B, int ldb,
    int row0, int col0, int kt, uint32_t sb)
{
    const int tid = threadIdx.x;
#pragma unroll
    for (int i = 0; i < 8; i++) {
        const int idx = tid + i * 128;       // 0..1023
        const int r = idx >> 3, s = idx & 7;
        const uint32_t off = sw128(r, s);
        const size_t ga = (size_t)(row0 + r) * lda + kt + s * 8;
        const size_t gb = (size_t)(col0 + r) * ldb + kt + s * 8;
        cp16(sb + off,         A + ga);
        cp16(sb + 16384 + off, B + gb);
    }
    CP_COMMIT();
}

__device__ __forceinline__ void mma_nt_mainloop_u(
    const fp16* __restrict__ A, int lda,
    const fp16* __restrict__ B, int ldb,
    int row0, int col0, int K, uint32_t sdu, float (&c)[4][8][4])
{
    const int tid = threadIdx.x;
    const int lane = tid & 31, wid = tid >> 5;
    const int wm = (wid & 1) << 6;
    const int wn = (wid >> 1) << 6;

    const int arow0 = wm + (lane & 15);
    const int akseg = lane >> 4;                       // 16B seg parity
    const int brow0 = wn + ((lane >> 4) << 3) + (lane & 7);
    const int bkseg = (lane >> 3) & 1;

    const int NC = K >> 6;                  // chunks of 64 (NC>=16 for callers)
    issue_chunk_u(A, lda, B, ldb, row0, col0, 0,  sdu);
    issue_chunk_u(A, lda, B, ldb, row0, col0, 64, sdu + 32768);

    int buf = 0;
    for (int ci = 0; ci < NC; ci++) {
        if (ci + 1 < NC) { CP_WAIT1(); } else { CP_WAIT0(); }
        __syncthreads();
        if (ci + 2 < NC) {
            int nb = buf + 2; if (nb >= 3) nb -= 3;
            issue_chunk_u(A, lda, B, ldb, row0, col0,
                          (ci + 2) << 6, sdu + nb * 32768);
        }

        const uint32_t sb = sdu + buf * 32768;
#pragma unroll
        for (int k = 0; k < 4; k++) {
            uint32_t af[4][4], bf[4][4];
#pragma unroll
            for (int mi = 0; mi < 4; mi++) {
                const int r = arow0 + mi * 16;
                const uint32_t off = sw128(r, 2 * k + akseg);
                ldmx4(af[mi], sb + off);
            }
#pragma unroll
            for (int nj = 0; nj < 4; nj++) {
                const int r = brow0 + nj * 16;
                const uint32_t off = sw128(r, 2 * k + bkseg);
                ldmx4(bf[nj], sb + 16384 + off);
            }
#pragma unroll
            for (int mi = 0; mi < 4; mi++)
#pragma unroll
                for (int ni = 0; ni < 8; ni++) {
                    const int nj = ni >> 1, o = (ni & 1) << 1;
                    mma16816h(c[mi][ni], af[mi], bf[nj][o], bf[nj][o + 1]);
                }
        }
        if (++buf == 3) buf = 0;
    }
}

// Epilogue mapping (both loops) for c[mi][j][q]:
//   row = row0 + wm + mi*16 + (lane>>2) + (q>=2 ? 8 : 0)
//   col = col0 + wn + j*8 + (lane&3)*2 + (q&1)
//   wm = (wid&1)<<6, wn = (wid>>1)<<6

// ===================== merged prep kernel (launch #1) ======================
// blockIdx.x: [0,8192) conv_x | [8192,8256) conv_wenc | [8256,8768) conv_wvt
//             | [8768,8896) mt
__global__ __launch_bounds__(256) void prep_kernel(
    const float* __restrict__ x, const float* __restrict__ W_enc,
    const float* __restrict__ WV,
    const float* __restrict__ WQ, const float* __restrict__ WK)
{
    const int bid = blockIdx.x;
    if (bid < 8192) {
        size_t idx = (size_t)bid * 256 + threadIdx.x;   // over float4s
        float4 v = ((const float4*)x)[idx];
        v.x = v.x > 0.f ? v.x : 0.01f * v.x;
        v.y = v.y > 0.f ? v.y : 0.01f * v.y;
        v.z = v.z > 0.f ? v.z : 0.01f * v.z;
        v.w = v.w > 0.f ? v.w : 0.01f * v.w;
        bf16 h0,l0,h1,l1,h2,l2,h3,l3;
        split2(v.x,h0,l0); split2(v.y,h1,l1); split2(v.z,h2,l2); split2(v.w,h3,l3);
        *(uint2*)(g_xh + idx * 4) = make_uint2(packbf2(h0,h1), packbf2(h2,h3));
        *(uint2*)(g_xl + idx * 4) = make_uint2(packbf2(l0,l1), packbf2(l2,l3));
        return;
    }
    if (bid < 8256) {
        size_t idx = (size_t)(bid - 8192) * 256 + threadIdx.x;  // 16384 float4s
        float4 v = ((const float4*)W_enc)[idx];
        bf16 h0,l0,h1,l1,h2,l2,h3,l3;
        split2(v.x,h0,l0); split2(v.y,h1,l1); split2(v.z,h2,l2); split2(v.w,h3,l3);
        *(uint2*)(g_weh + idx * 4) = make_uint2(packbf2(h0,h1), packbf2(h2,h3));
        *(uint2*)(g_wel + idx * 4) = make_uint2(packbf2(l0,l1), packbf2(l2,l3));
        return;
    }
    if (bid < 8768) {
        __shared__ float t[32][33];
        const int tb = bid - 8256;
        const int k0 = (tb & 63) * 32, e0 = (tb >> 6) * 32;
        const int tx = threadIdx.x & 31, ty = threadIdx.x >> 5;
#pragma unroll
        for (int i = 0; i < 4; i++) {
            const int k = ty + i * 8;
            t[k][tx] = WV[(size_t)(k0 + k) * 256 + e0 + tx];
        }
        __syncthreads();
#pragma unroll
        for (int i = 0; i < 4; i++) {
            const int e = ty + i * 8;
            g_wv16[(size_t)(e0 + e) * 2048 + k0 + tx] = __float2half(t[tx][e]);
        }
        return;
    }
    {
        __shared__ float As[8][68], Bs[8][68];
        float acc[4][4] = {};
        const int tb = bid - 8768;
        const int hh = tb >> 4;
        const int row0 = ((tb >> 2) & 3) * 64, col0 = (tb & 3) * 64;
        const float* A = WK + (size_t)hh * 65536;
        const float* B = WQ + (size_t)hh * 65536;
        const int tid = threadIdx.x;
        const int lr = tid >> 2, lk = (tid & 3) << 1;
        const int tx = tid & 15, ty = tid >> 4;
        const float* aP = A + (size_t)(row0 + lr) * 256 + lk;
        const float* bP = B + (size_t)(col0 + lr) * 256 + lk;
        for (int kt = 0; kt < 256; kt += 8) {
            float2 av = *(const float2*)(aP + kt);
            float2 bv = *(const float2*)(bP + kt);
            As[lk][lr] = av.x; As[lk + 1][lr] = av.y;
            Bs[lk][lr] = bv.x; Bs[lk + 1][lr] = bv.y;
            __syncthreads();
#pragma unroll
            for (int k = 0; k < 8; k++) {
                float ar[4], br[4];
                *(float4*)ar = *(const float4*)(&As[k][ty * 4]);
                *(float4*)br = *(const float4*)(&Bs[k][tx * 4]);
#pragma unroll
                for (int i = 0; i < 4; i++)
#pragma unroll
                    for (int j = 0; j < 4; j++)
                        acc[i][j] = fmaf(ar[i], br[j], acc[i][j]);
            }
            __syncthreads();
        }
        bf16* Dh = g_mth + (size_t)hh * 65536;
        bf16* Dl = g_mtl + (size_t)hh * 65536;
#pragma unroll
        for (int i = 0; i < 4; i++) {
            size_t base = (size_t)(row0 + ty * 4 + i) * 256 + col0 + tx * 4;
#pragma unroll
            for (int j = 0; j < 4; j += 2) {
                bf16 h0,l0,h1,l1;
                split2(acc[i][j],h0,l0); split2(acc[i][j+1],h1,l1);
                *(uint32_t*)(Dh + base + j) = packbf2(h0,h1);
                *(uint32_t*)(Dl + base + j) = packbf2(l0,l1);
            }
        }
    }
}

// ============================== MMA kernels ================================

// h = x_sp @ Wenc^T + b. grid (2, 256). Also writes h^T fp16 via smem bounce.
__global__ __launch_bounds__(128, 2) void enc_mma_kernel(const float* __restrict__ bias) {
    extern __shared__ char sd[];
    const uint32_t sdu = s2u(sd);
    float c[4][8][4] = {};
    const int row0 = blockIdx.y * 128, col0 = blockIdx.x * 128;
    mma_nt_mainloop(g_xh, g_xl, 256, g_weh, g_wel, 256, row0, col0, 256, sdu, c);
    const int lane = threadIdx.x & 31, wid = threadIdx.x >> 5;
    const int wm = (wid & 1) << 6, wn = (wid >> 1) << 6;

    __syncthreads();                       // mainloop smem free for reuse
    fp16* ts = (fp16*)sd;                  // transpose tile [128 d][stride 136]
#pragma unroll
    for (int mi = 0; mi < 4; mi++)
#pragma unroll
        for (int j = 0; j < 8; j++) {
            const int col = col0 + wn + j * 8 + (lane & 3) * 2;
            const float b0 = bias[col], b1 = bias[col + 1];
            const int dl = wn + j * 8 + (lane & 3) * 2;   // d_local
#pragma unroll
            for (int q = 0; q < 2; q++) {
                const int row = row0 + wm + mi * 16 + (lane >> 2) + q * 8;
                const int nl = wm + mi * 16 + (lane >> 2) + q * 8;  // n_local
                const float v0 = c[mi][j][q * 2]     + b0;
                const float v1 = c[mi][j][q * 2 + 1] + b1;
                bf16 h0,l0,h1,l1; split2(v0,h0,l0); split2(v1,h1,l1);
                const size_t p = (size_t)row * 256 + col;
                *(uint32_t*)(g_hh + p) = packbf2(h0,h1);
                *(uint32_t*)(g_hl + p) = packbf2(l0,l1);
                ts[dl * 136 + nl]       = __float2half(v0);
                ts[(dl + 1) * 136 + nl] = __float2half(v1);
            }
        }
    __syncthreads();
    // write h^T fp16: g_h16[b][col0+d][nbase+n], coalesced along n.
    const int b = row0 >> 10, nbase = row0 & 1023;
    fp16* oh = g_h16 + (size_t)b * 262144 + (size_t)col0 * 1024 + nbase;
    const int tid = threadIdx.x;
#pragma unroll
    for (int i = 0; i < 16; i++) {
        const int idx = tid + i * 128;     // 0..2047 uint4s
        const int d = idx >> 4, s = idx & 15;
        uint4 v = *(const uint4*)(ts + d * 136 + s * 8);
        *(uint4*)(oh + (size_t)d * 1024 + s * 8) = v;
    }
}

// G[bh] = ha_sp[b] @ MT[h]^T. grid (2, 2, 256).
__global__ __launch_bounds__(128, 2) void g_mma_kernel() {
    extern __shared__ char sd[];
    const uint32_t sdu = s2u(sd);
    float c[4][8][4] = {};
    const int z = blockIdx.z, b = z >> 3, hh = z & 7;
    const int row0 = blockIdx.y * 128, col0 = blockIdx.x * 128;
    mma_nt_mainloop(g_hh + (size_t)b * 262144, g_hl + (size_t)b * 262144, 256,
                    g_mth + (size_t)hh * 65536, g_mtl + (size_t)hh * 65536, 256,
                    row0, col0, 256, sdu, c);
    const int lane = threadIdx.x & 31, wid = threadIdx.x >> 5;
    const int wm = (wid & 1) << 6, wn = (wid >> 1) << 6;
    bf16* Dh = g_gh + (size_t)z * 65536;
    bf16* Dl = g_gl + (size_t)z * 65536;
#pragma unroll
    for (int mi = 0; mi < 4; mi++)
#pragma unroll
        for (int j = 0; j < 8; j++) {
            const int col = col0 + wn + j * 8 + (lane & 3) * 2;
#pragma unroll
            for (int q = 0; q < 2; q++) {
                const int row = row0 + wm + mi * 16 + (lane >> 2) + q * 8;
                bf16 h0,l0,h1,l1;
                split2(c[mi][j][q*2],h0,l0); split2(c[mi][j][q*2+1],h1,l1);
                const size_t p = (size_t)row * 256 + col;
                *(uint32_t*)(Dh + p) = packbf2(h0,h1);
                *(uint32_t*)(Dl + p) = packbf2(l0,l1);
            }
        }
}

// S[bh] = G[bh] @ h[b]^T * SCALE -> fp32. grid (8, 2, 256).  [profiled slot]
__global__ __launch_bounds__(128, 2) void s_mma_kernel() {
    extern __shared__ char sd[];
    const uint32_t sdu = s2u(sd);
    float c[4][8][4] = {};
    const int z = blockIdx.z, b = z >> 3;
    const int row0 = blockIdx.y * 128, col0 = blockIdx.x * 128;
    mma_nt_mainloop(g_gh + (size_t)z * 65536, g_gl + (size_t)z * 65536, 256,
                    g_hh + (size_t)b * 262144, g_hl + (size_t)b * 262144, 256,
                    row0, col0, 256, sdu, c);
    const int lane = threadIdx.x & 31, wid = threadIdx.x >> 5;
    const int wm = (wid & 1) << 6, wn = (wid >> 1) << 6;
    float* D = g_S + (size_t)z * 262144;
#pragma unroll
    for (int mi = 0; mi < 4; mi++)
#pragma unroll
        for (int j = 0; j < 8; j++) {
            const int col = col0 + wn + j * 8 + (lane & 3) * 2;
#pragma unroll
            for (int q = 0; q < 2; q++) {
                const int row = row0 + wm + mi * 16 + (lane >> 2) + q * 8;
                float2 v;
                v.x = kScale * c[mi][j][q*2];
                v.y = kScale * c[mi][j][q*2+1];
                *(float2*)(D + (size_t)row * 1024 + col) = v;
            }
        }
}

// ===================== softmax (launch #5, warp-per-row) ===================
__global__ __launch_bounds__(256) void post_kernel(const float* __restrict__ mglob) {
    const int tid = threadIdx.x;
    const int lane = tid & 31;
    const int row_id = blockIdx.x * 8 + (tid >> 5);    // 0..65535
    const int a = row_id & 255, b = row_id >> 11;
    const float4* row4 = (const float4*)(g_S + (size_t)row_id * 1024);
    const float4* m4 = (const float4*)(mglob + ((size_t)b * 256 + a) * 1024);

    float4 v[8];
#pragma unroll
    for (int i = 0; i < 8; i++) v[i] = row4[lane + i * 32];

    float mx = -1e30f;
#pragma unroll
    for (int i = 0; i < 8; i++)
        mx = fmaxf(mx, fmaxf(fmaxf(v[i].x, v[i].y), fmaxf(v[i].z, v[i].w)));
#pragma unroll
    for (int o = 16; o > 0; o >>= 1)
        mx = fmaxf(mx, __shfl_xor_sync(0xffffffffu, mx, o));

    float4 mv[8];
#pragma unroll
    for (int i = 0; i < 8; i++) mv[i] = m4[lane + i * 32];

    float zs = 0.f, ms = 0.f;
#pragma unroll
    for (int i = 0; i < 8; i++) {
        v[i].x = __expf(v[i].x - mx);
        v[i].y = __expf(v[i].y - mx);
        v[i].z = __expf(v[i].z - mx);
        v[i].w = __expf(v[i].w - mx);
        zs += v[i].x + v[i].y + v[i].z + v[i].w;
        ms += v[i].x * mv[i].x + v[i].y * mv[i].y
            + v[i].z * mv[i].z + v[i].w * mv[i].w;
    }
#pragma unroll
    for (int o = 16; o > 0; o >>= 1) {
        zs += __shfl_xor_sync(0xffffffffu, zs, o);
        ms += __shfl_xor_sync(0xffffffffu, ms, o);
    }
    const float inv = 1.0f / (ms + kEps * zs);

    uint2* out2 = (uint2*)(g_pf + (size_t)row_id * 1024);
#pragma unroll
    for (int i = 0; i < 8; i++) {
        const fp16 p0 = __float2half(v[i].x * mv[i].x * inv);
        const fp16 p1 = __float2half(v[i].y * mv[i].y * inv);
        const fp16 p2 = __float2half(v[i].z * mv[i].z * inv);
        const fp16 p3 = __float2half(v[i].w * mv[i].w * inv);
        out2[lane + i * 32] = make_uint2(packh2(p0, p1), packh2(p2, p3));
    }
}

// Ucat[b][a][h*256+d] = prob[bh] @ h[b].  grid (2, 2, 256), K=1024. fp16 1-pass.
__global__ __launch_bounds__(128, 2) void u_mma_kernel() {
    extern __shared__ char sd[];
    const uint32_t sdu = s2u(sd);
    float c[4][8][4] = {};
    const int z = blockIdx.z, b = z >> 3, hh = z & 7;
    const int row0 = blockIdx.y * 128, col0 = blockIdx.x * 128;
    mma_nt_mainloop_u(g_pf + (size_t)z * 262144, 1024,
                      g_h16 + (size_t)b * 262144, 1024,
                      row0, col0, 1024, sdu, c);
    const int lane = threadIdx.x & 31, wid = threadIdx.x >> 5;
    const int wm = (wid & 1) << 6, wn = (wid >> 1) << 6;
#pragma unroll
    for (int mi = 0; mi < 4; mi++)
#pragma unroll
        for (int j = 0; j < 8; j++) {
            const int col = col0 + wn + j * 8 + (lane & 3) * 2;
#pragma unroll
            for (int q = 0; q < 2; q++) {
                const int row = row0 + wm + mi * 16 + (lane >> 2) + q * 8;
                const size_t p = ((size_t)b * 256 + row) * 2048 + hh * 256 + col;
                *(uint32_t*)(g_u16 + p) =
                    packh2(__float2half(c[mi][j][q*2]), __float2half(c[mi][j][q*2+1]));
            }
        }
}

// out[b] = 1/8 * U_f16[b] @ WVT_f16^T.  grid (2, 2, 32), K=2048. fp16 1-pass.
__global__ __launch_bounds__(128, 2) void out_mma_kernel(float* __restrict__ out) {
    extern __shared__ char sd[];
    const uint32_t sdu = s2u(sd);
    float c[4][8][4] = {};
    const int b = blockIdx.z;
    const int row0 = blockIdx.y * 128, col0 = blockIdx.x * 128;
    mma_nt_mainloop_u(g_u16 + (size_t)b * 524288, 2048,
                      g_wv16, 2048, row0, col0, 2048, sdu, c);
    const int lane = threadIdx.x & 31, wid = threadIdx.x >> 5;
    const int wm = (wid & 1) << 6, wn = (wid >> 1) << 6;
    float* D = out + (size_t)b * 65536;
#pragma unroll
    for (int mi = 0; mi < 4; mi++)
#pragma unroll
        for (int j = 0; j < 8; j++) {
            const int col = col0 + wn + j * 8 + (lane & 3) * 2;
#pragma unroll
            for (int q = 0; q < 2; q++) {
                const int row = row0 + wm + mi * 16 + (lane >> 2) + q * 8;
                float2 v;
                v.x = 0.125f * c[mi][j][q*2];
                v.y = 0.125f * c[mi][j][q*2+1];
                *(float2*)(D + (size_t)row * 256 + col) = v;
            }
        }
}

// ===========================================================================
extern "C" void kernel_launch(void* const* d_in, const int* in_sizes, int n_in,
                              void* d_out, int out_size)
{
    const float* x     = (const float*)d_in[0];
    const float* m     = (const float*)d_in[1];
    const float* W_enc = (const float*)d_in[2];
    const float* b_enc = (const float*)d_in[3];
    const float* WQ    = (const float*)d_in[4];
    const float* WK    = (const float*)d_in[5];
    const float* WV    = (const float*)d_in[6];
    float* out = (float*)d_out;

    cudaFuncSetAttribute(enc_mma_kernel, cudaFuncAttributeMaxDynamicSharedMemorySize, kDynSmem);
    cudaFuncSetAttribute(g_mma_kernel,   cudaFuncAttributeMaxDynamicSharedMemorySize, kDynSmem);
    cudaFuncSetAttribute(s_mma_kernel,   cudaFuncAttributeMaxDynamicSharedMemorySize, kDynSmem);
    cudaFuncSetAttribute(u_mma_kernel,   cudaFuncAttributeMaxDynamicSharedMemorySize, kDynSmemU);
    cudaFuncSetAttribute(out_mma_kernel, cudaFuncAttributeMaxDynamicSharedMemorySize, kDynSmemU);

    prep_kernel<<<8896, 256>>>(x, W_enc, WV, WQ, WK);                 // launch 1
    enc_mma_kernel<<<dim3(2, 256, 1), 128, kDynSmem>>>(b_enc);        // launch 2
    g_mma_kernel<<<dim3(2, 2, 256), 128, kDynSmem>>>();               // launch 3
    s_mma_kernel<<<dim3(8, 2, 256), 128, kDynSmem>>>();               // launch 4 (profiled)
    post_kernel<<<8192, 256>>>(m);                                    // launch 5 (softmax only)
    u_mma_kernel<<<dim3(2, 2, 256), 128, kDynSmemU>>>();              // launch 6
    out_mma_kernel<<<dim3(2, 2, 32), 128, kDynSmemU>>>(out);          // launch 7
}